// round 1
// baseline (speedup 1.0000x reference)
#include <cuda_runtime.h>
#include <math.h>

#define BD   2
#define SD   1024
#define DD   1024
#define HH   16
#define HDIM 64
#define LL   4
#define MMF  2730
#define VV   32000
#define NTOK (BD*SD)

// ---------------- scratch (device globals; no allocation allowed) ----------
__device__ float g_x[NTOK*DD];
__device__ float g_h[NTOK*DD];
__device__ float g_qkv[NTOK*3*DD];
__device__ float g_scores[(size_t)BD*HH*SD*SD];   // 134 MB
__device__ float g_attn[NTOK*DD];
__device__ float g_gate[NTOK*MMF];
__device__ float g_up[NTOK*MMF];

// ---------------- embedding gather ----------------------------------------
__global__ void k_embed(const int* __restrict__ tok, const float* __restrict__ emb,
                        float* __restrict__ x) {
    int i = blockIdx.x * 256 + threadIdx.x;          // NTOK*DD threads
    int n = i >> 10, d = i & 1023;
    x[i] = emb[(long)tok[n] * DD + d];
}

// ---------------- rmsnorm ---------------------------------------------------
__global__ void __launch_bounds__(256) k_rmsnorm(const float* __restrict__ x,
                                                 const float* __restrict__ w,
                                                 float* __restrict__ o) {
    int row = blockIdx.x;
    const float* xr = x + (long)row * DD;
    float s = 0.f;
    for (int c = threadIdx.x; c < DD; c += 256) { float v = xr[c]; s += v * v; }
    __shared__ float red[8];
    #pragma unroll
    for (int off = 16; off; off >>= 1) s += __shfl_xor_sync(0xffffffffu, s, off);
    if ((threadIdx.x & 31) == 0) red[threadIdx.x >> 5] = s;
    __syncthreads();
    if (threadIdx.x == 0) {
        float t = 0.f;
        #pragma unroll
        for (int i = 0; i < 8; ++i) t += red[i];
        red[0] = t;
    }
    __syncthreads();
    float r = rsqrtf(red[0] * (1.0f / DD) + 1e-6f);
    for (int c = threadIdx.x; c < DD; c += 256)
        o[(long)row * DD + c] = xr[c] * r * w[c];
}

// ---------------- generic tiled SGEMM: C = A@B + bias (+ add) --------------
// A: N x K, B: K x M, row-major. 128x128 tile, BK=8, 8x8 per thread.
__global__ void __launch_bounds__(256) k_gemm(const float* __restrict__ A,
                                              const float* __restrict__ B,
                                              const float* __restrict__ bias,
                                              const float* __restrict__ add,
                                              float* __restrict__ C,
                                              int N, int K, int M) {
    __shared__ float As[8][128];
    __shared__ float Bs[8][128];
    int tid = threadIdx.x;
    int br = blockIdx.y * 128, bc = blockIdx.x * 128;
    float acc[8][8] = {};
    int tr = (tid >> 4) * 8, tc = (tid & 15) * 8;

    for (int k0 = 0; k0 < K; k0 += 8) {
        #pragma unroll
        for (int r = 0; r < 4; ++r) {
            int e = tid + r * 256;
            int i = e >> 3, j = e & 7;
            int gr = br + i, gc = k0 + j;
            As[j][i] = (gr < N && gc < K) ? A[(long)gr * K + gc] : 0.f;
        }
        #pragma unroll
        for (int r = 0; r < 4; ++r) {
            int e = tid + r * 256;
            int j = e >> 7, i = e & 127;
            int gr = k0 + j, gc = bc + i;
            Bs[j][i] = (gr < K && gc < M) ? B[(long)gr * M + gc] : 0.f;
        }
        __syncthreads();
        #pragma unroll
        for (int j = 0; j < 8; ++j) {
            float a[8], b[8];
            #pragma unroll
            for (int t = 0; t < 8; ++t) a[t] = As[j][tr + t];
            #pragma unroll
            for (int t = 0; t < 8; ++t) b[t] = Bs[j][tc + t];
            #pragma unroll
            for (int y = 0; y < 8; ++y)
                #pragma unroll
                for (int x = 0; x < 8; ++x) acc[y][x] += a[y] * b[x];
        }
        __syncthreads();
    }

    #pragma unroll
    for (int y = 0; y < 8; ++y) {
        int gr = br + tr + y;
        if (gr >= N) continue;
        #pragma unroll
        for (int x = 0; x < 8; ++x) {
            int gc = bc + tc + x;
            if (gc >= M) continue;
            float v = acc[y][x];
            if (bias) v += bias[gc];
            if (add)  v += add[(long)gr * M + gc];
            C[(long)gr * M + gc] = v;
        }
    }
}

// ---------------- RoPE (in-place on q,k halves of qkv) ---------------------
__global__ void k_rope(float* __restrict__ qkv) {
    int idx = blockIdx.x * 256 + threadIdx.x;  // NTOK*2*HH*32 pair-threads
    int j = idx & 31;
    int h = (idx >> 5) & 15;
    int t = (idx >> 9) & 1;
    int n = idx >> 10;
    int pos = n & (SD - 1);
    float freq = powf(10000.f, -(float)j / 32.f);
    float ang = (float)pos * freq;
    float s, c;
    sincosf(ang, &s, &c);
    float* p = qkv + (long)n * 3 * DD + t * DD + h * HDIM + 2 * j;
    float e = p[0], o = p[1];
    p[0] = e * c - o * s;
    p[1] = e * s + o * c;
}

// ---------------- attention scores: S = scale * Q K^T (causal tiles only) --
__global__ void __launch_bounds__(256) k_score(const float* __restrict__ qkv,
                                               float* __restrict__ sc) {
    int kt = blockIdx.x, qt = blockIdx.y, bh = blockIdx.z;
    if (kt > qt) return;                       // fully masked tile
    int b = bh >> 4, h = bh & 15;
    __shared__ float Qs[64][65];
    __shared__ float Ks[64][65];
    int tid = threadIdx.x;
    const float* qb = qkv + (long)(b * SD + qt * 64) * 3 * DD + h * HDIM;
    const float* kb = qkv + (long)(b * SD + kt * 64) * 3 * DD + DD + h * HDIM;
    #pragma unroll
    for (int r = 0; r < 16; ++r) {
        int e = tid + r * 256;
        int i = e >> 6, d = e & 63;
        Qs[d][i] = qb[(long)i * 3 * DD + d];
        Ks[d][i] = kb[(long)i * 3 * DD + d];
    }
    __syncthreads();
    float acc[4][4] = {};
    int tq = (tid >> 4) * 4, tk = (tid & 15) * 4;
    #pragma unroll
    for (int kk = 0; kk < 64; ++kk) {
        float a[4], bb[4];
        #pragma unroll
        for (int t = 0; t < 4; ++t) a[t] = Qs[kk][tq + t];
        #pragma unroll
        for (int t = 0; t < 4; ++t) bb[t] = Ks[kk][tk + t];
        #pragma unroll
        for (int y = 0; y < 4; ++y)
            #pragma unroll
            for (int x = 0; x < 4; ++x) acc[y][x] += a[y] * bb[x];
    }
    float* out = sc + ((long)bh * SD + qt * 64) * SD + kt * 64;
    #pragma unroll
    for (int y = 0; y < 4; ++y)
        #pragma unroll
        for (int x = 0; x < 4; ++x)
            out[(long)(tq + y) * SD + tk + x] = acc[y][x] * 0.125f;
}

// ---------------- causal softmax (one block per row; single global pass) ---
__global__ void __launch_bounds__(128) k_softmax(float* __restrict__ sc) {
    int row = blockIdx.x;                    // B*H*S rows
    int q = row & (SD - 1);
    float* p = sc + (long)row * SD;
    int tid = threadIdx.x;
    float v[8];
    float m = -INFINITY;
    #pragma unroll
    for (int t = 0; t < 8; ++t) {
        int c = tid + t * 128;
        v[t] = (c <= q) ? p[c] : -INFINITY;
        m = fmaxf(m, v[t]);
    }
    __shared__ float redm[4], reds[4];
    #pragma unroll
    for (int off = 16; off; off >>= 1) m = fmaxf(m, __shfl_xor_sync(0xffffffffu, m, off));
    if ((tid & 31) == 0) redm[tid >> 5] = m;
    __syncthreads();
    m = fmaxf(fmaxf(redm[0], redm[1]), fmaxf(redm[2], redm[3]));
    float s = 0.f;
    #pragma unroll
    for (int t = 0; t < 8; ++t) { v[t] = expf(v[t] - m); s += v[t]; }
    #pragma unroll
    for (int off = 16; off; off >>= 1) s += __shfl_xor_sync(0xffffffffu, s, off);
    if ((tid & 31) == 0) reds[tid >> 5] = s;
    __syncthreads();
    s = reds[0] + reds[1] + reds[2] + reds[3];
    float inv = 1.f / s;
    #pragma unroll
    for (int t = 0; t < 8; ++t) p[tid + t * 128] = v[t] * inv;
}

// ---------------- O = P @ V (causal tiles only), write [n, D] layout -------
__global__ void __launch_bounds__(256) k_av(const float* __restrict__ sc,
                                            const float* __restrict__ qkv,
                                            float* __restrict__ attn) {
    int qt = blockIdx.x, bh = blockIdx.y;
    int b = bh >> 4, h = bh & 15;
    __shared__ float Ps[64][65];
    __shared__ float Vs[64][65];
    int tid = threadIdx.x;
    float acc[4][4] = {};
    int tq = (tid >> 4) * 4, td = (tid & 15) * 4;
    for (int kt = 0; kt <= qt; ++kt) {
        const float* pp = sc + ((long)bh * SD + qt * 64) * SD + kt * 64;
        const float* vb = qkv + (long)(b * SD + kt * 64) * 3 * DD + 2 * DD + h * HDIM;
        #pragma unroll
        for (int r = 0; r < 16; ++r) {
            int e = tid + r * 256;
            int i = e >> 6, d = e & 63;
            Ps[i][d] = pp[(long)i * SD + d];
            Vs[i][d] = vb[(long)i * 3 * DD + d];
        }
        __syncthreads();
        #pragma unroll
        for (int kk = 0; kk < 64; ++kk) {
            float a[4], vv[4];
            #pragma unroll
            for (int t = 0; t < 4; ++t) a[t] = Ps[tq + t][kk];
            #pragma unroll
            for (int t = 0; t < 4; ++t) vv[t] = Vs[kk][td + t];
            #pragma unroll
            for (int y = 0; y < 4; ++y)
                #pragma unroll
                for (int x = 0; x < 4; ++x) acc[y][x] += a[y] * vv[x];
        }
        __syncthreads();
    }
    float* ob = attn + (long)(b * SD + qt * 64) * DD + h * HDIM;
    #pragma unroll
    for (int y = 0; y < 4; ++y)
        #pragma unroll
        for (int x = 0; x < 4; ++x)
            ob[(long)(tq + y) * DD + td + x] = acc[y][x];
}

// ---------------- SwiGLU elementwise ----------------------------------------
__global__ void k_silu(float* __restrict__ g, const float* __restrict__ u, long n) {
    long i = (long)blockIdx.x * 256 + threadIdx.x;
    if (i < n) {
        float s = g[i];
        g[i] = (s / (1.f + expf(-s))) * u[i];
    }
}

// ---------------- head: logits for the 2 last-token rows --------------------
__global__ void __launch_bounds__(256) k_head(const float* __restrict__ hN,
                                              const float* __restrict__ W,
                                              const float* __restrict__ bias,
                                              float* __restrict__ out) {
    int bidx = blockIdx.y;
    int col = blockIdx.x * 256 + threadIdx.x;
    __shared__ float sx[DD];
    const float* xr = hN + (long)(bidx * SD + SD - 1) * DD;
    for (int c = threadIdx.x; c < DD; c += 256) sx[c] = xr[c];
    __syncthreads();
    if (col >= VV) return;
    float acc = 0.f;
    #pragma unroll 8
    for (int k = 0; k < DD; ++k) acc += sx[k] * W[(long)k * VV + col];
    out[(long)bidx * VV + col] = acc + bias[col];
}

// ---------------- driver -----------------------------------------------------
extern "C" void kernel_launch(void* const* d_in, const int* in_sizes, int n_in,
                              void* d_out, int out_size) {
    const int*   tokens = (const int*)  d_in[0];
    const float* embed  = (const float*)d_in[1];
    const float* Wqkv   = (const float*)d_in[2];
    const float* bqkv   = (const float*)d_in[3];
    const float* Wout   = (const float*)d_in[4];
    const float* bout   = (const float*)d_in[5];
    const float* ln1    = (const float*)d_in[6];
    const float* ln2    = (const float*)d_in[7];
    const float* Wg     = (const float*)d_in[8];
    const float* bg     = (const float*)d_in[9];
    const float* Wu     = (const float*)d_in[10];
    const float* bu     = (const float*)d_in[11];
    const float* Wd     = (const float*)d_in[12];
    const float* bd     = (const float*)d_in[13];
    const float* lnf    = (const float*)d_in[14];
    const float* Whead  = (const float*)d_in[15];
    const float* bhead  = (const float*)d_in[16];
    float* out = (float*)d_out;

    float *x, *h, *qkv, *sc, *attn, *gate, *up;
    cudaGetSymbolAddress((void**)&x,    g_x);
    cudaGetSymbolAddress((void**)&h,    g_h);
    cudaGetSymbolAddress((void**)&qkv,  g_qkv);
    cudaGetSymbolAddress((void**)&sc,   g_scores);
    cudaGetSymbolAddress((void**)&attn, g_attn);
    cudaGetSymbolAddress((void**)&gate, g_gate);
    cudaGetSymbolAddress((void**)&up,   g_up);

    k_embed<<<NTOK * DD / 256, 256>>>(tokens, embed, x);

    for (int l = 0; l < LL; ++l) {
        k_rmsnorm<<<NTOK, 256>>>(x, ln1 + (long)l * DD, h);

        dim3 gq(3 * DD / 128, NTOK / 128);
        k_gemm<<<gq, 256>>>(h, Wqkv + (long)l * DD * 3 * DD, bqkv + (long)l * 3 * DD,
                            nullptr, qkv, NTOK, DD, 3 * DD);

        k_rope<<<NTOK * 2 * HH * 32 / 256, 256>>>(qkv);

        dim3 gs(16, 16, BD * HH);
        k_score<<<gs, 256>>>(qkv, sc);

        k_softmax<<<BD * HH * SD, 128>>>(sc);

        dim3 ga(16, BD * HH);
        k_av<<<ga, 256>>>(sc, qkv, attn);

        dim3 go(DD / 128, NTOK / 128);
        k_gemm<<<go, 256>>>(attn, Wout + (long)l * DD * DD, bout + (long)l * DD,
                            x, x, NTOK, DD, DD);

        k_rmsnorm<<<NTOK, 256>>>(x, ln2 + (long)l * DD, h);

        dim3 gm((MMF + 127) / 128, NTOK / 128);
        k_gemm<<<gm, 256>>>(h, Wg + (long)l * DD * MMF, bg + (long)l * MMF,
                            nullptr, gate, NTOK, DD, MMF);
        k_gemm<<<gm, 256>>>(h, Wu + (long)l * DD * MMF, bu + (long)l * MMF,
                            nullptr, up, NTOK, DD, MMF);

        long nel = (long)NTOK * MMF;
        k_silu<<<(int)((nel + 255) / 256), 256>>>(gate, up, nel);

        dim3 gd(DD / 128, NTOK / 128);
        k_gemm<<<gd, 256>>>(gate, Wd + (long)l * MMF * DD, bd + (long)l * DD,
                            x, x, NTOK, MMF, DD);
    }

    k_rmsnorm<<<NTOK, 256>>>(x, lnf, h);
    dim3 gh((VV + 255) / 256, BD);
    k_head<<<gh, 256>>>(h, Whead, bhead, out);
}

// round 3
// speedup vs baseline: 1.5060x; 1.5060x over previous
#include <cuda_runtime.h>
#include <math.h>

#define BD   2
#define SD   1024
#define DD   1024
#define HH   16
#define HDIM 64
#define LL   4
#define MMF  2730
#define VV   32000
#define NTOK (BD*SD)

// ---------------- scratch (device globals; no allocation allowed) ----------
__device__ float g_x[NTOK*DD];
__device__ float g_h[NTOK*DD];
__device__ float g_qkv[NTOK*3*DD];
__device__ float g_scores[(size_t)BD*HH*SD*SD];
__device__ float g_attn[NTOK*DD];
__device__ float g_gate[NTOK*MMF];
__device__ float g_up[NTOK*MMF];

// ---------------- tf32 helpers ----------------------------------------------
__device__ __forceinline__ unsigned f2tf(float f) {
    unsigned r;
    asm("cvt.rna.tf32.f32 %0, %1;" : "=r"(r) : "f"(f));
    return r;
}
// split f = hi + lo, both tf32 (3xTF32 scheme)
__device__ __forceinline__ void split_tf(float f, unsigned& hi, unsigned& lo) {
    hi = f2tf(f);
    float fh = __uint_as_float(hi);
    lo = f2tf(f - fh);
}

__device__ __forceinline__ void mma_tf32(float* d, const unsigned* a,
                                         const unsigned* b, const float* c) {
    asm volatile(
        "mma.sync.aligned.m16n8k8.row.col.f32.tf32.tf32.f32 "
        "{%0,%1,%2,%3}, {%4,%5,%6,%7}, {%8,%9}, {%10,%11,%12,%13};"
        : "=f"(d[0]), "=f"(d[1]), "=f"(d[2]), "=f"(d[3])
        : "r"(a[0]), "r"(a[1]), "r"(a[2]), "r"(a[3]),
          "r"(b[0]), "r"(b[1]),
          "f"(c[0]), "f"(c[1]), "f"(c[2]), "f"(c[3]));
}
// 3 mma: hi*hi + hi*lo + lo*hi
__device__ __forceinline__ void mma3(float* acc, const unsigned* ah, const unsigned* al,
                                     const unsigned* bh, const unsigned* bl) {
    mma_tf32(acc, ah, bh, acc);
    mma_tf32(acc, ah, bl, acc);
    mma_tf32(acc, al, bh, acc);
}

// ---------------- embedding gather ----------------------------------------
__global__ void k_embed(const int* __restrict__ tok, const float* __restrict__ emb,
                        float* __restrict__ x) {
    int i = blockIdx.x * 256 + threadIdx.x;
    int n = i >> 10, d = i & 1023;
    x[i] = emb[(long)tok[n] * DD + d];
}

// ---------------- rmsnorm ---------------------------------------------------
__global__ void __launch_bounds__(256) k_rmsnorm(const float* __restrict__ x,
                                                 const float* __restrict__ w,
                                                 float* __restrict__ o) {
    int row = blockIdx.x;
    const float* xr = x + (long)row * DD;
    float s = 0.f;
    for (int c = threadIdx.x; c < DD; c += 256) { float v = xr[c]; s += v * v; }
    __shared__ float red[8];
    #pragma unroll
    for (int off = 16; off; off >>= 1) s += __shfl_xor_sync(0xffffffffu, s, off);
    if ((threadIdx.x & 31) == 0) red[threadIdx.x >> 5] = s;
    __syncthreads();
    if (threadIdx.x == 0) {
        float t = 0.f;
        #pragma unroll
        for (int i = 0; i < 8; ++i) t += red[i];
        red[0] = t;
    }
    __syncthreads();
    float r = rsqrtf(red[0] * (1.0f / DD) + 1e-6f);
    for (int c = threadIdx.x; c < DD; c += 256)
        o[(long)row * DD + c] = xr[c] * r * w[c];
}

// ---------------- 3xTF32 tensor-core GEMM: C = A@B + bias (+ add) ----------
// A: N x K row-major, B: K x M row-major. Block 128x128, BK=16, 256 thr.
// A smem [m][k] stride 20 (20%32==4 -> conflict-free frags).
// B smem [k][n] stride 136 (136%32==8 -> conflict-free frags).
#define GASTR 20
#define GBSTR 136
__global__ void __launch_bounds__(256) k_gemm_tc(const float* __restrict__ A,
                                                 const float* __restrict__ B,
                                                 const float* __restrict__ bias,
                                                 const float* __restrict__ add,
                                                 float* __restrict__ C,
                                                 int N, int K, int M) {
    __shared__ unsigned Ah[128 * GASTR], Al[128 * GASTR];
    __shared__ unsigned Bh[16 * GBSTR],  Bl[16 * GBSTR];
    int tid = threadIdx.x;
    int wid = tid >> 5, lane = tid & 31;
    int g = lane >> 2, t = lane & 3;
    int wm = (wid & 1) * 64, wn = (wid >> 1) * 32;
    int br = blockIdx.y * 128, bc = blockIdx.x * 128;
    float acc[4][4][4] = {};

    for (int k0 = 0; k0 < K; k0 += 16) {
        #pragma unroll
        for (int it = 0; it < 8; ++it) {
            int idx = tid + it * 256;
            int m = idx >> 4, kk = idx & 15;
            int gk = k0 + kk;
            float v = (gk < K) ? A[(long)(br + m) * K + gk] : 0.f;
            unsigned h, l; split_tf(v, h, l);
            Ah[m * GASTR + kk] = h;
            Al[m * GASTR + kk] = l;
        }
        #pragma unroll
        for (int it = 0; it < 8; ++it) {
            int idx = tid + it * 256;
            int kk = idx >> 7, n = idx & 127;
            int gk = k0 + kk, gn = bc + n;
            float v = (gk < K && gn < M) ? B[(long)gk * M + gn] : 0.f;
            unsigned h, l; split_tf(v, h, l);
            Bh[kk * GBSTR + n] = h;
            Bl[kk * GBSTR + n] = l;
        }
        __syncthreads();
        #pragma unroll
        for (int ks = 0; ks < 2; ++ks) {
            unsigned ah[4][4], al[4][4], bh[4][2], bl[4][2];
            int kc = ks * 8 + t;
            #pragma unroll
            for (int mt = 0; mt < 4; ++mt) {
                int mrow = wm + mt * 16 + g;
                ah[mt][0] = Ah[mrow * GASTR + kc];
                ah[mt][1] = Ah[(mrow + 8) * GASTR + kc];
                ah[mt][2] = Ah[mrow * GASTR + kc + 4];
                ah[mt][3] = Ah[(mrow + 8) * GASTR + kc + 4];
                al[mt][0] = Al[mrow * GASTR + kc];
                al[mt][1] = Al[(mrow + 8) * GASTR + kc];
                al[mt][2] = Al[mrow * GASTR + kc + 4];
                al[mt][3] = Al[(mrow + 8) * GASTR + kc + 4];
            }
            #pragma unroll
            for (int nt = 0; nt < 4; ++nt) {
                int nc = wn + nt * 8 + g;
                bh[nt][0] = Bh[kc * GBSTR + nc];
                bh[nt][1] = Bh[(kc + 4) * GBSTR + nc];
                bl[nt][0] = Bl[kc * GBSTR + nc];
                bl[nt][1] = Bl[(kc + 4) * GBSTR + nc];
            }
            #pragma unroll
            for (int mt = 0; mt < 4; ++mt)
                #pragma unroll
                for (int nt = 0; nt < 4; ++nt)
                    mma3(acc[mt][nt], ah[mt], al[mt], bh[nt], bl[nt]);
        }
        __syncthreads();
    }

    #pragma unroll
    for (int mt = 0; mt < 4; ++mt) {
        int r0 = br + wm + mt * 16 + g;
        #pragma unroll
        for (int nt = 0; nt < 4; ++nt) {
            int c0 = bc + wn + nt * 8 + 2 * t;
            const float* a4 = acc[mt][nt];
            if (c0 < M) {
                float bv = bias ? bias[c0] : 0.f;
                float v0 = a4[0] + bv;
                float v2 = a4[2] + bv;
                if (add) { v0 += add[(long)r0 * M + c0]; v2 += add[(long)(r0 + 8) * M + c0]; }
                C[(long)r0 * M + c0] = v0;
                C[(long)(r0 + 8) * M + c0] = v2;
            }
            if (c0 + 1 < M) {
                float bv = bias ? bias[c0 + 1] : 0.f;
                float v1 = a4[1] + bv;
                float v3 = a4[3] + bv;
                if (add) { v1 += add[(long)r0 * M + c0 + 1]; v3 += add[(long)(r0 + 8) * M + c0 + 1]; }
                C[(long)r0 * M + c0 + 1] = v1;
                C[(long)(r0 + 8) * M + c0 + 1] = v3;
            }
        }
    }
}

// ---------------- RoPE (in-place on q,k halves of qkv) ---------------------
__global__ void k_rope(float* __restrict__ qkv) {
    int idx = blockIdx.x * 256 + threadIdx.x;
    int j = idx & 31;
    int h = (idx >> 5) & 15;
    int t = (idx >> 9) & 1;
    int n = idx >> 10;
    int pos = n & (SD - 1);
    float freq = powf(10000.f, -(float)j / 32.f);
    float ang = (float)pos * freq;
    float s, c;
    sincosf(ang, &s, &c);
    float* p = qkv + (long)n * 3 * DD + t * DD + h * HDIM + 2 * j;
    float e = p[0], o = p[1];
    p[0] = e * c - o * s;
    p[1] = e * s + o * c;
}

// ---------------- scores via 3xTF32 mma: S = scale * Q K^T ------------------
// Computes the transposed tile: A = K tile (m=ktok), B = Q (col-major).
// d-dimension chunked by 32 to fit hi/lo tiles in 48KB smem.
__global__ void __launch_bounds__(128) k_score_tc(const float* __restrict__ qkv,
                                                  float* __restrict__ sc) {
    int kt = blockIdx.x, qt = blockIdx.y, bh = blockIdx.z;
    if (kt > qt) return;
    int b = bh >> 4, h = bh & 15;
    __shared__ unsigned Kh[64 * 36], Kl[64 * 36];
    __shared__ unsigned Qh[64 * 36], Ql[64 * 36];
    int tid = threadIdx.x, wid = tid >> 5, lane = tid & 31;
    int g = lane >> 2, t = lane & 3;
    const float* qb = qkv + (long)(b * SD + qt * 64) * 3 * DD + h * HDIM;
    const float* kb = qkv + (long)(b * SD + kt * 64) * 3 * DD + DD + h * HDIM;
    float acc[8][4] = {};
    for (int c0 = 0; c0 < 64; c0 += 32) {
        #pragma unroll
        for (int it = 0; it < 4; ++it) {
            int idx = tid + it * 128;
            int row = idx >> 3, d4 = (idx & 7) * 4;
            float4 qv = *(const float4*)(qb + (long)row * 3 * DD + c0 + d4);
            float4 kv = *(const float4*)(kb + (long)row * 3 * DD + c0 + d4);
            unsigned h0, l0;
            split_tf(qv.x, h0, l0); Qh[row*36+d4+0]=h0; Ql[row*36+d4+0]=l0;
            split_tf(qv.y, h0, l0); Qh[row*36+d4+1]=h0; Ql[row*36+d4+1]=l0;
            split_tf(qv.z, h0, l0); Qh[row*36+d4+2]=h0; Ql[row*36+d4+2]=l0;
            split_tf(qv.w, h0, l0); Qh[row*36+d4+3]=h0; Ql[row*36+d4+3]=l0;
            split_tf(kv.x, h0, l0); Kh[row*36+d4+0]=h0; Kl[row*36+d4+0]=l0;
            split_tf(kv.y, h0, l0); Kh[row*36+d4+1]=h0; Kl[row*36+d4+1]=l0;
            split_tf(kv.z, h0, l0); Kh[row*36+d4+2]=h0; Kl[row*36+d4+2]=l0;
            split_tf(kv.w, h0, l0); Kh[row*36+d4+3]=h0; Kl[row*36+d4+3]=l0;
        }
        __syncthreads();
        #pragma unroll
        for (int ks = 0; ks < 4; ++ks) {
            int kc = ks * 8 + t;
            unsigned ah[4], al[4];
            int mrow = wid * 16 + g;
            ah[0] = Kh[mrow * 36 + kc];
            ah[1] = Kh[(mrow + 8) * 36 + kc];
            ah[2] = Kh[mrow * 36 + kc + 4];
            ah[3] = Kh[(mrow + 8) * 36 + kc + 4];
            al[0] = Kl[mrow * 36 + kc];
            al[1] = Kl[(mrow + 8) * 36 + kc];
            al[2] = Kl[mrow * 36 + kc + 4];
            al[3] = Kl[(mrow + 8) * 36 + kc + 4];
            #pragma unroll
            for (int nt = 0; nt < 8; ++nt) {
                int q = nt * 8 + g;
                unsigned bh2[2], bl2[2];
                bh2[0] = Qh[q * 36 + kc];
                bh2[1] = Qh[q * 36 + kc + 4];
                bl2[0] = Ql[q * 36 + kc];
                bl2[1] = Ql[q * 36 + kc + 4];
                mma3(acc[nt], ah, al, bh2, bl2);
            }
        }
        __syncthreads();
    }
    float* base = sc + ((long)bh * SD + qt * 64) * SD + kt * 64;
    int m0 = wid * 16 + g;
    #pragma unroll
    for (int nt = 0; nt < 8; ++nt) {
        int q0 = nt * 8 + 2 * t;
        base[(long)q0 * SD + m0]           = acc[nt][0] * 0.125f;
        base[(long)(q0 + 1) * SD + m0]     = acc[nt][1] * 0.125f;
        base[(long)q0 * SD + m0 + 8]       = acc[nt][2] * 0.125f;
        base[(long)(q0 + 1) * SD + m0 + 8] = acc[nt][3] * 0.125f;
    }
}

// ---------------- causal softmax -------------------------------------------
__global__ void __launch_bounds__(128) k_softmax(float* __restrict__ sc) {
    int row = blockIdx.x;
    int q = row & (SD - 1);
    float* p = sc + (long)row * SD;
    int tid = threadIdx.x;
    float v[8];
    float m = -INFINITY;
    #pragma unroll
    for (int t = 0; t < 8; ++t) {
        int c = tid + t * 128;
        v[t] = (c <= q) ? p[c] : -INFINITY;
        m = fmaxf(m, v[t]);
    }
    __shared__ float redm[4], reds[4];
    #pragma unroll
    for (int off = 16; off; off >>= 1) m = fmaxf(m, __shfl_xor_sync(0xffffffffu, m, off));
    if ((tid & 31) == 0) redm[tid >> 5] = m;
    __syncthreads();
    m = fmaxf(fmaxf(redm[0], redm[1]), fmaxf(redm[2], redm[3]));
    float s = 0.f;
    #pragma unroll
    for (int t = 0; t < 8; ++t) { v[t] = expf(v[t] - m); s += v[t]; }
    #pragma unroll
    for (int off = 16; off; off >>= 1) s += __shfl_xor_sync(0xffffffffu, s, off);
    if ((tid & 31) == 0) reds[tid >> 5] = s;
    __syncthreads();
    s = reds[0] + reds[1] + reds[2] + reds[3];
    float inv = 1.f / s;
    #pragma unroll
    for (int t = 0; t < 8; ++t) p[tid + t * 128] = v[t] * inv;
}

// ---------------- O = P @ V via 3xTF32 mma (causal tiles only) --------------
// A = P tile [q][k] stride 36; B = V tile [k][d] stride 72; k chunked by 32.
__global__ void __launch_bounds__(128) k_av_tc(const float* __restrict__ sc,
                                               const float* __restrict__ qkv,
                                               float* __restrict__ attn) {
    int qt = blockIdx.x, bh = blockIdx.y;
    int b = bh >> 4, h = bh & 15;
    __shared__ unsigned Ph[64 * 36], Pl[64 * 36];
    __shared__ unsigned Vh[32 * 72], Vl[32 * 72];
    int tid = threadIdx.x, wid = tid >> 5, lane = tid & 31;
    int g = lane >> 2, t = lane & 3;
    float acc[8][4] = {};
    for (int kt = 0; kt <= qt; ++kt) {
        const float* pp = sc + ((long)bh * SD + qt * 64) * SD + kt * 64;
        const float* vb = qkv + (long)(b * SD + kt * 64) * 3 * DD + 2 * DD + h * HDIM;
        for (int c0 = 0; c0 < 64; c0 += 32) {
            #pragma unroll
            for (int it = 0; it < 4; ++it) {
                int idx = tid + it * 128;
                // P: 64 q-rows x 32 k-cols
                int prow = idx >> 3, pd4 = (idx & 7) * 4;
                float4 pv = *(const float4*)(pp + (long)prow * SD + c0 + pd4);
                unsigned h0, l0;
                split_tf(pv.x, h0, l0); Ph[prow*36+pd4+0]=h0; Pl[prow*36+pd4+0]=l0;
                split_tf(pv.y, h0, l0); Ph[prow*36+pd4+1]=h0; Pl[prow*36+pd4+1]=l0;
                split_tf(pv.z, h0, l0); Ph[prow*36+pd4+2]=h0; Pl[prow*36+pd4+2]=l0;
                split_tf(pv.w, h0, l0); Ph[prow*36+pd4+3]=h0; Pl[prow*36+pd4+3]=l0;
                // V: 32 k-rows x 64 d-cols
                int vrow = idx >> 4, vd4 = (idx & 15) * 4;
                float4 vv = *(const float4*)(vb + (long)(c0 + vrow) * 3 * DD + vd4);
                split_tf(vv.x, h0, l0); Vh[vrow*72+vd4+0]=h0; Vl[vrow*72+vd4+0]=l0;
                split_tf(vv.y, h0, l0); Vh[vrow*72+vd4+1]=h0; Vl[vrow*72+vd4+1]=l0;
                split_tf(vv.z, h0, l0); Vh[vrow*72+vd4+2]=h0; Vl[vrow*72+vd4+2]=l0;
                split_tf(vv.w, h0, l0); Vh[vrow*72+vd4+3]=h0; Vl[vrow*72+vd4+3]=l0;
            }
            __syncthreads();
            #pragma unroll
            for (int ks = 0; ks < 4; ++ks) {
                int kc = ks * 8 + t;
                unsigned ah[4], al[4];
                int mrow = wid * 16 + g;
                ah[0] = Ph[mrow * 36 + kc];
                ah[1] = Ph[(mrow + 8) * 36 + kc];
                ah[2] = Ph[mrow * 36 + kc + 4];
                ah[3] = Ph[(mrow + 8) * 36 + kc + 4];
                al[0] = Pl[mrow * 36 + kc];
                al[1] = Pl[(mrow + 8) * 36 + kc];
                al[2] = Pl[mrow * 36 + kc + 4];
                al[3] = Pl[(mrow + 8) * 36 + kc + 4];
                #pragma unroll
                for (int nt = 0; nt < 8; ++nt) {
                    int nc = nt * 8 + g;
                    unsigned bh2[2], bl2[2];
                    bh2[0] = Vh[kc * 72 + nc];
                    bh2[1] = Vh[(kc + 4) * 72 + nc];
                    bl2[0] = Vl[kc * 72 + nc];
                    bl2[1] = Vl[(kc + 4) * 72 + nc];
                    mma3(acc[nt], ah, al, bh2, bl2);
                }
            }
            __syncthreads();
        }
    }
    float* ob = attn + (long)(b * SD + qt * 64) * DD + h * HDIM;
    int m0 = wid * 16 + g;
    #pragma unroll
    for (int nt = 0; nt < 8; ++nt) {
        int d0 = nt * 8 + 2 * t;
        ob[(long)m0 * DD + d0]           = acc[nt][0];
        ob[(long)m0 * DD + d0 + 1]       = acc[nt][1];
        ob[(long)(m0 + 8) * DD + d0]     = acc[nt][2];
        ob[(long)(m0 + 8) * DD + d0 + 1] = acc[nt][3];
    }
}

// ---------------- SwiGLU elementwise ----------------------------------------
__global__ void k_silu(float* __restrict__ g, const float* __restrict__ u, long n) {
    long i = (long)blockIdx.x * 256 + threadIdx.x;
    if (i < n) {
        float s = g[i];
        g[i] = (s / (1.f + expf(-s))) * u[i];
    }
}

// ---------------- head: logits for the 2 last-token rows --------------------
__global__ void __launch_bounds__(256) k_head(const float* __restrict__ hN,
                                              const float* __restrict__ W,
                                              const float* __restrict__ bias,
                                              float* __restrict__ out) {
    int bidx = blockIdx.y;
    int col = blockIdx.x * 256 + threadIdx.x;
    __shared__ float sx[DD];
    const float* xr = hN + (long)(bidx * SD + SD - 1) * DD;
    for (int c = threadIdx.x; c < DD; c += 256) sx[c] = xr[c];
    __syncthreads();
    if (col >= VV) return;
    float acc = 0.f;
    #pragma unroll 8
    for (int k = 0; k < DD; ++k) acc += sx[k] * W[(long)k * VV + col];
    out[(long)bidx * VV + col] = acc + bias[col];
}

// ---------------- driver -----------------------------------------------------
extern "C" void kernel_launch(void* const* d_in, const int* in_sizes, int n_in,
                              void* d_out, int out_size) {
    const int*   tokens = (const int*)  d_in[0];
    const float* embed  = (const float*)d_in[1];
    const float* Wqkv   = (const float*)d_in[2];
    const float* bqkv   = (const float*)d_in[3];
    const float* Wout   = (const float*)d_in[4];
    const float* bout   = (const float*)d_in[5];
    const float* ln1    = (const float*)d_in[6];
    const float* ln2    = (const float*)d_in[7];
    const float* Wg     = (const float*)d_in[8];
    const float* bg     = (const float*)d_in[9];
    const float* Wu     = (const float*)d_in[10];
    const float* bu     = (const float*)d_in[11];
    const float* Wd     = (const float*)d_in[12];
    const float* bd     = (const float*)d_in[13];
    const float* lnf    = (const float*)d_in[14];
    const float* Whead  = (const float*)d_in[15];
    const float* bhead  = (const float*)d_in[16];
    float* out = (float*)d_out;

    float *x, *h, *qkv, *sc, *attn, *gate, *up;
    cudaGetSymbolAddress((void**)&x,    g_x);
    cudaGetSymbolAddress((void**)&h,    g_h);
    cudaGetSymbolAddress((void**)&qkv,  g_qkv);
    cudaGetSymbolAddress((void**)&sc,   g_scores);
    cudaGetSymbolAddress((void**)&attn, g_attn);
    cudaGetSymbolAddress((void**)&gate, g_gate);
    cudaGetSymbolAddress((void**)&up,   g_up);

    k_embed<<<NTOK * DD / 256, 256>>>(tokens, embed, x);

    for (int l = 0; l < LL; ++l) {
        k_rmsnorm<<<NTOK, 256>>>(x, ln1 + (long)l * DD, h);

        dim3 gq(3 * DD / 128, NTOK / 128);
        k_gemm_tc<<<gq, 256>>>(h, Wqkv + (long)l * DD * 3 * DD, bqkv + (long)l * 3 * DD,
                               nullptr, qkv, NTOK, DD, 3 * DD);

        k_rope<<<NTOK * 2 * HH * 32 / 256, 256>>>(qkv);

        dim3 gs(16, 16, BD * HH);
        k_score_tc<<<gs, 128>>>(qkv, sc);

        k_softmax<<<BD * HH * SD, 128>>>(sc);

        dim3 ga(16, BD * HH);
        k_av_tc<<<ga, 128>>>(sc, qkv, attn);

        dim3 go(DD / 128, NTOK / 128);
        k_gemm_tc<<<go, 256>>>(attn, Wout + (long)l * DD * DD, bout + (long)l * DD,
                               x, x, NTOK, DD, DD);

        k_rmsnorm<<<NTOK, 256>>>(x, ln2 + (long)l * DD, h);

        dim3 gm((MMF + 127) / 128, NTOK / 128);
        k_gemm_tc<<<gm, 256>>>(h, Wg + (long)l * DD * MMF, bg + (long)l * MMF,
                               nullptr, gate, NTOK, DD, MMF);
        k_gemm_tc<<<gm, 256>>>(h, Wu + (long)l * DD * MMF, bu + (long)l * MMF,
                               nullptr, up, NTOK, DD, MMF);

        long nel = (long)NTOK * MMF;
        k_silu<<<(int)((nel + 255) / 256), 256>>>(gate, up, nel);

        dim3 gd(DD / 128, NTOK / 128);
        k_gemm_tc<<<gd, 256>>>(gate, Wd + (long)l * MMF * DD, bd + (long)l * DD,
                               x, x, NTOK, MMF, DD);
    }

    k_rmsnorm<<<NTOK, 256>>>(x, lnf, h);
    dim3 gh((VV + 255) / 256, BD);
    k_head<<<gh, 256>>>(h, Whead, bhead, out);
}

// round 4
// speedup vs baseline: 1.8480x; 1.2271x over previous
#include <cuda_runtime.h>
#include <cuda_bf16.h>
#include <math.h>

#define BD   2
#define SD   1024
#define DD   1024
#define HH   16
#define HDIM 64
#define LL   4
#define MMF  2730
#define VV   32000
#define NTOK (BD*SD)

// ---------------- scratch (device globals; no allocation allowed) ----------
__device__ float g_x[NTOK*DD];
__device__ float g_qkv[NTOK*3*DD];
__device__ float g_scores[(size_t)BD*HH*SD*SD];
__device__ float g_gate[NTOK*MMF];
__device__ float g_up[NTOK*MMF];

// activation hi/lo (bf16 split), k-major
__device__ __nv_bfloat16 g_h_h[NTOK*DD],    g_h_l[NTOK*DD];
__device__ __nv_bfloat16 g_attn_h[NTOK*DD], g_attn_l[NTOK*DD];
__device__ __nv_bfloat16 g_gate_h[NTOK*MMF], g_gate_l[NTOK*MMF];

// transposed weights hi/lo (bf16), layout [out_col][k] (k-major)
__device__ __nv_bfloat16 g_wqkvT_h[LL*3*DD*DD], g_wqkvT_l[LL*3*DD*DD];
__device__ __nv_bfloat16 g_woutT_h[LL*DD*DD],   g_woutT_l[LL*DD*DD];
__device__ __nv_bfloat16 g_wgT_h[LL*MMF*DD],    g_wgT_l[LL*MMF*DD];
__device__ __nv_bfloat16 g_wuT_h[LL*MMF*DD],    g_wuT_l[LL*MMF*DD];
__device__ __nv_bfloat16 g_wdT_h[LL*DD*MMF],    g_wdT_l[LL*DD*MMF];

// ---------------- helpers ----------------------------------------------------
__device__ __forceinline__ unsigned f2tf(float f) {
    unsigned r;
    asm("cvt.rna.tf32.f32 %0, %1;" : "=r"(r) : "f"(f));
    return r;
}
__device__ __forceinline__ void split_tf(float f, unsigned& hi, unsigned& lo) {
    hi = f2tf(f);
    lo = f2tf(f - __uint_as_float(hi));
}
__device__ __forceinline__ void split_bf(float f, __nv_bfloat16& h, __nv_bfloat16& l) {
    h = __float2bfloat16(f);
    l = __float2bfloat16(f - __bfloat162float(h));
}

__device__ __forceinline__ void mma_tf32(float* d, const unsigned* a,
                                         const unsigned* b, const float* c) {
    asm volatile(
        "mma.sync.aligned.m16n8k8.row.col.f32.tf32.tf32.f32 "
        "{%0,%1,%2,%3}, {%4,%5,%6,%7}, {%8,%9}, {%10,%11,%12,%13};"
        : "=f"(d[0]), "=f"(d[1]), "=f"(d[2]), "=f"(d[3])
        : "r"(a[0]), "r"(a[1]), "r"(a[2]), "r"(a[3]),
          "r"(b[0]), "r"(b[1]),
          "f"(c[0]), "f"(c[1]), "f"(c[2]), "f"(c[3]));
}
__device__ __forceinline__ void mma3_tf(float* acc, const unsigned* ah, const unsigned* al,
                                        const unsigned* bh, const unsigned* bl) {
    mma_tf32(acc, ah, bh, acc);
    mma_tf32(acc, ah, bl, acc);
    mma_tf32(acc, al, bh, acc);
}

__device__ __forceinline__ void mma_bf16(float* d, const unsigned* a,
                                         const unsigned* b, const float* c) {
    asm volatile(
        "mma.sync.aligned.m16n8k16.row.col.f32.bf16.bf16.f32 "
        "{%0,%1,%2,%3}, {%4,%5,%6,%7}, {%8,%9}, {%10,%11,%12,%13};"
        : "=f"(d[0]), "=f"(d[1]), "=f"(d[2]), "=f"(d[3])
        : "r"(a[0]), "r"(a[1]), "r"(a[2]), "r"(a[3]),
          "r"(b[0]), "r"(b[1]),
          "f"(c[0]), "f"(c[1]), "f"(c[2]), "f"(c[3]));
}

// ---------------- weight transpose + bf16 split -----------------------------
// W: K x M fp32 row-major  ->  Th/Tl: M x K bf16 (k-major rows)
__global__ void k_wsplit(const float* __restrict__ W,
                         __nv_bfloat16* __restrict__ Th,
                         __nv_bfloat16* __restrict__ Tl, int K, int M) {
    __shared__ float t[32][33];
    int m0 = blockIdx.x * 32, k0 = blockIdx.y * 32;
    int tx = threadIdx.x, ty = threadIdx.y;
    #pragma unroll
    for (int i = 0; i < 32; i += 8) {
        int k = k0 + ty + i, m = m0 + tx;
        t[ty + i][tx] = (k < K && m < M) ? W[(long)k * M + m] : 0.f;
    }
    __syncthreads();
    #pragma unroll
    for (int i = 0; i < 32; i += 8) {
        int m = m0 + ty + i, k = k0 + tx;
        if (m < M && k < K) {
            __nv_bfloat16 h, l;
            split_bf(t[tx][ty + i], h, l);
            Th[(long)m * K + k] = h;
            Tl[(long)m * K + k] = l;
        }
    }
}

// ---------------- embedding gather ----------------------------------------
__global__ void k_embed(const int* __restrict__ tok, const float* __restrict__ emb,
                        float* __restrict__ x) {
    int i = blockIdx.x * 256 + threadIdx.x;
    int n = i >> 10, d = i & 1023;
    x[i] = emb[(long)tok[n] * DD + d];
}

// ---------------- rmsnorm -> bf16 hi/lo -------------------------------------
__global__ void __launch_bounds__(256) k_rmsnorm(const float* __restrict__ x,
                                                 const float* __restrict__ w,
                                                 __nv_bfloat16* __restrict__ oh,
                                                 __nv_bfloat16* __restrict__ ol) {
    int row = blockIdx.x;
    const float* xr = x + (long)row * DD;
    float s = 0.f;
    for (int c = threadIdx.x; c < DD; c += 256) { float v = xr[c]; s += v * v; }
    __shared__ float red[8];
    #pragma unroll
    for (int off = 16; off; off >>= 1) s += __shfl_xor_sync(0xffffffffu, s, off);
    if ((threadIdx.x & 31) == 0) red[threadIdx.x >> 5] = s;
    __syncthreads();
    if (threadIdx.x == 0) {
        float t = 0.f;
        #pragma unroll
        for (int i = 0; i < 8; ++i) t += red[i];
        red[0] = t;
    }
    __syncthreads();
    float r = rsqrtf(red[0] * (1.0f / DD) + 1e-6f);
    for (int c = threadIdx.x; c < DD; c += 256) {
        float v = xr[c] * r * w[c];
        __nv_bfloat16 h, l;
        split_bf(v, h, l);
        oh[(long)row * DD + c] = h;
        ol[(long)row * DD + c] = l;
    }
}

// ---------------- bf16 split-3 tensor-core GEMM -----------------------------
// A: N x K (bf16 hi/lo, k-major), B: M x K (bf16 hi/lo, k-major, pre-transposed)
// C = A@B^T + bias (+ add), fp32 out. Block 128x128, BK=32, 256 thr.
// smem stored as 32-bit words (= bf16 k-pairs), row stride 20 words (20%32==4).
#define XS 20
__global__ void __launch_bounds__(256, 2) k_gemm_bf3(
        const __nv_bfloat16* __restrict__ Ah_, const __nv_bfloat16* __restrict__ Al_,
        const __nv_bfloat16* __restrict__ Bh_, const __nv_bfloat16* __restrict__ Bl_,
        const float* __restrict__ bias, const float* __restrict__ add,
        float* __restrict__ C, int N, int K, int M) {
    __shared__ unsigned Ash[128 * XS], Asl[128 * XS];
    __shared__ unsigned Bsh[128 * XS], Bsl[128 * XS];
    const unsigned* Ahw = (const unsigned*)Ah_;
    const unsigned* Alw = (const unsigned*)Al_;
    const unsigned* Bhw = (const unsigned*)Bh_;
    const unsigned* Blw = (const unsigned*)Bl_;
    int tid = threadIdx.x, wid = tid >> 5, lane = tid & 31;
    int g = lane >> 2, t = lane & 3;
    int wm = (wid & 1) * 64, wn = (wid >> 1) * 32;
    int br = blockIdx.y * 128, bc = blockIdx.x * 128;
    int Kw = K >> 1;
    float acc[4][4][4] = {};

    for (int k0 = 0; k0 < K; k0 += 32) {
        int kw0 = k0 >> 1;
        #pragma unroll
        for (int it = 0; it < 8; ++it) {
            int idx = tid + it * 256;
            int row = idx >> 4, w = idx & 15;
            bool kv = (k0 + 2 * w) < K;
            long aoff = (long)(br + row) * Kw + kw0 + w;
            Ash[row * XS + w] = kv ? Ahw[aoff] : 0u;
            Asl[row * XS + w] = kv ? Alw[aoff] : 0u;
            int brow = bc + row;
            bool bv = kv && (brow < M);
            long boff = (long)brow * Kw + kw0 + w;
            Bsh[row * XS + w] = bv ? Bhw[boff] : 0u;
            Bsl[row * XS + w] = bv ? Blw[boff] : 0u;
        }
        __syncthreads();
        #pragma unroll
        for (int ks = 0; ks < 2; ++ks) {
            int kpb = ks * 8;
            unsigned ah[4][4], al[4][4], bh[4][2], bl[4][2];
            #pragma unroll
            for (int mt = 0; mt < 4; ++mt) {
                int mrow = wm + mt * 16 + g;
                ah[mt][0] = Ash[mrow * XS + kpb + t];
                ah[mt][1] = Ash[(mrow + 8) * XS + kpb + t];
                ah[mt][2] = Ash[mrow * XS + kpb + t + 4];
                ah[mt][3] = Ash[(mrow + 8) * XS + kpb + t + 4];
                al[mt][0] = Asl[mrow * XS + kpb + t];
                al[mt][1] = Asl[(mrow + 8) * XS + kpb + t];
                al[mt][2] = Asl[mrow * XS + kpb + t + 4];
                al[mt][3] = Asl[(mrow + 8) * XS + kpb + t + 4];
            }
            #pragma unroll
            for (int nt = 0; nt < 4; ++nt) {
                int nrow = wn + nt * 8 + g;
                bh[nt][0] = Bsh[nrow * XS + kpb + t];
                bh[nt][1] = Bsh[nrow * XS + kpb + t + 4];
                bl[nt][0] = Bsl[nrow * XS + kpb + t];
                bl[nt][1] = Bsl[nrow * XS + kpb + t + 4];
            }
            #pragma unroll
            for (int mt = 0; mt < 4; ++mt)
                #pragma unroll
                for (int nt = 0; nt < 4; ++nt) {
                    mma_bf16(acc[mt][nt], ah[mt], bh[nt], acc[mt][nt]);
                    mma_bf16(acc[mt][nt], ah[mt], bl[nt], acc[mt][nt]);
                    mma_bf16(acc[mt][nt], al[mt], bh[nt], acc[mt][nt]);
                }
        }
        __syncthreads();
    }

    #pragma unroll
    for (int mt = 0; mt < 4; ++mt) {
        int r0 = br + wm + mt * 16 + g;
        #pragma unroll
        for (int nt = 0; nt < 4; ++nt) {
            int c0 = bc + wn + nt * 8 + 2 * t;
            const float* a4 = acc[mt][nt];
            if (c0 < M) {
                float bv = bias ? bias[c0] : 0.f;
                float v0 = a4[0] + bv;
                float v2 = a4[2] + bv;
                if (add) { v0 += add[(long)r0 * M + c0]; v2 += add[(long)(r0 + 8) * M + c0]; }
                C[(long)r0 * M + c0] = v0;
                C[(long)(r0 + 8) * M + c0] = v2;
            }
            if (c0 + 1 < M) {
                float bv = bias ? bias[c0 + 1] : 0.f;
                float v1 = a4[1] + bv;
                float v3 = a4[3] + bv;
                if (add) { v1 += add[(long)r0 * M + c0 + 1]; v3 += add[(long)(r0 + 8) * M + c0 + 1]; }
                C[(long)r0 * M + c0 + 1] = v1;
                C[(long)(r0 + 8) * M + c0 + 1] = v3;
            }
        }
    }
}

// ---------------- RoPE (in-place on q,k halves of qkv) ---------------------
__global__ void k_rope(float* __restrict__ qkv) {
    int idx = blockIdx.x * 256 + threadIdx.x;
    int j = idx & 31;
    int h = (idx >> 5) & 15;
    int t = (idx >> 9) & 1;
    int n = idx >> 10;
    int pos = n & (SD - 1);
    float freq = powf(10000.f, -(float)j / 32.f);
    float ang = (float)pos * freq;
    float s, c;
    sincosf(ang, &s, &c);
    float* p = qkv + (long)n * 3 * DD + t * DD + h * HDIM + 2 * j;
    float e = p[0], o = p[1];
    p[0] = e * c - o * s;
    p[1] = e * s + o * c;
}

// ---------------- scores via 3xTF32 mma: S = scale * Q K^T ------------------
__global__ void __launch_bounds__(128) k_score_tc(const float* __restrict__ qkv,
                                                  float* __restrict__ sc) {
    int kt = blockIdx.x, qt = blockIdx.y, bh = blockIdx.z;
    if (kt > qt) return;
    int b = bh >> 4, h = bh & 15;
    __shared__ unsigned Kh[64 * 36], Kl[64 * 36];
    __shared__ unsigned Qh[64 * 36], Ql[64 * 36];
    int tid = threadIdx.x, wid = tid >> 5, lane = tid & 31;
    int g = lane >> 2, t = lane & 3;
    const float* qb = qkv + (long)(b * SD + qt * 64) * 3 * DD + h * HDIM;
    const float* kb = qkv + (long)(b * SD + kt * 64) * 3 * DD + DD + h * HDIM;
    float acc[8][4] = {};
    for (int c0 = 0; c0 < 64; c0 += 32) {
        #pragma unroll
        for (int it = 0; it < 4; ++it) {
            int idx = tid + it * 128;
            int row = idx >> 3, d4 = (idx & 7) * 4;
            float4 qv = *(const float4*)(qb + (long)row * 3 * DD + c0 + d4);
            float4 kv = *(const float4*)(kb + (long)row * 3 * DD + c0 + d4);
            unsigned h0, l0;
            split_tf(qv.x, h0, l0); Qh[row*36+d4+0]=h0; Ql[row*36+d4+0]=l0;
            split_tf(qv.y, h0, l0); Qh[row*36+d4+1]=h0; Ql[row*36+d4+1]=l0;
            split_tf(qv.z, h0, l0); Qh[row*36+d4+2]=h0; Ql[row*36+d4+2]=l0;
            split_tf(qv.w, h0, l0); Qh[row*36+d4+3]=h0; Ql[row*36+d4+3]=l0;
            split_tf(kv.x, h0, l0); Kh[row*36+d4+0]=h0; Kl[row*36+d4+0]=l0;
            split_tf(kv.y, h0, l0); Kh[row*36+d4+1]=h0; Kl[row*36+d4+1]=l0;
            split_tf(kv.z, h0, l0); Kh[row*36+d4+2]=h0; Kl[row*36+d4+2]=l0;
            split_tf(kv.w, h0, l0); Kh[row*36+d4+3]=h0; Kl[row*36+d4+3]=l0;
        }
        __syncthreads();
        #pragma unroll
        for (int ks = 0; ks < 4; ++ks) {
            int kc = ks * 8 + t;
            unsigned ah[4], al[4];
            int mrow = wid * 16 + g;
            ah[0] = Kh[mrow * 36 + kc];
            ah[1] = Kh[(mrow + 8) * 36 + kc];
            ah[2] = Kh[mrow * 36 + kc + 4];
            ah[3] = Kh[(mrow + 8) * 36 + kc + 4];
            al[0] = Kl[mrow * 36 + kc];
            al[1] = Kl[(mrow + 8) * 36 + kc];
            al[2] = Kl[mrow * 36 + kc + 4];
            al[3] = Kl[(mrow + 8) * 36 + kc + 4];
            #pragma unroll
            for (int nt = 0; nt < 8; ++nt) {
                int q = nt * 8 + g;
                unsigned bh2[2], bl2[2];
                bh2[0] = Qh[q * 36 + kc];
                bh2[1] = Qh[q * 36 + kc + 4];
                bl2[0] = Ql[q * 36 + kc];
                bl2[1] = Ql[q * 36 + kc + 4];
                mma3_tf(acc[nt], ah, al, bh2, bl2);
            }
        }
        __syncthreads();
    }
    float* base = sc + ((long)bh * SD + qt * 64) * SD + kt * 64;
    int m0 = wid * 16 + g;
    #pragma unroll
    for (int nt = 0; nt < 8; ++nt) {
        int q0 = nt * 8 + 2 * t;
        base[(long)q0 * SD + m0]           = acc[nt][0] * 0.125f;
        base[(long)(q0 + 1) * SD + m0]     = acc[nt][1] * 0.125f;
        base[(long)q0 * SD + m0 + 8]       = acc[nt][2] * 0.125f;
        base[(long)(q0 + 1) * SD + m0 + 8] = acc[nt][3] * 0.125f;
    }
}

// ---------------- causal softmax -------------------------------------------
__global__ void __launch_bounds__(128) k_softmax(float* __restrict__ sc) {
    int row = blockIdx.x;
    int q = row & (SD - 1);
    float* p = sc + (long)row * SD;
    int tid = threadIdx.x;
    float v[8];
    float m = -INFINITY;
    #pragma unroll
    for (int t = 0; t < 8; ++t) {
        int c = tid + t * 128;
        v[t] = (c <= q) ? p[c] : -INFINITY;
        m = fmaxf(m, v[t]);
    }
    __shared__ float redm[4], reds[4];
    #pragma unroll
    for (int off = 16; off; off >>= 1) m = fmaxf(m, __shfl_xor_sync(0xffffffffu, m, off));
    if ((tid & 31) == 0) redm[tid >> 5] = m;
    __syncthreads();
    m = fmaxf(fmaxf(redm[0], redm[1]), fmaxf(redm[2], redm[3]));
    float s = 0.f;
    #pragma unroll
    for (int t = 0; t < 8; ++t) { v[t] = expf(v[t] - m); s += v[t]; }
    #pragma unroll
    for (int off = 16; off; off >>= 1) s += __shfl_xor_sync(0xffffffffu, s, off);
    if ((tid & 31) == 0) reds[tid >> 5] = s;
    __syncthreads();
    s = reds[0] + reds[1] + reds[2] + reds[3];
    float inv = 1.f / s;
    #pragma unroll
    for (int t = 0; t < 8; ++t) p[tid + t * 128] = v[t] * inv;
}

// ---------------- O = P @ V via 3xTF32 mma -> bf16 hi/lo output -------------
__global__ void __launch_bounds__(128) k_av_tc(const float* __restrict__ sc,
                                               const float* __restrict__ qkv,
                                               __nv_bfloat16* __restrict__ ah_out,
                                               __nv_bfloat16* __restrict__ al_out) {
    int qt = blockIdx.x, bh = blockIdx.y;
    int b = bh >> 4, h = bh & 15;
    __shared__ unsigned Ph[64 * 36], Pl[64 * 36];
    __shared__ unsigned Vh[32 * 72], Vl[32 * 72];
    int tid = threadIdx.x, wid = tid >> 5, lane = tid & 31;
    int g = lane >> 2, t = lane & 3;
    float acc[8][4] = {};
    for (int kt = 0; kt <= qt; ++kt) {
        const float* pp = sc + ((long)bh * SD + qt * 64) * SD + kt * 64;
        const float* vb = qkv + (long)(b * SD + kt * 64) * 3 * DD + 2 * DD + h * HDIM;
        for (int c0 = 0; c0 < 64; c0 += 32) {
            #pragma unroll
            for (int it = 0; it < 4; ++it) {
                int idx = tid + it * 128;
                int prow = idx >> 3, pd4 = (idx & 7) * 4;
                float4 pv = *(const float4*)(pp + (long)prow * SD + c0 + pd4);
                unsigned h0, l0;
                split_tf(pv.x, h0, l0); Ph[prow*36+pd4+0]=h0; Pl[prow*36+pd4+0]=l0;
                split_tf(pv.y, h0, l0); Ph[prow*36+pd4+1]=h0; Pl[prow*36+pd4+1]=l0;
                split_tf(pv.z, h0, l0); Ph[prow*36+pd4+2]=h0; Pl[prow*36+pd4+2]=l0;
                split_tf(pv.w, h0, l0); Ph[prow*36+pd4+3]=h0; Pl[prow*36+pd4+3]=l0;
                int vrow = idx >> 4, vd4 = (idx & 15) * 4;
                float4 vv = *(const float4*)(vb + (long)(c0 + vrow) * 3 * DD + vd4);
                split_tf(vv.x, h0, l0); Vh[vrow*72+vd4+0]=h0; Vl[vrow*72+vd4+0]=l0;
                split_tf(vv.y, h0, l0); Vh[vrow*72+vd4+1]=h0; Vl[vrow*72+vd4+1]=l0;
                split_tf(vv.z, h0, l0); Vh[vrow*72+vd4+2]=h0; Vl[vrow*72+vd4+2]=l0;
                split_tf(vv.w, h0, l0); Vh[vrow*72+vd4+3]=h0; Vl[vrow*72+vd4+3]=l0;
            }
            __syncthreads();
            #pragma unroll
            for (int ks = 0; ks < 4; ++ks) {
                int kc = ks * 8 + t;
                unsigned ah[4], al[4];
                int mrow = wid * 16 + g;
                ah[0] = Ph[mrow * 36 + kc];
                ah[1] = Ph[(mrow + 8) * 36 + kc];
                ah[2] = Ph[mrow * 36 + kc + 4];
                ah[3] = Ph[(mrow + 8) * 36 + kc + 4];
                al[0] = Pl[mrow * 36 + kc];
                al[1] = Pl[(mrow + 8) * 36 + kc];
                al[2] = Pl[mrow * 36 + kc + 4];
                al[3] = Pl[(mrow + 8) * 36 + kc + 4];
                #pragma unroll
                for (int nt = 0; nt < 8; ++nt) {
                    int nc = nt * 8 + g;
                    unsigned bh2[2], bl2[2];
                    bh2[0] = Vh[kc * 72 + nc];
                    bh2[1] = Vh[(kc + 4) * 72 + nc];
                    bl2[0] = Vl[kc * 72 + nc];
                    bl2[1] = Vl[(kc + 4) * 72 + nc];
                    mma3_tf(acc[nt], ah, al, bh2, bl2);
                }
            }
            __syncthreads();
        }
    }
    long obase = (long)(b * SD + qt * 64) * DD + h * HDIM;
    int m0 = wid * 16 + g;
    #pragma unroll
    for (int nt = 0; nt < 8; ++nt) {
        int d0 = nt * 8 + 2 * t;
        #pragma unroll
        for (int e = 0; e < 4; ++e) {
            int mm = m0 + (e >> 1) * 8;
            int dd = d0 + (e & 1);
            __nv_bfloat16 hbf, lbf;
            split_bf(acc[nt][e], hbf, lbf);
            ah_out[obase + (long)mm * DD + dd] = hbf;
            al_out[obase + (long)mm * DD + dd] = lbf;
        }
    }
}

// ---------------- SwiGLU elementwise -> bf16 hi/lo ---------------------------
__global__ void k_silu(const float* __restrict__ g, const float* __restrict__ u,
                       __nv_bfloat16* __restrict__ oh, __nv_bfloat16* __restrict__ ol,
                       long n) {
    long i = (long)blockIdx.x * 256 + threadIdx.x;
    if (i < n) {
        float s = g[i];
        float v = (s / (1.f + expf(-s))) * u[i];
        __nv_bfloat16 h, l;
        split_bf(v, h, l);
        oh[i] = h;
        ol[i] = l;
    }
}

// ---------------- head: logits for the 2 last-token rows --------------------
__global__ void __launch_bounds__(256) k_head(const __nv_bfloat16* __restrict__ hh,
                                              const __nv_bfloat16* __restrict__ hl,
                                              const float* __restrict__ W,
                                              const float* __restrict__ bias,
                                              float* __restrict__ out) {
    int bidx = blockIdx.y;
    int col = blockIdx.x * 256 + threadIdx.x;
    __shared__ float sx[DD];
    long roff = (long)(bidx * SD + SD - 1) * DD;
    for (int c = threadIdx.x; c < DD; c += 256)
        sx[c] = __bfloat162float(hh[roff + c]) + __bfloat162float(hl[roff + c]);
    __syncthreads();
    if (col >= VV) return;
    float acc = 0.f;
    #pragma unroll 8
    for (int k = 0; k < DD; ++k) acc += sx[k] * W[(long)k * VV + col];
    out[(long)bidx * VV + col] = acc + bias[col];
}

// ---------------- driver -----------------------------------------------------
extern "C" void kernel_launch(void* const* d_in, const int* in_sizes, int n_in,
                              void* d_out, int out_size) {
    const int*   tokens = (const int*)  d_in[0];
    const float* embed  = (const float*)d_in[1];
    const float* Wqkv   = (const float*)d_in[2];
    const float* bqkv   = (const float*)d_in[3];
    const float* Wout   = (const float*)d_in[4];
    const float* bout   = (const float*)d_in[5];
    const float* ln1    = (const float*)d_in[6];
    const float* ln2    = (const float*)d_in[7];
    const float* Wg     = (const float*)d_in[8];
    const float* bg     = (const float*)d_in[9];
    const float* Wu     = (const float*)d_in[10];
    const float* bu     = (const float*)d_in[11];
    const float* Wd     = (const float*)d_in[12];
    const float* bd     = (const float*)d_in[13];
    const float* lnf    = (const float*)d_in[14];
    const float* Whead  = (const float*)d_in[15];
    const float* bhead  = (const float*)d_in[16];
    float* out = (float*)d_out;

    float *x, *qkv, *sc, *gate, *up;
    __nv_bfloat16 *hh, *hl, *ath, *atl, *gth, *gtl;
    __nv_bfloat16 *wqkvh, *wqkvl, *wouth, *woutl, *wgh, *wgl, *wuh, *wul, *wdh, *wdl;
    cudaGetSymbolAddress((void**)&x,    g_x);
    cudaGetSymbolAddress((void**)&qkv,  g_qkv);
    cudaGetSymbolAddress((void**)&sc,   g_scores);
    cudaGetSymbolAddress((void**)&gate, g_gate);
    cudaGetSymbolAddress((void**)&up,   g_up);
    cudaGetSymbolAddress((void**)&hh,   g_h_h);
    cudaGetSymbolAddress((void**)&hl,   g_h_l);
    cudaGetSymbolAddress((void**)&ath,  g_attn_h);
    cudaGetSymbolAddress((void**)&atl,  g_attn_l);
    cudaGetSymbolAddress((void**)&gth,  g_gate_h);
    cudaGetSymbolAddress((void**)&gtl,  g_gate_l);
    cudaGetSymbolAddress((void**)&wqkvh, g_wqkvT_h);
    cudaGetSymbolAddress((void**)&wqkvl, g_wqkvT_l);
    cudaGetSymbolAddress((void**)&wouth, g_woutT_h);
    cudaGetSymbolAddress((void**)&woutl, g_woutT_l);
    cudaGetSymbolAddress((void**)&wgh,  g_wgT_h);
    cudaGetSymbolAddress((void**)&wgl,  g_wgT_l);
    cudaGetSymbolAddress((void**)&wuh,  g_wuT_h);
    cudaGetSymbolAddress((void**)&wul,  g_wuT_l);
    cudaGetSymbolAddress((void**)&wdh,  g_wdT_h);
    cudaGetSymbolAddress((void**)&wdl,  g_wdT_l);

    // ---- weight split/transpose (runs every launch; deterministic) ----
    dim3 tb(32, 8);
    for (int l = 0; l < LL; ++l) {
        k_wsplit<<<dim3(96, 32), tb>>>(Wqkv + (long)l * DD * 3 * DD,
                                       wqkvh + (long)l * 3 * DD * DD,
                                       wqkvl + (long)l * 3 * DD * DD, DD, 3 * DD);
        k_wsplit<<<dim3(32, 32), tb>>>(Wout + (long)l * DD * DD,
                                       wouth + (long)l * DD * DD,
                                       woutl + (long)l * DD * DD, DD, DD);
        k_wsplit<<<dim3(86, 32), tb>>>(Wg + (long)l * DD * MMF,
                                       wgh + (long)l * MMF * DD,
                                       wgl + (long)l * MMF * DD, DD, MMF);
        k_wsplit<<<dim3(86, 32), tb>>>(Wu + (long)l * DD * MMF,
                                       wuh + (long)l * MMF * DD,
                                       wul + (long)l * MMF * DD, DD, MMF);
        k_wsplit<<<dim3(32, 86), tb>>>(Wd + (long)l * MMF * DD,
                                       wdh + (long)l * DD * MMF,
                                       wdl + (long)l * DD * MMF, MMF, DD);
    }

    k_embed<<<NTOK * DD / 256, 256>>>(tokens, embed, x);

    for (int l = 0; l < LL; ++l) {
        k_rmsnorm<<<NTOK, 256>>>(x, ln1 + (long)l * DD, hh, hl);

        dim3 gq(24, 16);
        k_gemm_bf3<<<gq, 256>>>(hh, hl,
                                wqkvh + (long)l * 3 * DD * DD, wqkvl + (long)l * 3 * DD * DD,
                                bqkv + (long)l * 3 * DD, nullptr, qkv,
                                NTOK, DD, 3 * DD);

        k_rope<<<NTOK * 2 * HH * 32 / 256, 256>>>(qkv);

        dim3 gs(16, 16, BD * HH);
        k_score_tc<<<gs, 128>>>(qkv, sc);

        k_softmax<<<BD * HH * SD, 128>>>(sc);

        dim3 ga(16, BD * HH);
        k_av_tc<<<ga, 128>>>(sc, qkv, ath, atl);

        dim3 go(8, 16);
        k_gemm_bf3<<<go, 256>>>(ath, atl,
                                wouth + (long)l * DD * DD, woutl + (long)l * DD * DD,
                                bout + (long)l * DD, x, x,
                                NTOK, DD, DD);

        k_rmsnorm<<<NTOK, 256>>>(x, ln2 + (long)l * DD, hh, hl);

        dim3 gm(22, 16);
        k_gemm_bf3<<<gm, 256>>>(hh, hl,
                                wgh + (long)l * MMF * DD, wgl + (long)l * MMF * DD,
                                bg + (long)l * MMF, nullptr, gate,
                                NTOK, DD, MMF);
        k_gemm_bf3<<<gm, 256>>>(hh, hl,
                                wuh + (long)l * MMF * DD, wul + (long)l * MMF * DD,
                                bu + (long)l * MMF, nullptr, up,
                                NTOK, DD, MMF);

        long nel = (long)NTOK * MMF;
        k_silu<<<(int)((nel + 255) / 256), 256>>>(gate, up, gth, gtl, nel);

        dim3 gd(8, 16);
        k_gemm_bf3<<<gd, 256>>>(gth, gtl,
                                wdh + (long)l * DD * MMF, wdl + (long)l * DD * MMF,
                                bd + (long)l * DD, x, x,
                                NTOK, MMF, DD);
    }

    k_rmsnorm<<<NTOK, 256>>>(x, lnf, hh, hl);
    dim3 gh((VV + 255) / 256, BD);
    k_head<<<gh, 256>>>(hh, hl, Whead, bhead, out);
}

// round 5
// speedup vs baseline: 2.0634x; 1.1166x over previous
#include <cuda_runtime.h>
#include <cuda_bf16.h>
#include <math.h>

#define BD   2
#define SD   1024
#define DD   1024
#define HH   16
#define HDIM 64
#define LL   4
#define MMF  2730
#define VV   32000
#define NTOK (BD*SD)
#define BH   (BD*HH)

// ---------------- scratch (device globals; no allocation allowed) ----------
__device__ float g_x[NTOK*DD];
__device__ float g_qkv[NTOK*3*DD];
__device__ float g_gate[NTOK*MMF];
__device__ float g_up[NTOK*MMF];

// activation hi/lo (bf16 split), k-major
__device__ __nv_bfloat16 g_h_h[NTOK*DD],    g_h_l[NTOK*DD];
__device__ __nv_bfloat16 g_attn_h[NTOK*DD], g_attn_l[NTOK*DD];
__device__ __nv_bfloat16 g_gate_h[NTOK*MMF], g_gate_l[NTOK*MMF];

// attention operands, [bh][tok][64] (q,k) and [bh][d][tok] (v transposed)
__device__ __nv_bfloat16 g_q_h[BH*SD*HDIM], g_q_l[BH*SD*HDIM];
__device__ __nv_bfloat16 g_k_h[BH*SD*HDIM], g_k_l[BH*SD*HDIM];
__device__ __nv_bfloat16 g_vt_h[BH*SD*HDIM], g_vt_l[BH*SD*HDIM];

// transposed weights hi/lo (bf16), layout [out_col][k] (k-major)
__device__ __nv_bfloat16 g_wqkvT_h[LL*3*DD*DD], g_wqkvT_l[LL*3*DD*DD];
__device__ __nv_bfloat16 g_woutT_h[LL*DD*DD],   g_woutT_l[LL*DD*DD];
__device__ __nv_bfloat16 g_wgT_h[LL*MMF*DD],    g_wgT_l[LL*MMF*DD];
__device__ __nv_bfloat16 g_wuT_h[LL*MMF*DD],    g_wuT_l[LL*MMF*DD];
__device__ __nv_bfloat16 g_wdT_h[LL*DD*MMF],    g_wdT_l[LL*DD*MMF];

// ---------------- helpers ----------------------------------------------------
__device__ __forceinline__ void split_bf(float f, __nv_bfloat16& h, __nv_bfloat16& l) {
    h = __float2bfloat16(f);
    l = __float2bfloat16(f - __bfloat162float(h));
}
// pack two floats into bf16x2 hi word + bf16x2 lo (residual) word
__device__ __forceinline__ void pack_split2(float a, float b, unsigned& hi, unsigned& lo) {
    __nv_bfloat162 th, tl;
    th.x = __float2bfloat16(a);
    th.y = __float2bfloat16(b);
    tl.x = __float2bfloat16(a - __bfloat162float(th.x));
    tl.y = __float2bfloat16(b - __bfloat162float(th.y));
    hi = *(unsigned*)&th;
    lo = *(unsigned*)&tl;
}

__device__ __forceinline__ void mma_bf16(float* d, const unsigned* a,
                                         const unsigned* b, const float* c) {
    asm volatile(
        "mma.sync.aligned.m16n8k16.row.col.f32.bf16.bf16.f32 "
        "{%0,%1,%2,%3}, {%4,%5,%6,%7}, {%8,%9}, {%10,%11,%12,%13};"
        : "=f"(d[0]), "=f"(d[1]), "=f"(d[2]), "=f"(d[3])
        : "r"(a[0]), "r"(a[1]), "r"(a[2]), "r"(a[3]),
          "r"(b[0]), "r"(b[1]),
          "f"(c[0]), "f"(c[1]), "f"(c[2]), "f"(c[3]));
}

// ---------------- weight transpose + bf16 split -----------------------------
__global__ void k_wsplit(const float* __restrict__ W,
                         __nv_bfloat16* __restrict__ Th,
                         __nv_bfloat16* __restrict__ Tl, int K, int M) {
    __shared__ float t[32][33];
    int m0 = blockIdx.x * 32, k0 = blockIdx.y * 32;
    int tx = threadIdx.x, ty = threadIdx.y;
    #pragma unroll
    for (int i = 0; i < 32; i += 8) {
        int k = k0 + ty + i, m = m0 + tx;
        t[ty + i][tx] = (k < K && m < M) ? W[(long)k * M + m] : 0.f;
    }
    __syncthreads();
    #pragma unroll
    for (int i = 0; i < 32; i += 8) {
        int m = m0 + ty + i, k = k0 + tx;
        if (m < M && k < K) {
            __nv_bfloat16 h, l;
            split_bf(t[tx][ty + i], h, l);
            Th[(long)m * K + k] = h;
            Tl[(long)m * K + k] = l;
        }
    }
}

// ---------------- embedding gather ----------------------------------------
__global__ void k_embed(const int* __restrict__ tok, const float* __restrict__ emb,
                        float* __restrict__ x) {
    int i = blockIdx.x * 256 + threadIdx.x;
    int n = i >> 10, d = i & 1023;
    x[i] = emb[(long)tok[n] * DD + d];
}

// ---------------- rmsnorm -> bf16 hi/lo -------------------------------------
__global__ void __launch_bounds__(256) k_rmsnorm(const float* __restrict__ x,
                                                 const float* __restrict__ w,
                                                 __nv_bfloat16* __restrict__ oh,
                                                 __nv_bfloat16* __restrict__ ol) {
    int row = blockIdx.x;
    const float* xr = x + (long)row * DD;
    float s = 0.f;
    for (int c = threadIdx.x; c < DD; c += 256) { float v = xr[c]; s += v * v; }
    __shared__ float red[8];
    #pragma unroll
    for (int off = 16; off; off >>= 1) s += __shfl_xor_sync(0xffffffffu, s, off);
    if ((threadIdx.x & 31) == 0) red[threadIdx.x >> 5] = s;
    __syncthreads();
    if (threadIdx.x == 0) {
        float t = 0.f;
        #pragma unroll
        for (int i = 0; i < 8; ++i) t += red[i];
        red[0] = t;
    }
    __syncthreads();
    float r = rsqrtf(red[0] * (1.0f / DD) + 1e-6f);
    for (int c = threadIdx.x; c < DD; c += 256) {
        float v = xr[c] * r * w[c];
        __nv_bfloat16 h, l;
        split_bf(v, h, l);
        oh[(long)row * DD + c] = h;
        ol[(long)row * DD + c] = l;
    }
}

// ---------------- bf16 split-3 tensor-core GEMM -----------------------------
#define XS 20
__global__ void __launch_bounds__(256, 2) k_gemm_bf3(
        const __nv_bfloat16* __restrict__ Ah_, const __nv_bfloat16* __restrict__ Al_,
        const __nv_bfloat16* __restrict__ Bh_, const __nv_bfloat16* __restrict__ Bl_,
        const float* __restrict__ bias, const float* __restrict__ add,
        float* __restrict__ C, int N, int K, int M) {
    __shared__ unsigned Ash[128 * XS], Asl[128 * XS];
    __shared__ unsigned Bsh[128 * XS], Bsl[128 * XS];
    const unsigned* Ahw = (const unsigned*)Ah_;
    const unsigned* Alw = (const unsigned*)Al_;
    const unsigned* Bhw = (const unsigned*)Bh_;
    const unsigned* Blw = (const unsigned*)Bl_;
    int tid = threadIdx.x, wid = tid >> 5, lane = tid & 31;
    int g = lane >> 2, t = lane & 3;
    int wm = (wid & 1) * 64, wn = (wid >> 1) * 32;
    int br = blockIdx.y * 128, bc = blockIdx.x * 128;
    int Kw = K >> 1;
    float acc[4][4][4] = {};

    for (int k0 = 0; k0 < K; k0 += 32) {
        int kw0 = k0 >> 1;
        #pragma unroll
        for (int it = 0; it < 8; ++it) {
            int idx = tid + it * 256;
            int row = idx >> 4, w = idx & 15;
            bool kv = (k0 + 2 * w) < K;
            long aoff = (long)(br + row) * Kw + kw0 + w;
            Ash[row * XS + w] = kv ? Ahw[aoff] : 0u;
            Asl[row * XS + w] = kv ? Alw[aoff] : 0u;
            int brow = bc + row;
            bool bv = kv && (brow < M);
            long boff = (long)brow * Kw + kw0 + w;
            Bsh[row * XS + w] = bv ? Bhw[boff] : 0u;
            Bsl[row * XS + w] = bv ? Blw[boff] : 0u;
        }
        __syncthreads();
        #pragma unroll
        for (int ks = 0; ks < 2; ++ks) {
            int kpb = ks * 8;
            unsigned ah[4][4], al[4][4], bh[4][2], bl[4][2];
            #pragma unroll
            for (int mt = 0; mt < 4; ++mt) {
                int mrow = wm + mt * 16 + g;
                ah[mt][0] = Ash[mrow * XS + kpb + t];
                ah[mt][1] = Ash[(mrow + 8) * XS + kpb + t];
                ah[mt][2] = Ash[mrow * XS + kpb + t + 4];
                ah[mt][3] = Ash[(mrow + 8) * XS + kpb + t + 4];
                al[mt][0] = Asl[mrow * XS + kpb + t];
                al[mt][1] = Asl[(mrow + 8) * XS + kpb + t];
                al[mt][2] = Asl[mrow * XS + kpb + t + 4];
                al[mt][3] = Asl[(mrow + 8) * XS + kpb + t + 4];
            }
            #pragma unroll
            for (int nt = 0; nt < 4; ++nt) {
                int nrow = wn + nt * 8 + g;
                bh[nt][0] = Bsh[nrow * XS + kpb + t];
                bh[nt][1] = Bsh[nrow * XS + kpb + t + 4];
                bl[nt][0] = Bsl[nrow * XS + kpb + t];
                bl[nt][1] = Bsl[nrow * XS + kpb + t + 4];
            }
            #pragma unroll
            for (int mt = 0; mt < 4; ++mt)
                #pragma unroll
                for (int nt = 0; nt < 4; ++nt) {
                    mma_bf16(acc[mt][nt], ah[mt], bh[nt], acc[mt][nt]);
                    mma_bf16(acc[mt][nt], ah[mt], bl[nt], acc[mt][nt]);
                    mma_bf16(acc[mt][nt], al[mt], bh[nt], acc[mt][nt]);
                }
        }
        __syncthreads();
    }

    #pragma unroll
    for (int mt = 0; mt < 4; ++mt) {
        int r0 = br + wm + mt * 16 + g;
        #pragma unroll
        for (int nt = 0; nt < 4; ++nt) {
            int c0 = bc + wn + nt * 8 + 2 * t;
            const float* a4 = acc[mt][nt];
            if (c0 < M) {
                float bv = bias ? bias[c0] : 0.f;
                float v0 = a4[0] + bv;
                float v2 = a4[2] + bv;
                if (add) { v0 += add[(long)r0 * M + c0]; v2 += add[(long)(r0 + 8) * M + c0]; }
                C[(long)r0 * M + c0] = v0;
                C[(long)(r0 + 8) * M + c0] = v2;
            }
            if (c0 + 1 < M) {
                float bv = bias ? bias[c0 + 1] : 0.f;
                float v1 = a4[1] + bv;
                float v3 = a4[3] + bv;
                if (add) { v1 += add[(long)r0 * M + c0 + 1]; v3 += add[(long)(r0 + 8) * M + c0 + 1]; }
                C[(long)r0 * M + c0 + 1] = v1;
                C[(long)(r0 + 8) * M + c0 + 1] = v3;
            }
        }
    }
}

// ---------------- q/k: rope + bf16 split into [bh][tok][64] -----------------
__global__ void k_qk_prep(const float* __restrict__ qkv,
                          __nv_bfloat16* __restrict__ qh, __nv_bfloat16* __restrict__ ql,
                          __nv_bfloat16* __restrict__ kh, __nv_bfloat16* __restrict__ kl) {
    int idx = blockIdx.x * 256 + threadIdx.x;   // NTOK*HH*32 threads
    int j = idx & 31;
    int h = (idx >> 5) & 15;
    int tok = idx >> 9;
    int s = tok & (SD - 1), b = tok >> 10;
    float freq = powf(10000.f, -(float)j / 32.f);
    float ang = (float)s * freq;
    float sn, cs;
    sincosf(ang, &sn, &cs);
    const float* base = qkv + (long)tok * 3 * DD + h * HDIM + 2 * j;
    float qe = base[0], qo = base[1];
    float ke = base[DD], ko = base[DD + 1];
    float q0 = qe * cs - qo * sn, q1 = qe * sn + qo * cs;
    float k0 = ke * cs - ko * sn, k1 = ke * sn + ko * cs;
    long off = ((long)(b * HH + h) * SD + s) * 32 + j;   // bf16x2 units
    unsigned hi, lo;
    pack_split2(q0, q1, hi, lo);
    ((unsigned*)qh)[off] = hi;
    ((unsigned*)ql)[off] = lo;
    pack_split2(k0, k1, hi, lo);
    ((unsigned*)kh)[off] = hi;
    ((unsigned*)kl)[off] = lo;
}

// ---------------- v: transpose + bf16 split into [bh][d][tok] ---------------
__global__ void k_v_prep(const float* __restrict__ qkv,
                         __nv_bfloat16* __restrict__ vh, __nv_bfloat16* __restrict__ vl) {
    __shared__ float ts[32][33];
    int bh = blockIdx.z, b = bh >> 4, h = bh & 15;
    int t0 = blockIdx.x * 32, d0 = blockIdx.y * 32;
    int tx = threadIdx.x, ty = threadIdx.y;
    #pragma unroll
    for (int i = 0; i < 32; i += 8) {
        int tok = t0 + ty + i;
        ts[ty + i][tx] = qkv[((long)(b * SD + tok)) * 3 * DD + 2 * DD + h * HDIM + d0 + tx];
    }
    __syncthreads();
    #pragma unroll
    for (int i = 0; i < 32; i += 8) {
        int d = d0 + ty + i, tok = t0 + tx;
        __nv_bfloat16 hh, ll;
        split_bf(ts[tx][ty + i], hh, ll);
        long off = ((long)bh * HDIM + d) * SD + tok;
        vh[off] = hh;
        vl[off] = ll;
    }
}

// ---------------- flash attention: 64 q-rows per block, bf16 split-3 --------
__global__ void __launch_bounds__(128) k_flash(
        const __nv_bfloat16* __restrict__ qh_, const __nv_bfloat16* __restrict__ ql_,
        const __nv_bfloat16* __restrict__ kh_, const __nv_bfloat16* __restrict__ kl_,
        const __nv_bfloat16* __restrict__ vh_, const __nv_bfloat16* __restrict__ vl_,
        __nv_bfloat16* __restrict__ oh_, __nv_bfloat16* __restrict__ ol_) {
    int qt = (int)gridDim.x - 1 - blockIdx.x;   // heavy blocks first
    int bh = blockIdx.y;
    __shared__ unsigned Ksh[64 * 36], Ksl[64 * 36];
    __shared__ unsigned Vsh[64 * 36], Vsl[64 * 36];
    int tid = threadIdx.x, wid = tid >> 5, lane = tid & 31;
    int g = lane >> 2, t = lane & 3;
    const unsigned* qhw = (const unsigned*)qh_;
    const unsigned* qlw = (const unsigned*)ql_;
    const unsigned* khw = (const unsigned*)kh_;
    const unsigned* klw = (const unsigned*)kl_;
    const unsigned* vhw = (const unsigned*)vh_;
    const unsigned* vlw = (const unsigned*)vl_;

    // stage Q through smem, lift to register fragments
    long qbase = ((long)bh * SD + qt * 64) * 32;
    #pragma unroll
    for (int it = 0; it < 16; ++it) {
        int idx = tid + it * 128;
        int row = idx >> 5, col = idx & 31;
        Ksh[row * 36 + col] = qhw[qbase + row * 32 + col];
        Ksl[row * 36 + col] = qlw[qbase + row * 32 + col];
    }
    __syncthreads();
    int r0 = wid * 16 + g;
    unsigned qfh[4][4], qfl[4][4];
    #pragma unroll
    for (int kk = 0; kk < 4; ++kk) {
        qfh[kk][0] = Ksh[r0 * 36 + kk * 8 + t];
        qfh[kk][1] = Ksh[(r0 + 8) * 36 + kk * 8 + t];
        qfh[kk][2] = Ksh[r0 * 36 + kk * 8 + t + 4];
        qfh[kk][3] = Ksh[(r0 + 8) * 36 + kk * 8 + t + 4];
        qfl[kk][0] = Ksl[r0 * 36 + kk * 8 + t];
        qfl[kk][1] = Ksl[(r0 + 8) * 36 + kk * 8 + t];
        qfl[kk][2] = Ksl[r0 * 36 + kk * 8 + t + 4];
        qfl[kk][3] = Ksl[(r0 + 8) * 36 + kk * 8 + t + 4];
    }
    __syncthreads();

    float m0 = -INFINITY, m1 = -INFINITY, l0 = 0.f, l1 = 0.f;
    float od[8][4] = {};

    for (int kt = 0; kt <= qt; ++kt) {
        long kb = ((long)bh * SD + kt * 64) * 32;
        long vb = (long)bh * HDIM * (SD / 2) + kt * 32;
        #pragma unroll
        for (int it = 0; it < 16; ++it) {
            int idx = tid + it * 128;
            int row = idx >> 5, col = idx & 31;
            Ksh[row * 36 + col] = khw[kb + row * 32 + col];
            Ksl[row * 36 + col] = klw[kb + row * 32 + col];
            Vsh[row * 36 + col] = vhw[vb + (long)row * (SD / 2) + col];
            Vsl[row * 36 + col] = vlw[vb + (long)row * (SD / 2) + col];
        }
        __syncthreads();

        // S = Q K^T (split-3)
        float sacc[8][4] = {};
        #pragma unroll
        for (int kk = 0; kk < 4; ++kk) {
            #pragma unroll
            for (int nt = 0; nt < 8; ++nt) {
                int n = nt * 8 + g;
                unsigned kbh[2], kbl[2];
                kbh[0] = Ksh[n * 36 + kk * 8 + t];
                kbh[1] = Ksh[n * 36 + kk * 8 + t + 4];
                kbl[0] = Ksl[n * 36 + kk * 8 + t];
                kbl[1] = Ksl[n * 36 + kk * 8 + t + 4];
                mma_bf16(sacc[nt], qfh[kk], kbh, sacc[nt]);
                mma_bf16(sacc[nt], qfh[kk], kbl, sacc[nt]);
                mma_bf16(sacc[nt], qfl[kk], kbh, sacc[nt]);
            }
        }
        // scale + causal mask (diagonal tile only)
        #pragma unroll
        for (int nt = 0; nt < 8; ++nt) {
            #pragma unroll
            for (int e = 0; e < 4; ++e) sacc[nt][e] *= 0.125f;
        }
        if (kt == qt) {
            #pragma unroll
            for (int nt = 0; nt < 8; ++nt) {
                int c = nt * 8 + 2 * t;
                if (c > r0)         sacc[nt][0] = -1e30f;
                if (c + 1 > r0)     sacc[nt][1] = -1e30f;
                if (c > r0 + 8)     sacc[nt][2] = -1e30f;
                if (c + 1 > r0 + 8) sacc[nt][3] = -1e30f;
            }
        }
        // online softmax
        float tm0 = -1e30f, tm1 = -1e30f;
        #pragma unroll
        for (int nt = 0; nt < 8; ++nt) {
            tm0 = fmaxf(tm0, fmaxf(sacc[nt][0], sacc[nt][1]));
            tm1 = fmaxf(tm1, fmaxf(sacc[nt][2], sacc[nt][3]));
        }
        tm0 = fmaxf(tm0, __shfl_xor_sync(0xffffffffu, tm0, 1));
        tm0 = fmaxf(tm0, __shfl_xor_sync(0xffffffffu, tm0, 2));
        tm1 = fmaxf(tm1, __shfl_xor_sync(0xffffffffu, tm1, 1));
        tm1 = fmaxf(tm1, __shfl_xor_sync(0xffffffffu, tm1, 2));
        float mn0 = fmaxf(m0, tm0), mn1 = fmaxf(m1, tm1);
        float sc0 = __expf(m0 - mn0), sc1 = __expf(m1 - mn1);
        m0 = mn0; m1 = mn1;
        l0 *= sc0; l1 *= sc1;
        #pragma unroll
        for (int nt = 0; nt < 8; ++nt) {
            od[nt][0] *= sc0; od[nt][1] *= sc0;
            od[nt][2] *= sc1; od[nt][3] *= sc1;
        }
        #pragma unroll
        for (int nt = 0; nt < 8; ++nt) {
            sacc[nt][0] = __expf(sacc[nt][0] - m0);
            sacc[nt][1] = __expf(sacc[nt][1] - m0);
            sacc[nt][2] = __expf(sacc[nt][2] - m1);
            sacc[nt][3] = __expf(sacc[nt][3] - m1);
            l0 += sacc[nt][0] + sacc[nt][1];
            l1 += sacc[nt][2] + sacc[nt][3];
        }
        // pack P into A-operand fragments (register-only)
        unsigned pah[4][4], pal[4][4];
        #pragma unroll
        for (int kk = 0; kk < 4; ++kk) {
            pack_split2(sacc[2*kk][0],   sacc[2*kk][1],   pah[kk][0], pal[kk][0]);
            pack_split2(sacc[2*kk][2],   sacc[2*kk][3],   pah[kk][1], pal[kk][1]);
            pack_split2(sacc[2*kk+1][0], sacc[2*kk+1][1], pah[kk][2], pal[kk][2]);
            pack_split2(sacc[2*kk+1][2], sacc[2*kk+1][3], pah[kk][3], pal[kk][3]);
        }
        // O += P V (split-3)
        #pragma unroll
        for (int kk = 0; kk < 4; ++kk) {
            #pragma unroll
            for (int nt = 0; nt < 8; ++nt) {
                int n = nt * 8 + g;
                unsigned vbh[2], vbl[2];
                vbh[0] = Vsh[n * 36 + kk * 8 + t];
                vbh[1] = Vsh[n * 36 + kk * 8 + t + 4];
                vbl[0] = Vsl[n * 36 + kk * 8 + t];
                vbl[1] = Vsl[n * 36 + kk * 8 + t + 4];
                mma_bf16(od[nt], pah[kk], vbh, od[nt]);
                mma_bf16(od[nt], pah[kk], vbl, od[nt]);
                mma_bf16(od[nt], pal[kk], vbh, od[nt]);
            }
        }
        __syncthreads();
    }

    // finalize
    l0 += __shfl_xor_sync(0xffffffffu, l0, 1);
    l0 += __shfl_xor_sync(0xffffffffu, l0, 2);
    l1 += __shfl_xor_sync(0xffffffffu, l1, 1);
    l1 += __shfl_xor_sync(0xffffffffu, l1, 2);
    float i0 = 1.f / l0, i1 = 1.f / l1;
    int b = bh >> 4, h = bh & 15;
    long ob0 = ((long)(b * SD + qt * 64 + r0)) * DD + h * HDIM;
    long ob1 = ob0 + 8L * DD;
    #pragma unroll
    for (int nt = 0; nt < 8; ++nt) {
        int d = nt * 8 + 2 * t;
        __nv_bfloat16 hh, ll;
        split_bf(od[nt][0] * i0, hh, ll); oh_[ob0 + d] = hh;     ol_[ob0 + d] = ll;
        split_bf(od[nt][1] * i0, hh, ll); oh_[ob0 + d + 1] = hh; ol_[ob0 + d + 1] = ll;
        split_bf(od[nt][2] * i1, hh, ll); oh_[ob1 + d] = hh;     ol_[ob1 + d] = ll;
        split_bf(od[nt][3] * i1, hh, ll); oh_[ob1 + d + 1] = hh; ol_[ob1 + d + 1] = ll;
    }
}

// ---------------- SwiGLU elementwise -> bf16 hi/lo ---------------------------
__global__ void k_silu(const float* __restrict__ g, const float* __restrict__ u,
                       __nv_bfloat16* __restrict__ oh, __nv_bfloat16* __restrict__ ol,
                       long n) {
    long i = (long)blockIdx.x * 256 + threadIdx.x;
    if (i < n) {
        float s = g[i];
        float v = (s / (1.f + expf(-s))) * u[i];
        __nv_bfloat16 h, l;
        split_bf(v, h, l);
        oh[i] = h;
        ol[i] = l;
    }
}

// ---------------- head: logits for the 2 last-token rows --------------------
__global__ void __launch_bounds__(256) k_head(const __nv_bfloat16* __restrict__ hh,
                                              const __nv_bfloat16* __restrict__ hl,
                                              const float* __restrict__ W,
                                              const float* __restrict__ bias,
                                              float* __restrict__ out) {
    int bidx = blockIdx.y;
    int col = blockIdx.x * 256 + threadIdx.x;
    __shared__ float sx[DD];
    long roff = (long)(bidx * SD + SD - 1) * DD;
    for (int c = threadIdx.x; c < DD; c += 256)
        sx[c] = __bfloat162float(hh[roff + c]) + __bfloat162float(hl[roff + c]);
    __syncthreads();
    if (col >= VV) return;
    float acc = 0.f;
    #pragma unroll 8
    for (int k = 0; k < DD; ++k) acc += sx[k] * W[(long)k * VV + col];
    out[(long)bidx * VV + col] = acc + bias[col];
}

// ---------------- driver -----------------------------------------------------
extern "C" void kernel_launch(void* const* d_in, const int* in_sizes, int n_in,
                              void* d_out, int out_size) {
    const int*   tokens = (const int*)  d_in[0];
    const float* embed  = (const float*)d_in[1];
    const float* Wqkv   = (const float*)d_in[2];
    const float* bqkv   = (const float*)d_in[3];
    const float* Wout   = (const float*)d_in[4];
    const float* bout   = (const float*)d_in[5];
    const float* ln1    = (const float*)d_in[6];
    const float* ln2    = (const float*)d_in[7];
    const float* Wg     = (const float*)d_in[8];
    const float* bg     = (const float*)d_in[9];
    const float* Wu     = (const float*)d_in[10];
    const float* bu     = (const float*)d_in[11];
    const float* Wd     = (const float*)d_in[12];
    const float* bd     = (const float*)d_in[13];
    const float* lnf    = (const float*)d_in[14];
    const float* Whead  = (const float*)d_in[15];
    const float* bhead  = (const float*)d_in[16];
    float* out = (float*)d_out;

    float *x, *qkv, *gate, *up;
    __nv_bfloat16 *hh, *hl, *ath, *atl, *gth, *gtl;
    __nv_bfloat16 *qh, *ql, *kh, *kl, *vth, *vtl;
    __nv_bfloat16 *wqkvh, *wqkvl, *wouth, *woutl, *wgh, *wgl, *wuh, *wul, *wdh, *wdl;
    cudaGetSymbolAddress((void**)&x,    g_x);
    cudaGetSymbolAddress((void**)&qkv,  g_qkv);
    cudaGetSymbolAddress((void**)&gate, g_gate);
    cudaGetSymbolAddress((void**)&up,   g_up);
    cudaGetSymbolAddress((void**)&hh,   g_h_h);
    cudaGetSymbolAddress((void**)&hl,   g_h_l);
    cudaGetSymbolAddress((void**)&ath,  g_attn_h);
    cudaGetSymbolAddress((void**)&atl,  g_attn_l);
    cudaGetSymbolAddress((void**)&gth,  g_gate_h);
    cudaGetSymbolAddress((void**)&gtl,  g_gate_l);
    cudaGetSymbolAddress((void**)&qh,   g_q_h);
    cudaGetSymbolAddress((void**)&ql,   g_q_l);
    cudaGetSymbolAddress((void**)&kh,   g_k_h);
    cudaGetSymbolAddress((void**)&kl,   g_k_l);
    cudaGetSymbolAddress((void**)&vth,  g_vt_h);
    cudaGetSymbolAddress((void**)&vtl,  g_vt_l);
    cudaGetSymbolAddress((void**)&wqkvh, g_wqkvT_h);
    cudaGetSymbolAddress((void**)&wqkvl, g_wqkvT_l);
    cudaGetSymbolAddress((void**)&wouth, g_woutT_h);
    cudaGetSymbolAddress((void**)&woutl, g_woutT_l);
    cudaGetSymbolAddress((void**)&wgh,  g_wgT_h);
    cudaGetSymbolAddress((void**)&wgl,  g_wgT_l);
    cudaGetSymbolAddress((void**)&wuh,  g_wuT_h);
    cudaGetSymbolAddress((void**)&wul,  g_wuT_l);
    cudaGetSymbolAddress((void**)&wdh,  g_wdT_h);
    cudaGetSymbolAddress((void**)&wdl,  g_wdT_l);

    // ---- weight split/transpose ----
    dim3 tb(32, 8);
    for (int l = 0; l < LL; ++l) {
        k_wsplit<<<dim3(96, 32), tb>>>(Wqkv + (long)l * DD * 3 * DD,
                                       wqkvh + (long)l * 3 * DD * DD,
                                       wqkvl + (long)l * 3 * DD * DD, DD, 3 * DD);
        k_wsplit<<<dim3(32, 32), tb>>>(Wout + (long)l * DD * DD,
                                       wouth + (long)l * DD * DD,
                                       woutl + (long)l * DD * DD, DD, DD);
        k_wsplit<<<dim3(86, 32), tb>>>(Wg + (long)l * DD * MMF,
                                       wgh + (long)l * MMF * DD,
                                       wgl + (long)l * MMF * DD, DD, MMF);
        k_wsplit<<<dim3(86, 32), tb>>>(Wu + (long)l * DD * MMF,
                                       wuh + (long)l * MMF * DD,
                                       wul + (long)l * MMF * DD, DD, MMF);
        k_wsplit<<<dim3(32, 86), tb>>>(Wd + (long)l * MMF * DD,
                                       wdh + (long)l * DD * MMF,
                                       wdl + (long)l * DD * MMF, MMF, DD);
    }

    k_embed<<<NTOK * DD / 256, 256>>>(tokens, embed, x);

    for (int l = 0; l < LL; ++l) {
        k_rmsnorm<<<NTOK, 256>>>(x, ln1 + (long)l * DD, hh, hl);

        dim3 gq(24, 16);
        k_gemm_bf3<<<gq, 256>>>(hh, hl,
                                wqkvh + (long)l * 3 * DD * DD, wqkvl + (long)l * 3 * DD * DD,
                                bqkv + (long)l * 3 * DD, nullptr, qkv,
                                NTOK, DD, 3 * DD);

        k_qk_prep<<<NTOK * HH * 32 / 256, 256>>>(qkv, qh, ql, kh, kl);
        k_v_prep<<<dim3(SD / 32, HDIM / 32, BH), dim3(32, 8)>>>(qkv, vth, vtl);

        k_flash<<<dim3(SD / 64, BH), 128>>>(qh, ql, kh, kl, vth, vtl, ath, atl);

        dim3 go(8, 16);
        k_gemm_bf3<<<go, 256>>>(ath, atl,
                                wouth + (long)l * DD * DD, woutl + (long)l * DD * DD,
                                bout + (long)l * DD, x, x,
                                NTOK, DD, DD);

        k_rmsnorm<<<NTOK, 256>>>(x, ln2 + (long)l * DD, hh, hl);

        dim3 gm(22, 16);
        k_gemm_bf3<<<gm, 256>>>(hh, hl,
                                wgh + (long)l * MMF * DD, wgl + (long)l * MMF * DD,
                                bg + (long)l * MMF, nullptr, gate,
                                NTOK, DD, MMF);
        k_gemm_bf3<<<gm, 256>>>(hh, hl,
                                wuh + (long)l * MMF * DD, wul + (long)l * MMF * DD,
                                bu + (long)l * MMF, nullptr, up,
                                NTOK, DD, MMF);

        long nel = (long)NTOK * MMF;
        k_silu<<<(int)((nel + 255) / 256), 256>>>(gate, up, gth, gtl, nel);

        dim3 gd(8, 16);
        k_gemm_bf3<<<gd, 256>>>(gth, gtl,
                                wdh + (long)l * DD * MMF, wdl + (long)l * DD * MMF,
                                bd + (long)l * DD, x, x,
                                NTOK, MMF, DD);
    }

    k_rmsnorm<<<NTOK, 256>>>(x, lnf, hh, hl);
    dim3 gh((VV + 255) / 256, BD);
    k_head<<<gh, 256>>>(hh, hl, Whead, bhead, out);
}

// round 6
// speedup vs baseline: 3.4973x; 1.6949x over previous
#include <cuda_runtime.h>
#include <cuda_bf16.h>
#include <math.h>

#define BD   2
#define SD   1024
#define DD   1024
#define HH   16
#define HDIM 64
#define LL   4
#define MMF  2730
#define MP   2752          // MMF padded to a multiple of 32 (16B-aligned rows)
#define VV   32000
#define NTOK (BD*SD)
#define BH   (BD*HH)

// ---------------- scratch (device globals; no allocation allowed) ----------
__device__ float g_x[NTOK*DD];
__device__ float g_qkv[NTOK*3*DD];
__device__ float g_gate[NTOK*MMF];
__device__ float g_up[NTOK*MMF];

__device__ __nv_bfloat16 g_h_h[NTOK*DD],    g_h_l[NTOK*DD];
__device__ __nv_bfloat16 g_attn_h[NTOK*DD], g_attn_l[NTOK*DD];
__device__ __nv_bfloat16 g_gate_h[NTOK*MP], g_gate_l[NTOK*MP];   // K-padded

__device__ __nv_bfloat16 g_q_h[BH*SD*HDIM], g_q_l[BH*SD*HDIM];
__device__ __nv_bfloat16 g_k_h[BH*SD*HDIM], g_k_l[BH*SD*HDIM];
__device__ __nv_bfloat16 g_vt_h[BH*SD*HDIM], g_vt_l[BH*SD*HDIM];

__device__ __nv_bfloat16 g_wqkvT_h[LL*3*DD*DD], g_wqkvT_l[LL*3*DD*DD];
__device__ __nv_bfloat16 g_woutT_h[LL*DD*DD],   g_woutT_l[LL*DD*DD];
__device__ __nv_bfloat16 g_wgT_h[LL*MMF*DD],    g_wgT_l[LL*MMF*DD];
__device__ __nv_bfloat16 g_wuT_h[LL*MMF*DD],    g_wuT_l[LL*MMF*DD];
__device__ __nv_bfloat16 g_wdT_h[(long)LL*DD*MP], g_wdT_l[(long)LL*DD*MP]; // K-padded

// ---------------- helpers ----------------------------------------------------
__device__ __forceinline__ void split_bf(float f, __nv_bfloat16& h, __nv_bfloat16& l) {
    h = __float2bfloat16(f);
    l = __float2bfloat16(f - __bfloat162float(h));
}
__device__ __forceinline__ void pack_split2(float a, float b, unsigned& hi, unsigned& lo) {
    __nv_bfloat162 th, tl;
    th.x = __float2bfloat16(a);
    th.y = __float2bfloat16(b);
    tl.x = __float2bfloat16(a - __bfloat162float(th.x));
    tl.y = __float2bfloat16(b - __bfloat162float(th.y));
    hi = *(unsigned*)&th;
    lo = *(unsigned*)&tl;
}
__device__ __forceinline__ void mma_bf16(float* d, const unsigned* a,
                                         const unsigned* b, const float* c) {
    asm volatile(
        "mma.sync.aligned.m16n8k16.row.col.f32.bf16.bf16.f32 "
        "{%0,%1,%2,%3}, {%4,%5,%6,%7}, {%8,%9}, {%10,%11,%12,%13};"
        : "=f"(d[0]), "=f"(d[1]), "=f"(d[2]), "=f"(d[3])
        : "r"(a[0]), "r"(a[1]), "r"(a[2]), "r"(a[3]),
          "r"(b[0]), "r"(b[1]),
          "f"(c[0]), "f"(c[1]), "f"(c[2]), "f"(c[3]));
}
__device__ __forceinline__ void cp16(unsigned saddr, const void* g) {
    asm volatile("cp.async.cg.shared.global [%0], [%1], 16;" :: "r"(saddr), "l"(g));
}
__device__ __forceinline__ void cp_commit() {
    asm volatile("cp.async.commit_group;");
}
template<int N> __device__ __forceinline__ void cp_wait() {
    asm volatile("cp.async.wait_group %0;" :: "n"(N));
}

// ---------------- weight transpose + bf16 split (batched over layers) -------
// W: K x M fp32 -> Th/Tl: M x KP bf16 (k-major rows, zero-padded to KP)
__global__ void k_wsplit(const float* __restrict__ W,
                         __nv_bfloat16* __restrict__ Th,
                         __nv_bfloat16* __restrict__ Tl,
                         int K, int M, int KP, long wstride, long tstride) {
    W  += (long)blockIdx.z * wstride;
    Th += (long)blockIdx.z * tstride;
    Tl += (long)blockIdx.z * tstride;
    __shared__ float t[32][33];
    int m0 = blockIdx.x * 32, k0 = blockIdx.y * 32;
    int tx = threadIdx.x, ty = threadIdx.y;
    #pragma unroll
    for (int i = 0; i < 32; i += 8) {
        int k = k0 + ty + i, m = m0 + tx;
        t[ty + i][tx] = (k < K && m < M) ? W[(long)k * M + m] : 0.f;
    }
    __syncthreads();
    #pragma unroll
    for (int i = 0; i < 32; i += 8) {
        int m = m0 + ty + i, k = k0 + tx;
        if (m < M && k < KP) {
            __nv_bfloat16 h, l;
            split_bf(t[tx][ty + i], h, l);
            Th[(long)m * KP + k] = h;
            Tl[(long)m * KP + k] = l;
        }
    }
}

// ---------------- zero the K-pad region of gate hi/lo (once) ----------------
__global__ void k_padzero(__nv_bfloat16* __restrict__ gh, __nv_bfloat16* __restrict__ gl) {
    int i = blockIdx.x * 256 + threadIdx.x;           // NTOK*(MP-MMF)
    int row = i / (MP - MMF), col = MMF + i % (MP - MMF);
    if (row < NTOK) {
        gh[(long)row * MP + col] = __float2bfloat16(0.f);
        gl[(long)row * MP + col] = __float2bfloat16(0.f);
    }
}

// ---------------- embedding gather ----------------------------------------
__global__ void k_embed(const int* __restrict__ tok, const float* __restrict__ emb,
                        float* __restrict__ x) {
    int i = blockIdx.x * 256 + threadIdx.x;
    int n = i >> 10, d = i & 1023;
    x[i] = emb[(long)tok[n] * DD + d];
}

// ---------------- rmsnorm -> bf16 hi/lo -------------------------------------
__global__ void __launch_bounds__(256) k_rmsnorm(const float* __restrict__ x,
                                                 const float* __restrict__ w,
                                                 __nv_bfloat16* __restrict__ oh,
                                                 __nv_bfloat16* __restrict__ ol) {
    int row = blockIdx.x;
    const float* xr = x + (long)row * DD;
    float s = 0.f;
    for (int c = threadIdx.x; c < DD; c += 256) { float v = xr[c]; s += v * v; }
    __shared__ float red[8];
    #pragma unroll
    for (int off = 16; off; off >>= 1) s += __shfl_xor_sync(0xffffffffu, s, off);
    if ((threadIdx.x & 31) == 0) red[threadIdx.x >> 5] = s;
    __syncthreads();
    if (threadIdx.x == 0) {
        float t = 0.f;
        #pragma unroll
        for (int i = 0; i < 8; ++i) t += red[i];
        red[0] = t;
    }
    __syncthreads();
    float r = rsqrtf(red[0] * (1.0f / DD) + 1e-6f);
    for (int c = threadIdx.x; c < DD; c += 256) {
        float v = xr[c] * r * w[c];
        __nv_bfloat16 h, l;
        split_bf(v, h, l);
        oh[(long)row * DD + c] = h;
        ol[(long)row * DD + c] = l;
    }
}

// ---------------- bf16 split-3 GEMM, cp.async 2-stage pipeline --------------
// A: N x K (bf16 hi/lo k-major), B: M x K (bf16 hi/lo k-major). K%32==0.
// smem words, row stride XS=20 (20%32==4 -> conflict-free frag LDS).
#define XS 20
#define ASZ (128*XS)
__global__ void __launch_bounds__(256, 2) k_gemm_bf3(
        const __nv_bfloat16* __restrict__ Ah_, const __nv_bfloat16* __restrict__ Al_,
        const __nv_bfloat16* __restrict__ Bh_, const __nv_bfloat16* __restrict__ Bl_,
        const float* __restrict__ bias, const float* __restrict__ add,
        float* __restrict__ C, int N, int K, int M) {
    extern __shared__ unsigned sm[];
    const unsigned* Ahw = (const unsigned*)Ah_;
    const unsigned* Alw = (const unsigned*)Al_;
    const unsigned* Bhw = (const unsigned*)Bh_;
    const unsigned* Blw = (const unsigned*)Bl_;
    int tid = threadIdx.x, wid = tid >> 5, lane = tid & 31;
    int g = lane >> 2, t = lane & 3;
    int wm = (wid & 1) * 64, wn = (wid >> 1) * 32;
    int br = blockIdx.y * 128, bc = blockIdx.x * 128;
    int Kw = K >> 1;
    int NC = Kw >> 4;                       // K%32==0 guaranteed
    unsigned sbase = (unsigned)__cvta_generic_to_shared(sm);
    float acc[4][4][4] = {};

    // per-thread load coords: i = tid + half*256, row = i>>2, w4 = (i&3)*4
    int lrow0 = tid >> 2, lw4 = (tid & 3) * 4;
    int lrow1 = lrow0 + 64;
    int brow0 = bc + lrow0; if (brow0 >= M) brow0 = M - 1;
    int brow1 = bc + lrow1; if (brow1 >= M) brow1 = M - 1;

    auto load_chunk = [&](int c, int stage) {
        int kw = c * 16 + lw4;
        unsigned sb = sbase + (unsigned)stage * (4u * ASZ * 4u);
        unsigned d0 = sb + (lrow0 * XS + lw4) * 4u;
        unsigned d1 = sb + (lrow1 * XS + lw4) * 4u;
        long a0 = (long)(br + lrow0) * Kw + kw;
        long a1 = (long)(br + lrow1) * Kw + kw;
        long b0 = (long)brow0 * Kw + kw;
        long b1 = (long)brow1 * Kw + kw;
        cp16(d0,                 Ahw + a0);
        cp16(d1,                 Ahw + a1);
        cp16(d0 + ASZ * 4u,      Alw + a0);
        cp16(d1 + ASZ * 4u,      Alw + a1);
        cp16(d0 + 2u * ASZ * 4u, Bhw + b0);
        cp16(d1 + 2u * ASZ * 4u, Bhw + b1);
        cp16(d0 + 3u * ASZ * 4u, Blw + b0);
        cp16(d1 + 3u * ASZ * 4u, Blw + b1);
        cp_commit();
    };

    load_chunk(0, 0);

    for (int c = 0; c < NC; ++c) {
        if (c + 1 < NC) {
            load_chunk(c + 1, (c + 1) & 1);
            cp_wait<1>();
        } else {
            cp_wait<0>();
        }
        __syncthreads();
        const unsigned* Ash = sm + (c & 1) * (4 * ASZ);
        const unsigned* Asl = Ash + ASZ;
        const unsigned* Bsh = Ash + 2 * ASZ;
        const unsigned* Bsl = Ash + 3 * ASZ;
        #pragma unroll
        for (int ks = 0; ks < 2; ++ks) {
            int kpb = ks * 8;
            unsigned ah[4][4], al[4][4], bh[4][2], bl[4][2];
            #pragma unroll
            for (int mt = 0; mt < 4; ++mt) {
                int mrow = wm + mt * 16 + g;
                ah[mt][0] = Ash[mrow * XS + kpb + t];
                ah[mt][1] = Ash[(mrow + 8) * XS + kpb + t];
                ah[mt][2] = Ash[mrow * XS + kpb + t + 4];
                ah[mt][3] = Ash[(mrow + 8) * XS + kpb + t + 4];
                al[mt][0] = Asl[mrow * XS + kpb + t];
                al[mt][1] = Asl[(mrow + 8) * XS + kpb + t];
                al[mt][2] = Asl[mrow * XS + kpb + t + 4];
                al[mt][3] = Asl[(mrow + 8) * XS + kpb + t + 4];
            }
            #pragma unroll
            for (int nt = 0; nt < 4; ++nt) {
                int nrow = wn + nt * 8 + g;
                bh[nt][0] = Bsh[nrow * XS + kpb + t];
                bh[nt][1] = Bsh[nrow * XS + kpb + t + 4];
                bl[nt][0] = Bsl[nrow * XS + kpb + t];
                bl[nt][1] = Bsl[nrow * XS + kpb + t + 4];
            }
            #pragma unroll
            for (int mt = 0; mt < 4; ++mt)
                #pragma unroll
                for (int nt = 0; nt < 4; ++nt) {
                    mma_bf16(acc[mt][nt], ah[mt], bh[nt], acc[mt][nt]);
                    mma_bf16(acc[mt][nt], ah[mt], bl[nt], acc[mt][nt]);
                    mma_bf16(acc[mt][nt], al[mt], bh[nt], acc[mt][nt]);
                }
        }
        __syncthreads();
    }

    #pragma unroll
    for (int mt = 0; mt < 4; ++mt) {
        int r0 = br + wm + mt * 16 + g;
        #pragma unroll
        for (int nt = 0; nt < 4; ++nt) {
            int c0 = bc + wn + nt * 8 + 2 * t;
            const float* a4 = acc[mt][nt];
            if (c0 < M) {
                float bv = bias ? bias[c0] : 0.f;
                float v0 = a4[0] + bv;
                float v2 = a4[2] + bv;
                if (add) { v0 += add[(long)r0 * M + c0]; v2 += add[(long)(r0 + 8) * M + c0]; }
                C[(long)r0 * M + c0] = v0;
                C[(long)(r0 + 8) * M + c0] = v2;
            }
            if (c0 + 1 < M) {
                float bv = bias ? bias[c0 + 1] : 0.f;
                float v1 = a4[1] + bv;
                float v3 = a4[3] + bv;
                if (add) { v1 += add[(long)r0 * M + c0 + 1]; v3 += add[(long)(r0 + 8) * M + c0 + 1]; }
                C[(long)r0 * M + c0 + 1] = v1;
                C[(long)(r0 + 8) * M + c0 + 1] = v3;
            }
        }
    }
}

// ---------------- q/k: rope + bf16 split into [bh][tok][64] -----------------
__global__ void k_qk_prep(const float* __restrict__ qkv,
                          __nv_bfloat16* __restrict__ qh, __nv_bfloat16* __restrict__ ql,
                          __nv_bfloat16* __restrict__ kh, __nv_bfloat16* __restrict__ kl) {
    int idx = blockIdx.x * 256 + threadIdx.x;
    int j = idx & 31;
    int h = (idx >> 5) & 15;
    int tok = idx >> 9;
    int s = tok & (SD - 1), b = tok >> 10;
    float freq = powf(10000.f, -(float)j / 32.f);
    float ang = (float)s * freq;
    float sn, cs;
    sincosf(ang, &sn, &cs);
    const float* base = qkv + (long)tok * 3 * DD + h * HDIM + 2 * j;
    float qe = base[0], qo = base[1];
    float ke = base[DD], ko = base[DD + 1];
    float q0 = qe * cs - qo * sn, q1 = qe * sn + qo * cs;
    float k0 = ke * cs - ko * sn, k1 = ke * sn + ko * cs;
    long off = ((long)(b * HH + h) * SD + s) * 32 + j;
    unsigned hi, lo;
    pack_split2(q0, q1, hi, lo);
    ((unsigned*)qh)[off] = hi;
    ((unsigned*)ql)[off] = lo;
    pack_split2(k0, k1, hi, lo);
    ((unsigned*)kh)[off] = hi;
    ((unsigned*)kl)[off] = lo;
}

// ---------------- v: transpose + bf16 split into [bh][d][tok] ---------------
__global__ void k_v_prep(const float* __restrict__ qkv,
                         __nv_bfloat16* __restrict__ vh, __nv_bfloat16* __restrict__ vl) {
    __shared__ float ts[32][33];
    int bh = blockIdx.z, b = bh >> 4, h = bh & 15;
    int t0 = blockIdx.x * 32, d0 = blockIdx.y * 32;
    int tx = threadIdx.x, ty = threadIdx.y;
    #pragma unroll
    for (int i = 0; i < 32; i += 8) {
        int tok = t0 + ty + i;
        ts[ty + i][tx] = qkv[((long)(b * SD + tok)) * 3 * DD + 2 * DD + h * HDIM + d0 + tx];
    }
    __syncthreads();
    #pragma unroll
    for (int i = 0; i < 32; i += 8) {
        int d = d0 + ty + i, tok = t0 + tx;
        __nv_bfloat16 hh, ll;
        split_bf(ts[tx][ty + i], hh, ll);
        long off = ((long)bh * HDIM + d) * SD + tok;
        vh[off] = hh;
        vl[off] = ll;
    }
}

// ---------------- flash attention: 64 q-rows per block, bf16 split-3 --------
__global__ void __launch_bounds__(128) k_flash(
        const __nv_bfloat16* __restrict__ qh_, const __nv_bfloat16* __restrict__ ql_,
        const __nv_bfloat16* __restrict__ kh_, const __nv_bfloat16* __restrict__ kl_,
        const __nv_bfloat16* __restrict__ vh_, const __nv_bfloat16* __restrict__ vl_,
        __nv_bfloat16* __restrict__ oh_, __nv_bfloat16* __restrict__ ol_) {
    int qt = (int)gridDim.x - 1 - blockIdx.x;
    int bh = blockIdx.y;
    __shared__ unsigned Ksh[64 * 36], Ksl[64 * 36];
    __shared__ unsigned Vsh[64 * 36], Vsl[64 * 36];
    int tid = threadIdx.x, wid = tid >> 5, lane = tid & 31;
    int g = lane >> 2, t = lane & 3;
    const unsigned* qhw = (const unsigned*)qh_;
    const unsigned* qlw = (const unsigned*)ql_;
    const unsigned* khw = (const unsigned*)kh_;
    const unsigned* klw = (const unsigned*)kl_;
    const unsigned* vhw = (const unsigned*)vh_;
    const unsigned* vlw = (const unsigned*)vl_;

    long qbase = ((long)bh * SD + qt * 64) * 32;
    #pragma unroll
    for (int it = 0; it < 16; ++it) {
        int idx = tid + it * 128;
        int row = idx >> 5, col = idx & 31;
        Ksh[row * 36 + col] = qhw[qbase + row * 32 + col];
        Ksl[row * 36 + col] = qlw[qbase + row * 32 + col];
    }
    __syncthreads();
    int r0 = wid * 16 + g;
    unsigned qfh[4][4], qfl[4][4];
    #pragma unroll
    for (int kk = 0; kk < 4; ++kk) {
        qfh[kk][0] = Ksh[r0 * 36 + kk * 8 + t];
        qfh[kk][1] = Ksh[(r0 + 8) * 36 + kk * 8 + t];
        qfh[kk][2] = Ksh[r0 * 36 + kk * 8 + t + 4];
        qfh[kk][3] = Ksh[(r0 + 8) * 36 + kk * 8 + t + 4];
        qfl[kk][0] = Ksl[r0 * 36 + kk * 8 + t];
        qfl[kk][1] = Ksl[(r0 + 8) * 36 + kk * 8 + t];
        qfl[kk][2] = Ksl[r0 * 36 + kk * 8 + t + 4];
        qfl[kk][3] = Ksl[(r0 + 8) * 36 + kk * 8 + t + 4];
    }
    __syncthreads();

    float m0 = -INFINITY, m1 = -INFINITY, l0 = 0.f, l1 = 0.f;
    float od[8][4] = {};

    for (int kt = 0; kt <= qt; ++kt) {
        long kb = ((long)bh * SD + kt * 64) * 32;
        long vb = (long)bh * HDIM * (SD / 2) + kt * 32;
        #pragma unroll
        for (int it = 0; it < 16; ++it) {
            int idx = tid + it * 128;
            int row = idx >> 5, col = idx & 31;
            Ksh[row * 36 + col] = khw[kb + row * 32 + col];
            Ksl[row * 36 + col] = klw[kb + row * 32 + col];
            Vsh[row * 36 + col] = vhw[vb + (long)row * (SD / 2) + col];
            Vsl[row * 36 + col] = vlw[vb + (long)row * (SD / 2) + col];
        }
        __syncthreads();

        float sacc[8][4] = {};
        #pragma unroll
        for (int kk = 0; kk < 4; ++kk) {
            #pragma unroll
            for (int nt = 0; nt < 8; ++nt) {
                int n = nt * 8 + g;
                unsigned kbh[2], kbl[2];
                kbh[0] = Ksh[n * 36 + kk * 8 + t];
                kbh[1] = Ksh[n * 36 + kk * 8 + t + 4];
                kbl[0] = Ksl[n * 36 + kk * 8 + t];
                kbl[1] = Ksl[n * 36 + kk * 8 + t + 4];
                mma_bf16(sacc[nt], qfh[kk], kbh, sacc[nt]);
                mma_bf16(sacc[nt], qfh[kk], kbl, sacc[nt]);
                mma_bf16(sacc[nt], qfl[kk], kbh, sacc[nt]);
            }
        }
        #pragma unroll
        for (int nt = 0; nt < 8; ++nt) {
            #pragma unroll
            for (int e = 0; e < 4; ++e) sacc[nt][e] *= 0.125f;
        }
        if (kt == qt) {
            #pragma unroll
            for (int nt = 0; nt < 8; ++nt) {
                int c = nt * 8 + 2 * t;
                if (c > r0)         sacc[nt][0] = -1e30f;
                if (c + 1 > r0)     sacc[nt][1] = -1e30f;
                if (c > r0 + 8)     sacc[nt][2] = -1e30f;
                if (c + 1 > r0 + 8) sacc[nt][3] = -1e30f;
            }
        }
        float tm0 = -1e30f, tm1 = -1e30f;
        #pragma unroll
        for (int nt = 0; nt < 8; ++nt) {
            tm0 = fmaxf(tm0, fmaxf(sacc[nt][0], sacc[nt][1]));
            tm1 = fmaxf(tm1, fmaxf(sacc[nt][2], sacc[nt][3]));
        }
        tm0 = fmaxf(tm0, __shfl_xor_sync(0xffffffffu, tm0, 1));
        tm0 = fmaxf(tm0, __shfl_xor_sync(0xffffffffu, tm0, 2));
        tm1 = fmaxf(tm1, __shfl_xor_sync(0xffffffffu, tm1, 1));
        tm1 = fmaxf(tm1, __shfl_xor_sync(0xffffffffu, tm1, 2));
        float mn0 = fmaxf(m0, tm0), mn1 = fmaxf(m1, tm1);
        float sc0 = __expf(m0 - mn0), sc1 = __expf(m1 - mn1);
        m0 = mn0; m1 = mn1;
        l0 *= sc0; l1 *= sc1;
        #pragma unroll
        for (int nt = 0; nt < 8; ++nt) {
            od[nt][0] *= sc0; od[nt][1] *= sc0;
            od[nt][2] *= sc1; od[nt][3] *= sc1;
        }
        #pragma unroll
        for (int nt = 0; nt < 8; ++nt) {
            sacc[nt][0] = __expf(sacc[nt][0] - m0);
            sacc[nt][1] = __expf(sacc[nt][1] - m0);
            sacc[nt][2] = __expf(sacc[nt][2] - m1);
            sacc[nt][3] = __expf(sacc[nt][3] - m1);
            l0 += sacc[nt][0] + sacc[nt][1];
            l1 += sacc[nt][2] + sacc[nt][3];
        }
        unsigned pah[4][4], pal[4][4];
        #pragma unroll
        for (int kk = 0; kk < 4; ++kk) {
            pack_split2(sacc[2*kk][0],   sacc[2*kk][1],   pah[kk][0], pal[kk][0]);
            pack_split2(sacc[2*kk][2],   sacc[2*kk][3],   pah[kk][1], pal[kk][1]);
            pack_split2(sacc[2*kk+1][0], sacc[2*kk+1][1], pah[kk][2], pal[kk][2]);
            pack_split2(sacc[2*kk+1][2], sacc[2*kk+1][3], pah[kk][3], pal[kk][3]);
        }
        #pragma unroll
        for (int kk = 0; kk < 4; ++kk) {
            #pragma unroll
            for (int nt = 0; nt < 8; ++nt) {
                int n = nt * 8 + g;
                unsigned vbh[2], vbl[2];
                vbh[0] = Vsh[n * 36 + kk * 8 + t];
                vbh[1] = Vsh[n * 36 + kk * 8 + t + 4];
                vbl[0] = Vsl[n * 36 + kk * 8 + t];
                vbl[1] = Vsl[n * 36 + kk * 8 + t + 4];
                mma_bf16(od[nt], pah[kk], vbh, od[nt]);
                mma_bf16(od[nt], pah[kk], vbl, od[nt]);
                mma_bf16(od[nt], pal[kk], vbh, od[nt]);
            }
        }
        __syncthreads();
    }

    l0 += __shfl_xor_sync(0xffffffffu, l0, 1);
    l0 += __shfl_xor_sync(0xffffffffu, l0, 2);
    l1 += __shfl_xor_sync(0xffffffffu, l1, 1);
    l1 += __shfl_xor_sync(0xffffffffu, l1, 2);
    float i0 = 1.f / l0, i1 = 1.f / l1;
    int b = bh >> 4, h = bh & 15;
    long ob0 = ((long)(b * SD + qt * 64 + r0)) * DD + h * HDIM;
    long ob1 = ob0 + 8L * DD;
    #pragma unroll
    for (int nt = 0; nt < 8; ++nt) {
        int d = nt * 8 + 2 * t;
        __nv_bfloat16 hh, ll;
        split_bf(od[nt][0] * i0, hh, ll); oh_[ob0 + d] = hh;     ol_[ob0 + d] = ll;
        split_bf(od[nt][1] * i0, hh, ll); oh_[ob0 + d + 1] = hh; ol_[ob0 + d + 1] = ll;
        split_bf(od[nt][2] * i1, hh, ll); oh_[ob1 + d] = hh;     ol_[ob1 + d] = ll;
        split_bf(od[nt][3] * i1, hh, ll); oh_[ob1 + d + 1] = hh; ol_[ob1 + d + 1] = ll;
    }
}

// ---------------- SwiGLU elementwise -> bf16 hi/lo (padded layout) ----------
__global__ void k_silu(const float* __restrict__ g, const float* __restrict__ u,
                       __nv_bfloat16* __restrict__ oh, __nv_bfloat16* __restrict__ ol) {
    long i = (long)blockIdx.x * 256 + threadIdx.x;
    if (i < (long)NTOK * MMF) {
        int row = (int)(i / MMF);
        int col = (int)(i - (long)row * MMF);
        float s = g[i];
        float v = (s / (1.f + expf(-s))) * u[i];
        __nv_bfloat16 h, l;
        split_bf(v, h, l);
        oh[(long)row * MP + col] = h;
        ol[(long)row * MP + col] = l;
    }
}

// ---------------- head: logits for the 2 last-token rows --------------------
__global__ void __launch_bounds__(256) k_head(const __nv_bfloat16* __restrict__ hh,
                                              const __nv_bfloat16* __restrict__ hl,
                                              const float* __restrict__ W,
                                              const float* __restrict__ bias,
                                              float* __restrict__ out) {
    int bidx = blockIdx.y;
    int col = blockIdx.x * 256 + threadIdx.x;
    __shared__ float sx[DD];
    long roff = (long)(bidx * SD + SD - 1) * DD;
    for (int c = threadIdx.x; c < DD; c += 256)
        sx[c] = __bfloat162float(hh[roff + c]) + __bfloat162float(hl[roff + c]);
    __syncthreads();
    if (col >= VV) return;
    float acc = 0.f;
    #pragma unroll 8
    for (int k = 0; k < DD; ++k) acc += sx[k] * W[(long)k * VV + col];
    out[(long)bidx * VV + col] = acc + bias[col];
}

// ---------------- driver -----------------------------------------------------
extern "C" void kernel_launch(void* const* d_in, const int* in_sizes, int n_in,
                              void* d_out, int out_size) {
    const int*   tokens = (const int*)  d_in[0];
    const float* embed  = (const float*)d_in[1];
    const float* Wqkv   = (const float*)d_in[2];
    const float* bqkv   = (const float*)d_in[3];
    const float* Wout   = (const float*)d_in[4];
    const float* bout   = (const float*)d_in[5];
    const float* ln1    = (const float*)d_in[6];
    const float* ln2    = (const float*)d_in[7];
    const float* Wg     = (const float*)d_in[8];
    const float* bg     = (const float*)d_in[9];
    const float* Wu     = (const float*)d_in[10];
    const float* bu     = (const float*)d_in[11];
    const float* Wd     = (const float*)d_in[12];
    const float* bd     = (const float*)d_in[13];
    const float* lnf    = (const float*)d_in[14];
    const float* Whead  = (const float*)d_in[15];
    const float* bhead  = (const float*)d_in[16];
    float* out = (float*)d_out;

    float *x, *qkv, *gate, *up;
    __nv_bfloat16 *hh, *hl, *ath, *atl, *gth, *gtl;
    __nv_bfloat16 *qh, *ql, *kh, *kl, *vth, *vtl;
    __nv_bfloat16 *wqkvh, *wqkvl, *wouth, *woutl, *wgh, *wgl, *wuh, *wul, *wdh, *wdl;
    cudaGetSymbolAddress((void**)&x,    g_x);
    cudaGetSymbolAddress((void**)&qkv,  g_qkv);
    cudaGetSymbolAddress((void**)&gate, g_gate);
    cudaGetSymbolAddress((void**)&up,   g_up);
    cudaGetSymbolAddress((void**)&hh,   g_h_h);
    cudaGetSymbolAddress((void**)&hl,   g_h_l);
    cudaGetSymbolAddress((void**)&ath,  g_attn_h);
    cudaGetSymbolAddress((void**)&atl,  g_attn_l);
    cudaGetSymbolAddress((void**)&gth,  g_gate_h);
    cudaGetSymbolAddress((void**)&gtl,  g_gate_l);
    cudaGetSymbolAddress((void**)&qh,   g_q_h);
    cudaGetSymbolAddress((void**)&ql,   g_q_l);
    cudaGetSymbolAddress((void**)&kh,   g_k_h);
    cudaGetSymbolAddress((void**)&kl,   g_k_l);
    cudaGetSymbolAddress((void**)&vth,  g_vt_h);
    cudaGetSymbolAddress((void**)&vtl,  g_vt_l);
    cudaGetSymbolAddress((void**)&wqkvh, g_wqkvT_h);
    cudaGetSymbolAddress((void**)&wqkvl, g_wqkvT_l);
    cudaGetSymbolAddress((void**)&wouth, g_woutT_h);
    cudaGetSymbolAddress((void**)&woutl, g_woutT_l);
    cudaGetSymbolAddress((void**)&wgh,  g_wgT_h);
    cudaGetSymbolAddress((void**)&wgl,  g_wgT_l);
    cudaGetSymbolAddress((void**)&wuh,  g_wuT_h);
    cudaGetSymbolAddress((void**)&wul,  g_wuT_l);
    cudaGetSymbolAddress((void**)&wdh,  g_wdT_h);
    cudaGetSymbolAddress((void**)&wdl,  g_wdT_l);

    cudaFuncSetAttribute(k_gemm_bf3, cudaFuncAttributeMaxDynamicSharedMemorySize, 81920);
    const int GSM = 81920;

    // ---- weight split/transpose (batched over layers) ----
    dim3 tb(32, 8);
    k_wsplit<<<dim3(96, 32, LL), tb>>>(Wqkv, wqkvh, wqkvl, DD, 3 * DD, DD,
                                       (long)DD * 3 * DD, (long)3 * DD * DD);
    k_wsplit<<<dim3(32, 32, LL), tb>>>(Wout, wouth, woutl, DD, DD, DD,
                                       (long)DD * DD, (long)DD * DD);
    k_wsplit<<<dim3(86, 32, LL), tb>>>(Wg, wgh, wgl, DD, MMF, DD,
                                       (long)DD * MMF, (long)MMF * DD);
    k_wsplit<<<dim3(86, 32, LL), tb>>>(Wu, wuh, wul, DD, MMF, DD,
                                       (long)DD * MMF, (long)MMF * DD);
    k_wsplit<<<dim3(32, 86, LL), tb>>>(Wd, wdh, wdl, MMF, DD, MP,
                                       (long)MMF * DD, (long)DD * MP);
    k_padzero<<<(NTOK * (MP - MMF) + 255) / 256, 256>>>(gth, gtl);

    k_embed<<<NTOK * DD / 256, 256>>>(tokens, embed, x);

    for (int l = 0; l < LL; ++l) {
        k_rmsnorm<<<NTOK, 256>>>(x, ln1 + (long)l * DD, hh, hl);

        dim3 gq(24, 16);
        k_gemm_bf3<<<gq, 256, GSM>>>(hh, hl,
                                wqkvh + (long)l * 3 * DD * DD, wqkvl + (long)l * 3 * DD * DD,
                                bqkv + (long)l * 3 * DD, nullptr, qkv,
                                NTOK, DD, 3 * DD);

        k_qk_prep<<<NTOK * HH * 32 / 256, 256>>>(qkv, qh, ql, kh, kl);
        k_v_prep<<<dim3(SD / 32, HDIM / 32, BH), dim3(32, 8)>>>(qkv, vth, vtl);

        k_flash<<<dim3(SD / 64, BH), 128>>>(qh, ql, kh, kl, vth, vtl, ath, atl);

        dim3 go(8, 16);
        k_gemm_bf3<<<go, 256, GSM>>>(ath, atl,
                                wouth + (long)l * DD * DD, woutl + (long)l * DD * DD,
                                bout + (long)l * DD, x, x,
                                NTOK, DD, DD);

        k_rmsnorm<<<NTOK, 256>>>(x, ln2 + (long)l * DD, hh, hl);

        dim3 gm(22, 16);
        k_gemm_bf3<<<gm, 256, GSM>>>(hh, hl,
                                wgh + (long)l * MMF * DD, wgl + (long)l * MMF * DD,
                                bg + (long)l * MMF, nullptr, gate,
                                NTOK, DD, MMF);
        k_gemm_bf3<<<gm, 256, GSM>>>(hh, hl,
                                wuh + (long)l * MMF * DD, wul + (long)l * MMF * DD,
                                bu + (long)l * MMF, nullptr, up,
                                NTOK, DD, MMF);

        long nel = (long)NTOK * MMF;
        k_silu<<<(int)((nel + 255) / 256), 256>>>(gate, up, gth, gtl);

        dim3 gd(8, 16);
        k_gemm_bf3<<<gd, 256, GSM>>>(gth, gtl,
                                wdh + (long)l * DD * MP, wdl + (long)l * DD * MP,
                                bd + (long)l * DD, x, x,
                                NTOK, MP, DD);
    }

    k_rmsnorm<<<NTOK, 256>>>(x, lnf, hh, hl);
    dim3 gh((VV + 255) / 256, BD);
    k_head<<<gh, 256>>>(hh, hl, Whead, bhead, out);
}

// round 8
// speedup vs baseline: 3.7490x; 1.0720x over previous
#include <cuda_runtime.h>
#include <cuda_bf16.h>
#include <math.h>

#define BD   2
#define SD   1024
#define DD   1024
#define HH   16
#define HDIM 64
#define LL   4
#define MMF  2730
#define MP   2752          // MMF padded to a multiple of 32 (16B-aligned rows)
#define VV   32000
#define NTOK (BD*SD)
#define BH   (BD*HH)

// ---------------- scratch (device globals; no allocation allowed) ----------
__device__ float g_x[NTOK*DD];
__device__ float g_qkv[NTOK*3*DD];
__device__ float g_gate[NTOK*MMF];
__device__ float g_up[NTOK*MMF];

__device__ __nv_bfloat16 g_h_h[NTOK*DD],    g_h_l[NTOK*DD];
__device__ __nv_bfloat16 g_attn_h[NTOK*DD], g_attn_l[NTOK*DD];
__device__ __nv_bfloat16 g_gate_h[NTOK*MP], g_gate_l[NTOK*MP];

__device__ __nv_bfloat16 g_q_h[BH*SD*HDIM], g_q_l[BH*SD*HDIM];
__device__ __nv_bfloat16 g_k_h[BH*SD*HDIM], g_k_l[BH*SD*HDIM];
__device__ __nv_bfloat16 g_vt_h[BH*SD*HDIM], g_vt_l[BH*SD*HDIM];

__device__ __nv_bfloat16 g_wqkvT_h[LL*3*DD*DD], g_wqkvT_l[LL*3*DD*DD];
__device__ __nv_bfloat16 g_woutT_h[LL*DD*DD],   g_woutT_l[LL*DD*DD];
__device__ __nv_bfloat16 g_wgT_h[LL*MMF*DD],    g_wgT_l[LL*MMF*DD];
__device__ __nv_bfloat16 g_wuT_h[LL*MMF*DD],    g_wuT_l[LL*MMF*DD];
__device__ __nv_bfloat16 g_wdT_h[(long)LL*DD*MP], g_wdT_l[(long)LL*DD*MP];

// ---------------- helpers ----------------------------------------------------
__device__ __forceinline__ void split_bf(float f, __nv_bfloat16& h, __nv_bfloat16& l) {
    h = __float2bfloat16(f);
    l = __float2bfloat16(f - __bfloat162float(h));
}
__device__ __forceinline__ void pack_split2(float a, float b, unsigned& hi, unsigned& lo) {
    __nv_bfloat162 th, tl;
    th.x = __float2bfloat16(a);
    th.y = __float2bfloat16(b);
    tl.x = __float2bfloat16(a - __bfloat162float(th.x));
    tl.y = __float2bfloat16(b - __bfloat162float(th.y));
    hi = *(unsigned*)&th;
    lo = *(unsigned*)&tl;
}
__device__ __forceinline__ void mma_bf16(float* d, const unsigned* a,
                                         const unsigned* b, const float* c) {
    asm volatile(
        "mma.sync.aligned.m16n8k16.row.col.f32.bf16.bf16.f32 "
        "{%0,%1,%2,%3}, {%4,%5,%6,%7}, {%8,%9}, {%10,%11,%12,%13};"
        : "=f"(d[0]), "=f"(d[1]), "=f"(d[2]), "=f"(d[3])
        : "r"(a[0]), "r"(a[1]), "r"(a[2]), "r"(a[3]),
          "r"(b[0]), "r"(b[1]),
          "f"(c[0]), "f"(c[1]), "f"(c[2]), "f"(c[3]));
}
__device__ __forceinline__ void ldsm4(unsigned& r0, unsigned& r1, unsigned& r2,
                                      unsigned& r3, unsigned addr) {
    asm volatile("ldmatrix.sync.aligned.m8n8.x4.shared.b16 {%0,%1,%2,%3}, [%4];"
                 : "=r"(r0), "=r"(r1), "=r"(r2), "=r"(r3) : "r"(addr));
}
__device__ __forceinline__ void cp16(unsigned saddr, const void* g) {
    asm volatile("cp.async.cg.shared.global [%0], [%1], 16;" :: "r"(saddr), "l"(g));
}
__device__ __forceinline__ void cp_commit() {
    asm volatile("cp.async.commit_group;");
}
template<int N> __device__ __forceinline__ void cp_wait() {
    asm volatile("cp.async.wait_group %0;" :: "n"(N));
}

// ---------------- weight transpose + bf16 split (batched over layers) -------
__global__ void k_wsplit(const float* __restrict__ W,
                         __nv_bfloat16* __restrict__ Th,
                         __nv_bfloat16* __restrict__ Tl,
                         int K, int M, int KP, long wstride, long tstride) {
    W  += (long)blockIdx.z * wstride;
    Th += (long)blockIdx.z * tstride;
    Tl += (long)blockIdx.z * tstride;
    __shared__ float t[32][33];
    int m0 = blockIdx.x * 32, k0 = blockIdx.y * 32;
    int tx = threadIdx.x, ty = threadIdx.y;
    #pragma unroll
    for (int i = 0; i < 32; i += 8) {
        int k = k0 + ty + i, m = m0 + tx;
        t[ty + i][tx] = (k < K && m < M) ? W[(long)k * M + m] : 0.f;
    }
    __syncthreads();
    #pragma unroll
    for (int i = 0; i < 32; i += 8) {
        int m = m0 + ty + i, k = k0 + tx;
        if (m < M && k < KP) {
            __nv_bfloat16 h, l;
            split_bf(t[tx][ty + i], h, l);
            Th[(long)m * KP + k] = h;
            Tl[(long)m * KP + k] = l;
        }
    }
}

__global__ void k_padzero(__nv_bfloat16* __restrict__ gh, __nv_bfloat16* __restrict__ gl) {
    int i = blockIdx.x * 256 + threadIdx.x;
    int row = i / (MP - MMF), col = MMF + i % (MP - MMF);
    if (row < NTOK) {
        gh[(long)row * MP + col] = __float2bfloat16(0.f);
        gl[(long)row * MP + col] = __float2bfloat16(0.f);
    }
}

__global__ void k_embed(const int* __restrict__ tok, const float* __restrict__ emb,
                        float* __restrict__ x) {
    int i = blockIdx.x * 256 + threadIdx.x;
    int n = i >> 10, d = i & 1023;
    x[i] = emb[(long)tok[n] * DD + d];
}

__global__ void __launch_bounds__(256) k_rmsnorm(const float* __restrict__ x,
                                                 const float* __restrict__ w,
                                                 __nv_bfloat16* __restrict__ oh,
                                                 __nv_bfloat16* __restrict__ ol) {
    int row = blockIdx.x;
    const float* xr = x + (long)row * DD;
    float s = 0.f;
    for (int c = threadIdx.x; c < DD; c += 256) { float v = xr[c]; s += v * v; }
    __shared__ float red[8];
    #pragma unroll
    for (int off = 16; off; off >>= 1) s += __shfl_xor_sync(0xffffffffu, s, off);
    if ((threadIdx.x & 31) == 0) red[threadIdx.x >> 5] = s;
    __syncthreads();
    if (threadIdx.x == 0) {
        float t = 0.f;
        #pragma unroll
        for (int i = 0; i < 8; ++i) t += red[i];
        red[0] = t;
    }
    __syncthreads();
    float r = rsqrtf(red[0] * (1.0f / DD) + 1e-6f);
    for (int c = threadIdx.x; c < DD; c += 256) {
        float v = xr[c] * r * w[c];
        __nv_bfloat16 h, l;
        split_bf(v, h, l);
        oh[(long)row * DD + c] = h;
        ol[(long)row * DD + c] = l;
    }
}

// ---------------- bf16 split-3 GEMM, cp.async 2-stage + ldmatrix ------------
// A: N x K (bf16 hi/lo k-major), B: M x K (bf16 hi/lo k-major). K%32==0.
// smem words, row stride XS=20 (20%32==4 -> conflict-free LDSM phases).
#define XS 20
#define ASZ (128*XS)
__global__ void __launch_bounds__(256, 2) k_gemm_bf3(
        const __nv_bfloat16* __restrict__ Ah_, const __nv_bfloat16* __restrict__ Al_,
        const __nv_bfloat16* __restrict__ Bh_, const __nv_bfloat16* __restrict__ Bl_,
        const float* __restrict__ bias, const float* __restrict__ add,
        float* __restrict__ C, int N, int K, int M) {
    extern __shared__ unsigned sm[];
    const unsigned* Ahw = (const unsigned*)Ah_;
    const unsigned* Alw = (const unsigned*)Al_;
    const unsigned* Bhw = (const unsigned*)Bh_;
    const unsigned* Blw = (const unsigned*)Bl_;
    int tid = threadIdx.x, wid = tid >> 5, lane = tid & 31;
    int wm = (wid & 1) * 64, wn = (wid >> 1) * 32;
    int br = blockIdx.y * 128, bc = blockIdx.x * 128;
    int Kw = K >> 1;
    int NC = Kw >> 4;
    unsigned sbase = (unsigned)__cvta_generic_to_shared(sm);
    float acc[4][4][4] = {};

    // cp.async per-thread coords
    int lrow0 = tid >> 2, lw4 = (tid & 3) * 4;
    int lrow1 = lrow0 + 64;
    int brow0 = bc + lrow0; if (brow0 >= M) brow0 = M - 1;
    int brow1 = bc + lrow1; if (brow1 >= M) brow1 = M - 1;

    auto load_chunk = [&](int c, int stage) {
        int kw = c * 16 + lw4;
        unsigned sb = sbase + (unsigned)stage * (4u * ASZ * 4u);
        unsigned d0 = sb + (lrow0 * XS + lw4) * 4u;
        unsigned d1 = sb + (lrow1 * XS + lw4) * 4u;
        long a0 = (long)(br + lrow0) * Kw + kw;
        long a1 = (long)(br + lrow1) * Kw + kw;
        long b0 = (long)brow0 * Kw + kw;
        long b1 = (long)brow1 * Kw + kw;
        cp16(d0,                 Ahw + a0);
        cp16(d1,                 Ahw + a1);
        cp16(d0 + ASZ * 4u,      Alw + a0);
        cp16(d1 + ASZ * 4u,      Alw + a1);
        cp16(d0 + 2u * ASZ * 4u, Bhw + b0);
        cp16(d1 + 2u * ASZ * 4u, Bhw + b1);
        cp16(d0 + 3u * ASZ * 4u, Blw + b0);
        cp16(d1 + 3u * ASZ * 4u, Blw + b1);
        cp_commit();
    };

    // ldmatrix per-lane address components
    int rq   = lane & 7;
    int a_r  = rq + ((lane >> 3) & 1) * 8;      // A: quad&1 -> +8 rows
    int a_wo = ((lane >> 4) << 2);              // A: quad>>1 -> +4 words
    int b_r  = rq + ((lane >> 4) << 3);         // B: quad>>1 -> +8 rows
    int b_wo = (((lane >> 3) & 1) << 2);        // B: quad&1 -> +4 words

    load_chunk(0, 0);

    for (int c = 0; c < NC; ++c) {
        if (c + 1 < NC) {
            load_chunk(c + 1, (c + 1) & 1);
            cp_wait<1>();
        } else {
            cp_wait<0>();
        }
        __syncthreads();
        unsigned stg = sbase + (unsigned)(c & 1) * (4u * ASZ * 4u);
        unsigned aAh = stg;
        unsigned aAl = stg + ASZ * 4u;
        unsigned aBh = stg + 2u * ASZ * 4u;
        unsigned aBl = stg + 3u * ASZ * 4u;
        #pragma unroll
        for (int ks = 0; ks < 2; ++ks) {
            int kpb = ks * 8;
            unsigned ah[4][4], al[4][4], bh[4][2], bl[4][2];
            #pragma unroll
            for (int mt = 0; mt < 4; ++mt) {
                unsigned off = (unsigned)(((wm + mt * 16 + a_r) * XS + kpb + a_wo) * 4);
                ldsm4(ah[mt][0], ah[mt][1], ah[mt][2], ah[mt][3], aAh + off);
                ldsm4(al[mt][0], al[mt][1], al[mt][2], al[mt][3], aAl + off);
            }
            #pragma unroll
            for (int p = 0; p < 2; ++p) {
                unsigned off = (unsigned)(((wn + p * 16 + b_r) * XS + kpb + b_wo) * 4);
                ldsm4(bh[2*p][0], bh[2*p][1], bh[2*p+1][0], bh[2*p+1][1], aBh + off);
                ldsm4(bl[2*p][0], bl[2*p][1], bl[2*p+1][0], bl[2*p+1][1], aBl + off);
            }
            #pragma unroll
            for (int mt = 0; mt < 4; ++mt)
                #pragma unroll
                for (int nt = 0; nt < 4; ++nt) {
                    mma_bf16(acc[mt][nt], ah[mt], bh[nt], acc[mt][nt]);
                    mma_bf16(acc[mt][nt], ah[mt], bl[nt], acc[mt][nt]);
                    mma_bf16(acc[mt][nt], al[mt], bh[nt], acc[mt][nt]);
                }
        }
        __syncthreads();
    }

    int g = lane >> 2, t = lane & 3;
    #pragma unroll
    for (int mt = 0; mt < 4; ++mt) {
        int r0 = br + wm + mt * 16 + g;
        #pragma unroll
        for (int nt = 0; nt < 4; ++nt) {
            int c0 = bc + wn + nt * 8 + 2 * t;
            const float* a4 = acc[mt][nt];
            if (c0 < M) {
                float bv = bias ? bias[c0] : 0.f;
                float v0 = a4[0] + bv;
                float v2 = a4[2] + bv;
                if (add) { v0 += add[(long)r0 * M + c0]; v2 += add[(long)(r0 + 8) * M + c0]; }
                C[(long)r0 * M + c0] = v0;
                C[(long)(r0 + 8) * M + c0] = v2;
            }
            if (c0 + 1 < M) {
                float bv = bias ? bias[c0 + 1] : 0.f;
                float v1 = a4[1] + bv;
                float v3 = a4[3] + bv;
                if (add) { v1 += add[(long)r0 * M + c0 + 1]; v3 += add[(long)(r0 + 8) * M + c0 + 1]; }
                C[(long)r0 * M + c0 + 1] = v1;
                C[(long)(r0 + 8) * M + c0 + 1] = v3;
            }
        }
    }
}

// ---------------- q/k: rope + bf16 split into [bh][tok][64] -----------------
__global__ void k_qk_prep(const float* __restrict__ qkv,
                          __nv_bfloat16* __restrict__ qh, __nv_bfloat16* __restrict__ ql,
                          __nv_bfloat16* __restrict__ kh, __nv_bfloat16* __restrict__ kl) {
    int idx = blockIdx.x * 256 + threadIdx.x;
    int j = idx & 31;
    int h = (idx >> 5) & 15;
    int tok = idx >> 9;
    int s = tok & (SD - 1), b = tok >> 10;
    float freq = powf(10000.f, -(float)j / 32.f);
    float ang = (float)s * freq;
    float sn, cs;
    sincosf(ang, &sn, &cs);
    const float* base = qkv + (long)tok * 3 * DD + h * HDIM + 2 * j;
    float qe = base[0], qo = base[1];
    float ke = base[DD], ko = base[DD + 1];
    float q0 = qe * cs - qo * sn, q1 = qe * sn + qo * cs;
    float k0 = ke * cs - ko * sn, k1 = ke * sn + ko * cs;
    long off = ((long)(b * HH + h) * SD + s) * 32 + j;
    unsigned hi, lo;
    pack_split2(q0, q1, hi, lo);
    ((unsigned*)qh)[off] = hi;
    ((unsigned*)ql)[off] = lo;
    pack_split2(k0, k1, hi, lo);
    ((unsigned*)kh)[off] = hi;
    ((unsigned*)kl)[off] = lo;
}

// ---------------- v: transpose + bf16 split into [bh][d][tok] ---------------
__global__ void k_v_prep(const float* __restrict__ qkv,
                         __nv_bfloat16* __restrict__ vh, __nv_bfloat16* __restrict__ vl) {
    __shared__ float ts[32][33];
    int bh = blockIdx.z, b = bh >> 4, h = bh & 15;
    int t0 = blockIdx.x * 32, d0 = blockIdx.y * 32;
    int tx = threadIdx.x, ty = threadIdx.y;
    #pragma unroll
    for (int i = 0; i < 32; i += 8) {
        int tok = t0 + ty + i;
        ts[ty + i][tx] = qkv[((long)(b * SD + tok)) * 3 * DD + 2 * DD + h * HDIM + d0 + tx];
    }
    __syncthreads();
    #pragma unroll
    for (int i = 0; i < 32; i += 8) {
        int d = d0 + ty + i, tok = t0 + tx;
        __nv_bfloat16 hh, ll;
        split_bf(ts[tx][ty + i], hh, ll);
        long off = ((long)bh * HDIM + d) * SD + tok;
        vh[off] = hh;
        vl[off] = ll;
    }
}

// ---------------- flash attention: 64 q-rows per block, bf16 split-3 --------
__global__ void __launch_bounds__(128) k_flash(
        const __nv_bfloat16* __restrict__ qh_, const __nv_bfloat16* __restrict__ ql_,
        const __nv_bfloat16* __restrict__ kh_, const __nv_bfloat16* __restrict__ kl_,
        const __nv_bfloat16* __restrict__ vh_, const __nv_bfloat16* __restrict__ vl_,
        __nv_bfloat16* __restrict__ oh_, __nv_bfloat16* __restrict__ ol_) {
    int qt = (int)gridDim.x - 1 - blockIdx.x;
    int bh = blockIdx.y;
    __shared__ unsigned Ksh[64 * 36], Ksl[64 * 36];
    __shared__ unsigned Vsh[64 * 36], Vsl[64 * 36];
    int tid = threadIdx.x, wid = tid >> 5, lane = tid & 31;
    int g = lane >> 2, t = lane & 3;
    const unsigned* qhw = (const unsigned*)qh_;
    const unsigned* qlw = (const unsigned*)ql_;
    const unsigned* khw = (const unsigned*)kh_;
    const unsigned* klw = (const unsigned*)kl_;
    const unsigned* vhw = (const unsigned*)vh_;
    const unsigned* vlw = (const unsigned*)vl_;

    long qbase = ((long)bh * SD + qt * 64) * 32;
    #pragma unroll
    for (int it = 0; it < 16; ++it) {
        int idx = tid + it * 128;
        int row = idx >> 5, col = idx & 31;
        Ksh[row * 36 + col] = qhw[qbase + row * 32 + col];
        Ksl[row * 36 + col] = qlw[qbase + row * 32 + col];
    }
    __syncthreads();
    int r0 = wid * 16 + g;
    unsigned qfh[4][4], qfl[4][4];
    #pragma unroll
    for (int kk = 0; kk < 4; ++kk) {
        qfh[kk][0] = Ksh[r0 * 36 + kk * 8 + t];
        qfh[kk][1] = Ksh[(r0 + 8) * 36 + kk * 8 + t];
        qfh[kk][2] = Ksh[r0 * 36 + kk * 8 + t + 4];
        qfh[kk][3] = Ksh[(r0 + 8) * 36 + kk * 8 + t + 4];
        qfl[kk][0] = Ksl[r0 * 36 + kk * 8 + t];
        qfl[kk][1] = Ksl[(r0 + 8) * 36 + kk * 8 + t];
        qfl[kk][2] = Ksl[r0 * 36 + kk * 8 + t + 4];
        qfl[kk][3] = Ksl[(r0 + 8) * 36 + kk * 8 + t + 4];
    }
    __syncthreads();

    float m0 = -INFINITY, m1 = -INFINITY, l0 = 0.f, l1 = 0.f;
    float od[8][4] = {};

    for (int kt = 0; kt <= qt; ++kt) {
        long kb = ((long)bh * SD + kt * 64) * 32;
        long vb = (long)bh * HDIM * (SD / 2) + kt * 32;
        #pragma unroll
        for (int it = 0; it < 16; ++it) {
            int idx = tid + it * 128;
            int row = idx >> 5, col = idx & 31;
            Ksh[row * 36 + col] = khw[kb + row * 32 + col];
            Ksl[row * 36 + col] = klw[kb + row * 32 + col];
            Vsh[row * 36 + col] = vhw[vb + (long)row * (SD / 2) + col];
            Vsl[row * 36 + col] = vlw[vb + (long)row * (SD / 2) + col];
        }
        __syncthreads();

        float sacc[8][4] = {};
        #pragma unroll
        for (int kk = 0; kk < 4; ++kk) {
            #pragma unroll
            for (int nt = 0; nt < 8; ++nt) {
                int n = nt * 8 + g;
                unsigned kbh[2], kbl[2];
                kbh[0] = Ksh[n * 36 + kk * 8 + t];
                kbh[1] = Ksh[n * 36 + kk * 8 + t + 4];
                kbl[0] = Ksl[n * 36 + kk * 8 + t];
                kbl[1] = Ksl[n * 36 + kk * 8 + t + 4];
                mma_bf16(sacc[nt], qfh[kk], kbh, sacc[nt]);
                mma_bf16(sacc[nt], qfh[kk], kbl, sacc[nt]);
                mma_bf16(sacc[nt], qfl[kk], kbh, sacc[nt]);
            }
        }
        #pragma unroll
        for (int nt = 0; nt < 8; ++nt) {
            #pragma unroll
            for (int e = 0; e < 4; ++e) sacc[nt][e] *= 0.125f;
        }
        if (kt == qt) {
            #pragma unroll
            for (int nt = 0; nt < 8; ++nt) {
                int c = nt * 8 + 2 * t;
                if (c > r0)         sacc[nt][0] = -1e30f;
                if (c + 1 > r0)     sacc[nt][1] = -1e30f;
                if (c > r0 + 8)     sacc[nt][2] = -1e30f;
                if (c + 1 > r0 + 8) sacc[nt][3] = -1e30f;
            }
        }
        float tm0 = -1e30f, tm1 = -1e30f;
        #pragma unroll
        for (int nt = 0; nt < 8; ++nt) {
            tm0 = fmaxf(tm0, fmaxf(sacc[nt][0], sacc[nt][1]));
            tm1 = fmaxf(tm1, fmaxf(sacc[nt][2], sacc[nt][3]));
        }
        tm0 = fmaxf(tm0, __shfl_xor_sync(0xffffffffu, tm0, 1));
        tm0 = fmaxf(tm0, __shfl_xor_sync(0xffffffffu, tm0, 2));
        tm1 = fmaxf(tm1, __shfl_xor_sync(0xffffffffu, tm1, 1));
        tm1 = fmaxf(tm1, __shfl_xor_sync(0xffffffffu, tm1, 2));
        float mn0 = fmaxf(m0, tm0), mn1 = fmaxf(m1, tm1);
        float sc0 = __expf(m0 - mn0), sc1 = __expf(m1 - mn1);
        m0 = mn0; m1 = mn1;
        l0 *= sc0; l1 *= sc1;
        #pragma unroll
        for (int nt = 0; nt < 8; ++nt) {
            od[nt][0] *= sc0; od[nt][1] *= sc0;
            od[nt][2] *= sc1; od[nt][3] *= sc1;
        }
        #pragma unroll
        for (int nt = 0; nt < 8; ++nt) {
            sacc[nt][0] = __expf(sacc[nt][0] - m0);
            sacc[nt][1] = __expf(sacc[nt][1] - m0);
            sacc[nt][2] = __expf(sacc[nt][2] - m1);
            sacc[nt][3] = __expf(sacc[nt][3] - m1);
            l0 += sacc[nt][0] + sacc[nt][1];
            l1 += sacc[nt][2] + sacc[nt][3];
        }
        unsigned pah[4][4], pal[4][4];
        #pragma unroll
        for (int kk = 0; kk < 4; ++kk) {
            pack_split2(sacc[2*kk][0],   sacc[2*kk][1],   pah[kk][0], pal[kk][0]);
            pack_split2(sacc[2*kk][2],   sacc[2*kk][3],   pah[kk][1], pal[kk][1]);
            pack_split2(sacc[2*kk+1][0], sacc[2*kk+1][1], pah[kk][2], pal[kk][2]);
            pack_split2(sacc[2*kk+1][2], sacc[2*kk+1][3], pah[kk][3], pal[kk][3]);
        }
        #pragma unroll
        for (int kk = 0; kk < 4; ++kk) {
            #pragma unroll
            for (int nt = 0; nt < 8; ++nt) {
                int n = nt * 8 + g;
                unsigned vbh[2], vbl[2];
                vbh[0] = Vsh[n * 36 + kk * 8 + t];
                vbh[1] = Vsh[n * 36 + kk * 8 + t + 4];
                vbl[0] = Vsl[n * 36 + kk * 8 + t];
                vbl[1] = Vsl[n * 36 + kk * 8 + t + 4];
                mma_bf16(od[nt], pah[kk], vbh, od[nt]);
                mma_bf16(od[nt], pah[kk], vbl, od[nt]);
                mma_bf16(od[nt], pal[kk], vbh, od[nt]);
            }
        }
        __syncthreads();
    }

    l0 += __shfl_xor_sync(0xffffffffu, l0, 1);
    l0 += __shfl_xor_sync(0xffffffffu, l0, 2);
    l1 += __shfl_xor_sync(0xffffffffu, l1, 1);
    l1 += __shfl_xor_sync(0xffffffffu, l1, 2);
    float i0 = 1.f / l0, i1 = 1.f / l1;
    int b = bh >> 4, h = bh & 15;
    long ob0 = ((long)(b * SD + qt * 64 + r0)) * DD + h * HDIM;
    long ob1 = ob0 + 8L * DD;
    #pragma unroll
    for (int nt = 0; nt < 8; ++nt) {
        int d = nt * 8 + 2 * t;
        __nv_bfloat16 hh, ll;
        split_bf(od[nt][0] * i0, hh, ll); oh_[ob0 + d] = hh;     ol_[ob0 + d] = ll;
        split_bf(od[nt][1] * i0, hh, ll); oh_[ob0 + d + 1] = hh; ol_[ob0 + d + 1] = ll;
        split_bf(od[nt][2] * i1, hh, ll); oh_[ob1 + d] = hh;     ol_[ob1 + d] = ll;
        split_bf(od[nt][3] * i1, hh, ll); oh_[ob1 + d + 1] = hh; ol_[ob1 + d + 1] = ll;
    }
}

// ---------------- SwiGLU elementwise -> bf16 hi/lo (padded layout) ----------
__global__ void k_silu(const float* __restrict__ g, const float* __restrict__ u,
                       __nv_bfloat16* __restrict__ oh, __nv_bfloat16* __restrict__ ol) {
    long i = (long)blockIdx.x * 256 + threadIdx.x;
    if (i < (long)NTOK * MMF) {
        int row = (int)(i / MMF);
        int col = (int)(i - (long)row * MMF);
        float s = g[i];
        float v = (s / (1.f + expf(-s))) * u[i];
        __nv_bfloat16 h, l;
        split_bf(v, h, l);
        oh[(long)row * MP + col] = h;
        ol[(long)row * MP + col] = l;
    }
}

// ---------------- head --------------------------------------------------------
__global__ void __launch_bounds__(256) k_head(const __nv_bfloat16* __restrict__ hh,
                                              const __nv_bfloat16* __restrict__ hl,
                                              const float* __restrict__ W,
                                              const float* __restrict__ bias,
                                              float* __restrict__ out) {
    int bidx = blockIdx.y;
    int col = blockIdx.x * 256 + threadIdx.x;
    __shared__ float sx[DD];
    long roff = (long)(bidx * SD + SD - 1) * DD;
    for (int c = threadIdx.x; c < DD; c += 256)
        sx[c] = __bfloat162float(hh[roff + c]) + __bfloat162float(hl[roff + c]);
    __syncthreads();
    if (col >= VV) return;
    float acc = 0.f;
    #pragma unroll 8
    for (int k = 0; k < DD; ++k) acc += sx[k] * W[(long)k * VV + col];
    out[(long)bidx * VV + col] = acc + bias[col];
}

// ---------------- driver -----------------------------------------------------
extern "C" void kernel_launch(void* const* d_in, const int* in_sizes, int n_in,
                              void* d_out, int out_size) {
    const int*   tokens = (const int*)  d_in[0];
    const float* embed  = (const float*)d_in[1];
    const float* Wqkv   = (const float*)d_in[2];
    const float* bqkv   = (const float*)d_in[3];
    const float* Wout   = (const float*)d_in[4];
    const float* bout   = (const float*)d_in[5];
    const float* ln1    = (const float*)d_in[6];
    const float* ln2    = (const float*)d_in[7];
    const float* Wg     = (const float*)d_in[8];
    const float* bg     = (const float*)d_in[9];
    const float* Wu     = (const float*)d_in[10];
    const float* bu     = (const float*)d_in[11];
    const float* Wd     = (const float*)d_in[12];
    const float* bd     = (const float*)d_in[13];
    const float* lnf    = (const float*)d_in[14];
    const float* Whead  = (const float*)d_in[15];
    const float* bhead  = (const float*)d_in[16];
    float* out = (float*)d_out;

    float *x, *qkv, *gate, *up;
    __nv_bfloat16 *hh, *hl, *ath, *atl, *gth, *gtl;
    __nv_bfloat16 *qh, *ql, *kh, *kl, *vth, *vtl;
    __nv_bfloat16 *wqkvh, *wqkvl, *wouth, *woutl, *wgh, *wgl, *wuh, *wul, *wdh, *wdl;
    cudaGetSymbolAddress((void**)&x,    g_x);
    cudaGetSymbolAddress((void**)&qkv,  g_qkv);
    cudaGetSymbolAddress((void**)&gate, g_gate);
    cudaGetSymbolAddress((void**)&up,   g_up);
    cudaGetSymbolAddress((void**)&hh,   g_h_h);
    cudaGetSymbolAddress((void**)&hl,   g_h_l);
    cudaGetSymbolAddress((void**)&ath,  g_attn_h);
    cudaGetSymbolAddress((void**)&atl,  g_attn_l);
    cudaGetSymbolAddress((void**)&gth,  g_gate_h);
    cudaGetSymbolAddress((void**)&gtl,  g_gate_l);
    cudaGetSymbolAddress((void**)&qh,   g_q_h);
    cudaGetSymbolAddress((void**)&ql,   g_q_l);
    cudaGetSymbolAddress((void**)&kh,   g_k_h);
    cudaGetSymbolAddress((void**)&kl,   g_k_l);
    cudaGetSymbolAddress((void**)&vth,  g_vt_h);
    cudaGetSymbolAddress((void**)&vtl,  g_vt_l);
    cudaGetSymbolAddress((void**)&wqkvh, g_wqkvT_h);
    cudaGetSymbolAddress((void**)&wqkvl, g_wqkvT_l);
    cudaGetSymbolAddress((void**)&wouth, g_woutT_h);
    cudaGetSymbolAddress((void**)&woutl, g_woutT_l);
    cudaGetSymbolAddress((void**)&wgh,  g_wgT_h);
    cudaGetSymbolAddress((void**)&wgl,  g_wgT_l);
    cudaGetSymbolAddress((void**)&wuh,  g_wuT_h);
    cudaGetSymbolAddress((void**)&wul,  g_wuT_l);
    cudaGetSymbolAddress((void**)&wdh,  g_wdT_h);
    cudaGetSymbolAddress((void**)&wdl,  g_wdT_l);

    cudaFuncSetAttribute(k_gemm_bf3, cudaFuncAttributeMaxDynamicSharedMemorySize, 81920);
    const int GSM = 81920;

    // ---- weight split/transpose (batched over layers) ----
    dim3 tb(32, 8);
    k_wsplit<<<dim3(96, 32, LL), tb>>>(Wqkv, wqkvh, wqkvl, DD, 3 * DD, DD,
                                       (long)DD * 3 * DD, (long)3 * DD * DD);
    k_wsplit<<<dim3(32, 32, LL), tb>>>(Wout, wouth, woutl, DD, DD, DD,
                                       (long)DD * DD, (long)DD * DD);
    k_wsplit<<<dim3(86, 32, LL), tb>>>(Wg, wgh, wgl, DD, MMF, DD,
                                       (long)DD * MMF, (long)MMF * DD);
    k_wsplit<<<dim3(86, 32, LL), tb>>>(Wu, wuh, wul, DD, MMF, DD,
                                       (long)DD * MMF, (long)MMF * DD);
    k_wsplit<<<dim3(32, 86, LL), tb>>>(Wd, wdh, wdl, MMF, DD, MP,
                                       (long)MMF * DD, (long)DD * MP);
    k_padzero<<<(NTOK * (MP - MMF) + 255) / 256, 256>>>(gth, gtl);

    k_embed<<<NTOK * DD / 256, 256>>>(tokens, embed, x);

    for (int l = 0; l < LL; ++l) {
        k_rmsnorm<<<NTOK, 256>>>(x, ln1 + (long)l * DD, hh, hl);

        dim3 gq(24, 16);
        k_gemm_bf3<<<gq, 256, GSM>>>(hh, hl,
                                wqkvh + (long)l * 3 * DD * DD, wqkvl + (long)l * 3 * DD * DD,
                                bqkv + (long)l * 3 * DD, nullptr, qkv,
                                NTOK, DD, 3 * DD);

        k_qk_prep<<<NTOK * HH * 32 / 256, 256>>>(qkv, qh, ql, kh, kl);
        k_v_prep<<<dim3(SD / 32, HDIM / 32, BH), dim3(32, 8)>>>(qkv, vth, vtl);

        k_flash<<<dim3(SD / 64, BH), 128>>>(qh, ql, kh, kl, vth, vtl, ath, atl);

        dim3 go(8, 16);
        k_gemm_bf3<<<go, 256, GSM>>>(ath, atl,
                                wouth + (long)l * DD * DD, woutl + (long)l * DD * DD,
                                bout + (long)l * DD, x, x,
                                NTOK, DD, DD);

        k_rmsnorm<<<NTOK, 256>>>(x, ln2 + (long)l * DD, hh, hl);

        dim3 gm(22, 16);
        k_gemm_bf3<<<gm, 256, GSM>>>(hh, hl,
                                wgh + (long)l * MMF * DD, wgl + (long)l * MMF * DD,
                                bg + (long)l * MMF, nullptr, gate,
                                NTOK, DD, MMF);
        k_gemm_bf3<<<gm, 256, GSM>>>(hh, hl,
                                wuh + (long)l * MMF * DD, wul + (long)l * MMF * DD,
                                bu + (long)l * MMF, nullptr, up,
                                NTOK, DD, MMF);

        long nel = (long)NTOK * MMF;
        k_silu<<<(int)((nel + 255) / 256), 256>>>(gate, up, gth, gtl);

        dim3 gd(8, 16);
        k_gemm_bf3<<<gd, 256, GSM>>>(gth, gtl,
                                wdh + (long)l * DD * MP, wdl + (long)l * DD * MP,
                                bd + (long)l * DD, x, x,
                                NTOK, MP, DD);
    }

    k_rmsnorm<<<NTOK, 256>>>(x, lnf, hh, hl);
    dim3 gh((VV + 255) / 256, BD);
    k_head<<<gh, 256>>>(hh, hl, Whead, bhead, out);
}

// round 9
// speedup vs baseline: 4.1718x; 1.1128x over previous
#include <cuda_runtime.h>
#include <cuda_bf16.h>
#include <math.h>

#define BD   2
#define SD   1024
#define DD   1024
#define HH   16
#define HDIM 64
#define LL   4
#define MMF  2730
#define MP   2752
#define VV   32000
#define NTOK (BD*SD)
#define BH   (BD*HH)

// ---------------- scratch (device globals; no allocation allowed) ----------
__device__ float g_x[NTOK*DD];
__device__ float g_qkv[NTOK*3*DD];
__device__ float g_gate[NTOK*MMF];
__device__ float g_up[NTOK*MMF];

__device__ __nv_bfloat16 g_h_h[NTOK*DD],    g_h_l[NTOK*DD];
__device__ __nv_bfloat16 g_attn_h[NTOK*DD], g_attn_l[NTOK*DD];
__device__ __nv_bfloat16 g_gate_h[NTOK*MP], g_gate_l[NTOK*MP];

__device__ __nv_bfloat16 g_q_h[BH*SD*HDIM], g_q_l[BH*SD*HDIM];
__device__ __nv_bfloat16 g_k_h[BH*SD*HDIM], g_k_l[BH*SD*HDIM];
__device__ __nv_bfloat16 g_vt_h[BH*SD*HDIM], g_vt_l[BH*SD*HDIM];

__device__ __nv_bfloat16 g_wqkvT_h[LL*3*DD*DD], g_wqkvT_l[LL*3*DD*DD];
__device__ __nv_bfloat16 g_woutT_h[LL*DD*DD],   g_woutT_l[LL*DD*DD];
__device__ __nv_bfloat16 g_wgT_h[LL*MMF*DD],    g_wgT_l[LL*MMF*DD];
__device__ __nv_bfloat16 g_wuT_h[LL*MMF*DD],    g_wuT_l[LL*MMF*DD];
__device__ __nv_bfloat16 g_wdT_h[(long)LL*DD*MP], g_wdT_l[(long)LL*DD*MP];

// ---------------- helpers ----------------------------------------------------
__device__ __forceinline__ void split_bf(float f, __nv_bfloat16& h, __nv_bfloat16& l) {
    h = __float2bfloat16(f);
    l = __float2bfloat16(f - __bfloat162float(h));
}
__device__ __forceinline__ void pack_split2(float a, float b, unsigned& hi, unsigned& lo) {
    __nv_bfloat162 th, tl;
    th.x = __float2bfloat16(a);
    th.y = __float2bfloat16(b);
    tl.x = __float2bfloat16(a - __bfloat162float(th.x));
    tl.y = __float2bfloat16(b - __bfloat162float(th.y));
    hi = *(unsigned*)&th;
    lo = *(unsigned*)&tl;
}
__device__ __forceinline__ void mma_bf16(float* d, const unsigned* a,
                                         const unsigned* b, const float* c) {
    asm volatile(
        "mma.sync.aligned.m16n8k16.row.col.f32.bf16.bf16.f32 "
        "{%0,%1,%2,%3}, {%4,%5,%6,%7}, {%8,%9}, {%10,%11,%12,%13};"
        : "=f"(d[0]), "=f"(d[1]), "=f"(d[2]), "=f"(d[3])
        : "r"(a[0]), "r"(a[1]), "r"(a[2]), "r"(a[3]),
          "r"(b[0]), "r"(b[1]),
          "f"(c[0]), "f"(c[1]), "f"(c[2]), "f"(c[3]));
}
__device__ __forceinline__ void ldsm4(unsigned& r0, unsigned& r1, unsigned& r2,
                                      unsigned& r3, unsigned addr) {
    asm volatile("ldmatrix.sync.aligned.m8n8.x4.shared.b16 {%0,%1,%2,%3}, [%4];"
                 : "=r"(r0), "=r"(r1), "=r"(r2), "=r"(r3) : "r"(addr));
}
__device__ __forceinline__ void cp16(unsigned saddr, const void* g) {
    asm volatile("cp.async.cg.shared.global [%0], [%1], 16;" :: "r"(saddr), "l"(g));
}
__device__ __forceinline__ void cp_commit() {
    asm volatile("cp.async.commit_group;");
}
template<int N> __device__ __forceinline__ void cp_wait() {
    asm volatile("cp.async.wait_group %0;" :: "n"(N));
}

// ---------------- weight transpose + bf16 split (batched over layers) -------
__global__ void k_wsplit(const float* __restrict__ W,
                         __nv_bfloat16* __restrict__ Th,
                         __nv_bfloat16* __restrict__ Tl,
                         int K, int M, int KP, long wstride, long tstride) {
    W  += (long)blockIdx.z * wstride;
    Th += (long)blockIdx.z * tstride;
    Tl += (long)blockIdx.z * tstride;
    __shared__ float t[32][33];
    int m0 = blockIdx.x * 32, k0 = blockIdx.y * 32;
    int tx = threadIdx.x, ty = threadIdx.y;
    #pragma unroll
    for (int i = 0; i < 32; i += 8) {
        int k = k0 + ty + i, m = m0 + tx;
        t[ty + i][tx] = (k < K && m < M) ? W[(long)k * M + m] : 0.f;
    }
    __syncthreads();
    #pragma unroll
    for (int i = 0; i < 32; i += 8) {
        int m = m0 + ty + i, k = k0 + tx;
        if (m < M && k < KP) {
            __nv_bfloat16 h, l;
            split_bf(t[tx][ty + i], h, l);
            Th[(long)m * KP + k] = h;
            Tl[(long)m * KP + k] = l;
        }
    }
}

__global__ void k_padzero(__nv_bfloat16* __restrict__ gh, __nv_bfloat16* __restrict__ gl) {
    int i = blockIdx.x * 256 + threadIdx.x;
    int row = i / (MP - MMF), col = MMF + i % (MP - MMF);
    if (row < NTOK) {
        gh[(long)row * MP + col] = __float2bfloat16(0.f);
        gl[(long)row * MP + col] = __float2bfloat16(0.f);
    }
}

__global__ void k_embed(const int* __restrict__ tok, const float* __restrict__ emb,
                        float* __restrict__ x) {
    int i = blockIdx.x * 256 + threadIdx.x;
    int n = i >> 10, d = i & 1023;
    x[i] = emb[(long)tok[n] * DD + d];
}

__global__ void __launch_bounds__(256) k_rmsnorm(const float* __restrict__ x,
                                                 const float* __restrict__ w,
                                                 __nv_bfloat16* __restrict__ oh,
                                                 __nv_bfloat16* __restrict__ ol) {
    int row = blockIdx.x;
    const float* xr = x + (long)row * DD;
    float s = 0.f;
    for (int c = threadIdx.x; c < DD; c += 256) { float v = xr[c]; s += v * v; }
    __shared__ float red[8];
    #pragma unroll
    for (int off = 16; off; off >>= 1) s += __shfl_xor_sync(0xffffffffu, s, off);
    if ((threadIdx.x & 31) == 0) red[threadIdx.x >> 5] = s;
    __syncthreads();
    if (threadIdx.x == 0) {
        float t = 0.f;
        #pragma unroll
        for (int i = 0; i < 8; ++i) t += red[i];
        red[0] = t;
    }
    __syncthreads();
    float r = rsqrtf(red[0] * (1.0f / DD) + 1e-6f);
    for (int c = threadIdx.x; c < DD; c += 256) {
        float v = xr[c] * r * w[c];
        __nv_bfloat16 h, l;
        split_bf(v, h, l);
        oh[(long)row * DD + c] = h;
        ol[(long)row * DD + c] = l;
    }
}

// ---------------- bf16 split-3 GEMM: persistent tiles + optional dual -------
// A: N x K (bf16 hi/lo k-major), B: M x K (bf16 hi/lo k-major). K%32==0.
// If B2h_ != null: tiles [per..2*per) use the second (B2,bias2,C2) set.
#define XS 20
#define ASZ (128*XS)
__global__ void __launch_bounds__(256, 2) k_gemm_bf3(
        const __nv_bfloat16* __restrict__ Ah_, const __nv_bfloat16* __restrict__ Al_,
        const __nv_bfloat16* __restrict__ B1h_, const __nv_bfloat16* __restrict__ B1l_,
        const float* __restrict__ bias1, const float* __restrict__ add,
        float* __restrict__ C1,
        const __nv_bfloat16* __restrict__ B2h_, const __nv_bfloat16* __restrict__ B2l_,
        const float* __restrict__ bias2, float* __restrict__ C2,
        int N, int K, int M, int tilesX) {
    extern __shared__ unsigned sm[];
    const unsigned* Ahw = (const unsigned*)Ah_;
    const unsigned* Alw = (const unsigned*)Al_;
    int tid = threadIdx.x, wid = tid >> 5, lane = tid & 31;
    int wm = (wid & 1) * 64, wn = (wid >> 1) * 32;
    int Kw = K >> 1;
    int NC = Kw >> 4;
    unsigned sbase = (unsigned)__cvta_generic_to_shared(sm);
    int tilesY = N >> 7;
    int per = tilesX * tilesY;
    int total = B2h_ ? 2 * per : per;

    int lrow0 = tid >> 2, lw4 = (tid & 3) * 4;
    int lrow1 = lrow0 + 64;
    int rq   = lane & 7;
    int a_r  = rq + ((lane >> 3) & 1) * 8;
    int a_wo = ((lane >> 4) << 2);
    int b_r  = rq + ((lane >> 4) << 3);
    int b_wo = (((lane >> 3) & 1) << 2);

    for (int tI = blockIdx.x; tI < total; tI += gridDim.x) {
        int which = (tI >= per) ? 1 : 0;
        int tt = which ? tI - per : tI;
        int by = tt / tilesX, bx = tt - by * tilesX;
        int br = by * 128, bc = bx * 128;
        const unsigned* Bhw = (const unsigned*)(which ? B2h_ : B1h_);
        const unsigned* Blw = (const unsigned*)(which ? B2l_ : B1l_);
        const float* bias = which ? bias2 : bias1;
        float* C = which ? C2 : C1;

        int brow0 = bc + lrow0; if (brow0 >= M) brow0 = M - 1;
        int brow1 = bc + lrow1; if (brow1 >= M) brow1 = M - 1;
        float acc[4][4][4] = {};

        auto load_chunk = [&](int c, int stage) {
            int kw = c * 16 + lw4;
            unsigned sb = sbase + (unsigned)stage * (4u * ASZ * 4u);
            unsigned d0 = sb + (lrow0 * XS + lw4) * 4u;
            unsigned d1 = sb + (lrow1 * XS + lw4) * 4u;
            long a0 = (long)(br + lrow0) * Kw + kw;
            long a1 = (long)(br + lrow1) * Kw + kw;
            long b0 = (long)brow0 * Kw + kw;
            long b1 = (long)brow1 * Kw + kw;
            cp16(d0,                 Ahw + a0);
            cp16(d1,                 Ahw + a1);
            cp16(d0 + ASZ * 4u,      Alw + a0);
            cp16(d1 + ASZ * 4u,      Alw + a1);
            cp16(d0 + 2u * ASZ * 4u, Bhw + b0);
            cp16(d1 + 2u * ASZ * 4u, Bhw + b1);
            cp16(d0 + 3u * ASZ * 4u, Blw + b0);
            cp16(d1 + 3u * ASZ * 4u, Blw + b1);
            cp_commit();
        };

        load_chunk(0, 0);

        for (int c = 0; c < NC; ++c) {
            if (c + 1 < NC) {
                load_chunk(c + 1, (c + 1) & 1);
                cp_wait<1>();
            } else {
                cp_wait<0>();
            }
            __syncthreads();
            unsigned stg = sbase + (unsigned)(c & 1) * (4u * ASZ * 4u);
            unsigned aAh = stg;
            unsigned aAl = stg + ASZ * 4u;
            unsigned aBh = stg + 2u * ASZ * 4u;
            unsigned aBl = stg + 3u * ASZ * 4u;
            #pragma unroll
            for (int ks = 0; ks < 2; ++ks) {
                int kpb = ks * 8;
                unsigned ah[4][4], al[4][4], bh[4][2], bl[4][2];
                #pragma unroll
                for (int mt = 0; mt < 4; ++mt) {
                    unsigned off = (unsigned)(((wm + mt * 16 + a_r) * XS + kpb + a_wo) * 4);
                    ldsm4(ah[mt][0], ah[mt][1], ah[mt][2], ah[mt][3], aAh + off);
                    ldsm4(al[mt][0], al[mt][1], al[mt][2], al[mt][3], aAl + off);
                }
                #pragma unroll
                for (int p = 0; p < 2; ++p) {
                    unsigned off = (unsigned)(((wn + p * 16 + b_r) * XS + kpb + b_wo) * 4);
                    ldsm4(bh[2*p][0], bh[2*p][1], bh[2*p+1][0], bh[2*p+1][1], aBh + off);
                    ldsm4(bl[2*p][0], bl[2*p][1], bl[2*p+1][0], bl[2*p+1][1], aBl + off);
                }
                #pragma unroll
                for (int mt = 0; mt < 4; ++mt)
                    #pragma unroll
                    for (int nt = 0; nt < 4; ++nt) {
                        mma_bf16(acc[mt][nt], ah[mt], bh[nt], acc[mt][nt]);
                        mma_bf16(acc[mt][nt], ah[mt], bl[nt], acc[mt][nt]);
                        mma_bf16(acc[mt][nt], al[mt], bh[nt], acc[mt][nt]);
                    }
            }
            __syncthreads();
        }

        int g = lane >> 2, t = lane & 3;
        #pragma unroll
        for (int mt = 0; mt < 4; ++mt) {
            int r0 = br + wm + mt * 16 + g;
            #pragma unroll
            for (int nt = 0; nt < 4; ++nt) {
                int c0 = bc + wn + nt * 8 + 2 * t;
                const float* a4 = acc[mt][nt];
                if (c0 < M) {
                    float bv = bias ? bias[c0] : 0.f;
                    float v0 = a4[0] + bv;
                    float v2 = a4[2] + bv;
                    if (add) { v0 += add[(long)r0 * M + c0]; v2 += add[(long)(r0 + 8) * M + c0]; }
                    C[(long)r0 * M + c0] = v0;
                    C[(long)(r0 + 8) * M + c0] = v2;
                }
                if (c0 + 1 < M) {
                    float bv = bias ? bias[c0 + 1] : 0.f;
                    float v1 = a4[1] + bv;
                    float v3 = a4[3] + bv;
                    if (add) { v1 += add[(long)r0 * M + c0 + 1]; v3 += add[(long)(r0 + 8) * M + c0 + 1]; }
                    C[(long)r0 * M + c0 + 1] = v1;
                    C[(long)(r0 + 8) * M + c0 + 1] = v3;
                }
            }
        }
        __syncthreads();
    }
}

// ---------------- q/k: rope + bf16 split into [bh][tok][64] -----------------
__global__ void k_qk_prep(const float* __restrict__ qkv,
                          __nv_bfloat16* __restrict__ qh, __nv_bfloat16* __restrict__ ql,
                          __nv_bfloat16* __restrict__ kh, __nv_bfloat16* __restrict__ kl) {
    int idx = blockIdx.x * 256 + threadIdx.x;
    int j = idx & 31;
    int h = (idx >> 5) & 15;
    int tok = idx >> 9;
    int s = tok & (SD - 1), b = tok >> 10;
    float freq = exp2f(-0.41524101186f * (float)j);   // 10000^(-j/32)
    float ang = (float)s * freq;
    float sn, cs;
    sincosf(ang, &sn, &cs);
    const float* base = qkv + (long)tok * 3 * DD + h * HDIM + 2 * j;
    float qe = base[0], qo = base[1];
    float ke = base[DD], ko = base[DD + 1];
    float q0 = qe * cs - qo * sn, q1 = qe * sn + qo * cs;
    float k0 = ke * cs - ko * sn, k1 = ke * sn + ko * cs;
    long off = ((long)(b * HH + h) * SD + s) * 32 + j;
    unsigned hi, lo;
    pack_split2(q0, q1, hi, lo);
    ((unsigned*)qh)[off] = hi;
    ((unsigned*)ql)[off] = lo;
    pack_split2(k0, k1, hi, lo);
    ((unsigned*)kh)[off] = hi;
    ((unsigned*)kl)[off] = lo;
}

// ---------------- v: transpose + bf16 split into [bh][d][tok] ---------------
__global__ void k_v_prep(const float* __restrict__ qkv,
                         __nv_bfloat16* __restrict__ vh, __nv_bfloat16* __restrict__ vl) {
    __shared__ float ts[32][33];
    int bh = blockIdx.z, b = bh >> 4, h = bh & 15;
    int t0 = blockIdx.x * 32, d0 = blockIdx.y * 32;
    int tx = threadIdx.x, ty = threadIdx.y;
    #pragma unroll
    for (int i = 0; i < 32; i += 8) {
        int tok = t0 + ty + i;
        ts[ty + i][tx] = qkv[((long)(b * SD + tok)) * 3 * DD + 2 * DD + h * HDIM + d0 + tx];
    }
    __syncthreads();
    #pragma unroll
    for (int i = 0; i < 32; i += 8) {
        int d = d0 + ty + i, tok = t0 + tx;
        __nv_bfloat16 hh, ll;
        split_bf(ts[tx][ty + i], hh, ll);
        long off = ((long)bh * HDIM + d) * SD + tok;
        vh[off] = hh;
        vl[off] = ll;
    }
}

// ---------------- flash attention: ldmatrix K/V fragments -------------------
__global__ void __launch_bounds__(128) k_flash(
        const __nv_bfloat16* __restrict__ qh_, const __nv_bfloat16* __restrict__ ql_,
        const __nv_bfloat16* __restrict__ kh_, const __nv_bfloat16* __restrict__ kl_,
        const __nv_bfloat16* __restrict__ vh_, const __nv_bfloat16* __restrict__ vl_,
        __nv_bfloat16* __restrict__ oh_, __nv_bfloat16* __restrict__ ol_) {
    int qt = (int)gridDim.x - 1 - blockIdx.x;
    int bh = blockIdx.y;
    __shared__ unsigned Ksh[64 * 36], Ksl[64 * 36];
    __shared__ unsigned Vsh[64 * 36], Vsl[64 * 36];
    int tid = threadIdx.x, wid = tid >> 5, lane = tid & 31;
    int g = lane >> 2, t = lane & 3;
    const unsigned* qhw = (const unsigned*)qh_;
    const unsigned* qlw = (const unsigned*)ql_;
    const unsigned* khw = (const unsigned*)kh_;
    const unsigned* klw = (const unsigned*)kl_;
    const unsigned* vhw = (const unsigned*)vh_;
    const unsigned* vlw = (const unsigned*)vl_;
    unsigned aKh = (unsigned)__cvta_generic_to_shared(Ksh);
    unsigned aKl = (unsigned)__cvta_generic_to_shared(Ksl);
    unsigned aVh = (unsigned)__cvta_generic_to_shared(Vsh);
    unsigned aVl = (unsigned)__cvta_generic_to_shared(Vsl);
    int rq  = lane & 7;
    int b_r = rq + ((lane >> 4) << 3);
    int b_wo = (((lane >> 3) & 1) << 2);

    long qbase = ((long)bh * SD + qt * 64) * 32;
    #pragma unroll
    for (int it = 0; it < 16; ++it) {
        int idx = tid + it * 128;
        int row = idx >> 5, col = idx & 31;
        Ksh[row * 36 + col] = qhw[qbase + row * 32 + col];
        Ksl[row * 36 + col] = qlw[qbase + row * 32 + col];
    }
    __syncthreads();
    int r0 = wid * 16 + g;
    unsigned qfh[4][4], qfl[4][4];
    #pragma unroll
    for (int kk = 0; kk < 4; ++kk) {
        qfh[kk][0] = Ksh[r0 * 36 + kk * 8 + t];
        qfh[kk][1] = Ksh[(r0 + 8) * 36 + kk * 8 + t];
        qfh[kk][2] = Ksh[r0 * 36 + kk * 8 + t + 4];
        qfh[kk][3] = Ksh[(r0 + 8) * 36 + kk * 8 + t + 4];
        qfl[kk][0] = Ksl[r0 * 36 + kk * 8 + t];
        qfl[kk][1] = Ksl[(r0 + 8) * 36 + kk * 8 + t];
        qfl[kk][2] = Ksl[r0 * 36 + kk * 8 + t + 4];
        qfl[kk][3] = Ksl[(r0 + 8) * 36 + kk * 8 + t + 4];
    }
    __syncthreads();

    float m0 = -INFINITY, m1 = -INFINITY, l0 = 0.f, l1 = 0.f;
    float od[8][4] = {};

    for (int kt = 0; kt <= qt; ++kt) {
        long kb = ((long)bh * SD + kt * 64) * 32;
        long vb = (long)bh * HDIM * (SD / 2) + kt * 32;
        #pragma unroll
        for (int it = 0; it < 16; ++it) {
            int idx = tid + it * 128;
            int row = idx >> 5, col = idx & 31;
            Ksh[row * 36 + col] = khw[kb + row * 32 + col];
            Ksl[row * 36 + col] = klw[kb + row * 32 + col];
            Vsh[row * 36 + col] = vhw[vb + (long)row * (SD / 2) + col];
            Vsl[row * 36 + col] = vlw[vb + (long)row * (SD / 2) + col];
        }
        __syncthreads();

        float sacc[8][4] = {};
        #pragma unroll
        for (int kk = 0; kk < 4; ++kk) {
            unsigned kbh[8][2], kbl[8][2];
            #pragma unroll
            for (int p = 0; p < 4; ++p) {
                unsigned off = (unsigned)(((p * 16 + b_r) * 36 + kk * 8 + b_wo) * 4);
                ldsm4(kbh[2*p][0], kbh[2*p][1], kbh[2*p+1][0], kbh[2*p+1][1], aKh + off);
                ldsm4(kbl[2*p][0], kbl[2*p][1], kbl[2*p+1][0], kbl[2*p+1][1], aKl + off);
            }
            #pragma unroll
            for (int nt = 0; nt < 8; ++nt) {
                mma_bf16(sacc[nt], qfh[kk], kbh[nt], sacc[nt]);
                mma_bf16(sacc[nt], qfh[kk], kbl[nt], sacc[nt]);
                mma_bf16(sacc[nt], qfl[kk], kbh[nt], sacc[nt]);
            }
        }
        #pragma unroll
        for (int nt = 0; nt < 8; ++nt) {
            #pragma unroll
            for (int e = 0; e < 4; ++e) sacc[nt][e] *= 0.125f;
        }
        if (kt == qt) {
            #pragma unroll
            for (int nt = 0; nt < 8; ++nt) {
                int c = nt * 8 + 2 * t;
                if (c > r0)         sacc[nt][0] = -1e30f;
                if (c + 1 > r0)     sacc[nt][1] = -1e30f;
                if (c > r0 + 8)     sacc[nt][2] = -1e30f;
                if (c + 1 > r0 + 8) sacc[nt][3] = -1e30f;
            }
        }
        float tm0 = -1e30f, tm1 = -1e30f;
        #pragma unroll
        for (int nt = 0; nt < 8; ++nt) {
            tm0 = fmaxf(tm0, fmaxf(sacc[nt][0], sacc[nt][1]));
            tm1 = fmaxf(tm1, fmaxf(sacc[nt][2], sacc[nt][3]));
        }
        tm0 = fmaxf(tm0, __shfl_xor_sync(0xffffffffu, tm0, 1));
        tm0 = fmaxf(tm0, __shfl_xor_sync(0xffffffffu, tm0, 2));
        tm1 = fmaxf(tm1, __shfl_xor_sync(0xffffffffu, tm1, 1));
        tm1 = fmaxf(tm1, __shfl_xor_sync(0xffffffffu, tm1, 2));
        float mn0 = fmaxf(m0, tm0), mn1 = fmaxf(m1, tm1);
        float sc0 = __expf(m0 - mn0), sc1 = __expf(m1 - mn1);
        m0 = mn0; m1 = mn1;
        l0 *= sc0; l1 *= sc1;
        #pragma unroll
        for (int nt = 0; nt < 8; ++nt) {
            od[nt][0] *= sc0; od[nt][1] *= sc0;
            od[nt][2] *= sc1; od[nt][3] *= sc1;
        }
        #pragma unroll
        for (int nt = 0; nt < 8; ++nt) {
            sacc[nt][0] = __expf(sacc[nt][0] - m0);
            sacc[nt][1] = __expf(sacc[nt][1] - m0);
            sacc[nt][2] = __expf(sacc[nt][2] - m1);
            sacc[nt][3] = __expf(sacc[nt][3] - m1);
            l0 += sacc[nt][0] + sacc[nt][1];
            l1 += sacc[nt][2] + sacc[nt][3];
        }
        unsigned pah[4][4], pal[4][4];
        #pragma unroll
        for (int kk = 0; kk < 4; ++kk) {
            pack_split2(sacc[2*kk][0],   sacc[2*kk][1],   pah[kk][0], pal[kk][0]);
            pack_split2(sacc[2*kk][2],   sacc[2*kk][3],   pah[kk][1], pal[kk][1]);
            pack_split2(sacc[2*kk+1][0], sacc[2*kk+1][1], pah[kk][2], pal[kk][2]);
            pack_split2(sacc[2*kk+1][2], sacc[2*kk+1][3], pah[kk][3], pal[kk][3]);
        }
        #pragma unroll
        for (int kk = 0; kk < 4; ++kk) {
            unsigned vbh[8][2], vbl[8][2];
            #pragma unroll
            for (int p = 0; p < 4; ++p) {
                unsigned off = (unsigned)(((p * 16 + b_r) * 36 + kk * 8 + b_wo) * 4);
                ldsm4(vbh[2*p][0], vbh[2*p][1], vbh[2*p+1][0], vbh[2*p+1][1], aVh + off);
                ldsm4(vbl[2*p][0], vbl[2*p][1], vbl[2*p+1][0], vbl[2*p+1][1], aVl + off);
            }
            #pragma unroll
            for (int nt = 0; nt < 8; ++nt) {
                mma_bf16(od[nt], pah[kk], vbh[nt], od[nt]);
                mma_bf16(od[nt], pah[kk], vbl[nt], od[nt]);
                mma_bf16(od[nt], pal[kk], vbh[nt], od[nt]);
            }
        }
        __syncthreads();
    }

    l0 += __shfl_xor_sync(0xffffffffu, l0, 1);
    l0 += __shfl_xor_sync(0xffffffffu, l0, 2);
    l1 += __shfl_xor_sync(0xffffffffu, l1, 1);
    l1 += __shfl_xor_sync(0xffffffffu, l1, 2);
    float i0 = 1.f / l0, i1 = 1.f / l1;
    int b = bh >> 4, h = bh & 15;
    long ob0 = ((long)(b * SD + qt * 64 + r0)) * DD + h * HDIM;
    long ob1 = ob0 + 8L * DD;
    #pragma unroll
    for (int nt = 0; nt < 8; ++nt) {
        int d = nt * 8 + 2 * t;
        __nv_bfloat16 hh, ll;
        split_bf(od[nt][0] * i0, hh, ll); oh_[ob0 + d] = hh;     ol_[ob0 + d] = ll;
        split_bf(od[nt][1] * i0, hh, ll); oh_[ob0 + d + 1] = hh; ol_[ob0 + d + 1] = ll;
        split_bf(od[nt][2] * i1, hh, ll); oh_[ob1 + d] = hh;     ol_[ob1 + d] = ll;
        split_bf(od[nt][3] * i1, hh, ll); oh_[ob1 + d + 1] = hh; ol_[ob1 + d + 1] = ll;
    }
}

// ---------------- SwiGLU elementwise -> bf16 hi/lo (padded layout) ----------
__global__ void k_silu(const float* __restrict__ g, const float* __restrict__ u,
                       __nv_bfloat16* __restrict__ oh, __nv_bfloat16* __restrict__ ol) {
    long i = (long)blockIdx.x * 256 + threadIdx.x;
    if (i < (long)NTOK * MMF) {
        int row = (int)(i / MMF);
        int col = (int)(i - (long)row * MMF);
        float s = g[i];
        float v = (s / (1.f + expf(-s))) * u[i];
        __nv_bfloat16 h, l;
        split_bf(v, h, l);
        oh[(long)row * MP + col] = h;
        ol[(long)row * MP + col] = l;
    }
}

// ---------------- head --------------------------------------------------------
__global__ void __launch_bounds__(256) k_head(const __nv_bfloat16* __restrict__ hh,
                                              const __nv_bfloat16* __restrict__ hl,
                                              const float* __restrict__ W,
                                              const float* __restrict__ bias,
                                              float* __restrict__ out) {
    int bidx = blockIdx.y;
    int col = blockIdx.x * 256 + threadIdx.x;
    __shared__ float sx[DD];
    long roff = (long)(bidx * SD + SD - 1) * DD;
    for (int c = threadIdx.x; c < DD; c += 256)
        sx[c] = __bfloat162float(hh[roff + c]) + __bfloat162float(hl[roff + c]);
    __syncthreads();
    if (col >= VV) return;
    float acc = 0.f;
    #pragma unroll 8
    for (int k = 0; k < DD; ++k) acc += sx[k] * W[(long)k * VV + col];
    out[(long)bidx * VV + col] = acc + bias[col];
}

// ---------------- driver -----------------------------------------------------
extern "C" void kernel_launch(void* const* d_in, const int* in_sizes, int n_in,
                              void* d_out, int out_size) {
    const int*   tokens = (const int*)  d_in[0];
    const float* embed  = (const float*)d_in[1];
    const float* Wqkv   = (const float*)d_in[2];
    const float* bqkv   = (const float*)d_in[3];
    const float* Wout   = (const float*)d_in[4];
    const float* bout   = (const float*)d_in[5];
    const float* ln1    = (const float*)d_in[6];
    const float* ln2    = (const float*)d_in[7];
    const float* Wg     = (const float*)d_in[8];
    const float* bg     = (const float*)d_in[9];
    const float* Wu     = (const float*)d_in[10];
    const float* bu     = (const float*)d_in[11];
    const float* Wd     = (const float*)d_in[12];
    const float* bd     = (const float*)d_in[13];
    const float* lnf    = (const float*)d_in[14];
    const float* Whead  = (const float*)d_in[15];
    const float* bhead  = (const float*)d_in[16];
    float* out = (float*)d_out;

    float *x, *qkv, *gate, *up;
    __nv_bfloat16 *hh, *hl, *ath, *atl, *gth, *gtl;
    __nv_bfloat16 *qh, *ql, *kh, *kl, *vth, *vtl;
    __nv_bfloat16 *wqkvh, *wqkvl, *wouth, *woutl, *wgh, *wgl, *wuh, *wul, *wdh, *wdl;
    cudaGetSymbolAddress((void**)&x,    g_x);
    cudaGetSymbolAddress((void**)&qkv,  g_qkv);
    cudaGetSymbolAddress((void**)&gate, g_gate);
    cudaGetSymbolAddress((void**)&up,   g_up);
    cudaGetSymbolAddress((void**)&hh,   g_h_h);
    cudaGetSymbolAddress((void**)&hl,   g_h_l);
    cudaGetSymbolAddress((void**)&ath,  g_attn_h);
    cudaGetSymbolAddress((void**)&atl,  g_attn_l);
    cudaGetSymbolAddress((void**)&gth,  g_gate_h);
    cudaGetSymbolAddress((void**)&gtl,  g_gate_l);
    cudaGetSymbolAddress((void**)&qh,   g_q_h);
    cudaGetSymbolAddress((void**)&ql,   g_q_l);
    cudaGetSymbolAddress((void**)&kh,   g_k_h);
    cudaGetSymbolAddress((void**)&kl,   g_k_l);
    cudaGetSymbolAddress((void**)&vth,  g_vt_h);
    cudaGetSymbolAddress((void**)&vtl,  g_vt_l);
    cudaGetSymbolAddress((void**)&wqkvh, g_wqkvT_h);
    cudaGetSymbolAddress((void**)&wqkvl, g_wqkvT_l);
    cudaGetSymbolAddress((void**)&wouth, g_woutT_h);
    cudaGetSymbolAddress((void**)&woutl, g_woutT_l);
    cudaGetSymbolAddress((void**)&wgh,  g_wgT_h);
    cudaGetSymbolAddress((void**)&wgl,  g_wgT_l);
    cudaGetSymbolAddress((void**)&wuh,  g_wuT_h);
    cudaGetSymbolAddress((void**)&wul,  g_wuT_l);
    cudaGetSymbolAddress((void**)&wdh,  g_wdT_h);
    cudaGetSymbolAddress((void**)&wdl,  g_wdT_l);

    cudaFuncSetAttribute(k_gemm_bf3, cudaFuncAttributeMaxDynamicSharedMemorySize, 81920);
    const int GSM = 81920;
    const int PBLK = 296;   // 148 SMs x 2 CTAs

    // ---- weight split/transpose (batched over layers) ----
    dim3 tb(32, 8);
    k_wsplit<<<dim3(96, 32, LL), tb>>>(Wqkv, wqkvh, wqkvl, DD, 3 * DD, DD,
                                       (long)DD * 3 * DD, (long)3 * DD * DD);
    k_wsplit<<<dim3(32, 32, LL), tb>>>(Wout, wouth, woutl, DD, DD, DD,
                                       (long)DD * DD, (long)DD * DD);
    k_wsplit<<<dim3(86, 32, LL), tb>>>(Wg, wgh, wgl, DD, MMF, DD,
                                       (long)DD * MMF, (long)MMF * DD);
    k_wsplit<<<dim3(86, 32, LL), tb>>>(Wu, wuh, wul, DD, MMF, DD,
                                       (long)DD * MMF, (long)MMF * DD);
    k_wsplit<<<dim3(32, 86, LL), tb>>>(Wd, wdh, wdl, MMF, DD, MP,
                                       (long)MMF * DD, (long)DD * MP);
    k_padzero<<<(NTOK * (MP - MMF) + 255) / 256, 256>>>(gth, gtl);

    k_embed<<<NTOK * DD / 256, 256>>>(tokens, embed, x);

    for (int l = 0; l < LL; ++l) {
        k_rmsnorm<<<NTOK, 256>>>(x, ln1 + (long)l * DD, hh, hl);

        // QKV: 24x16 = 384 tiles
        k_gemm_bf3<<<PBLK, 256, GSM>>>(hh, hl,
                                wqkvh + (long)l * 3 * DD * DD, wqkvl + (long)l * 3 * DD * DD,
                                bqkv + (long)l * 3 * DD, nullptr, qkv,
                                nullptr, nullptr, nullptr, nullptr,
                                NTOK, DD, 3 * DD, 24);

        k_qk_prep<<<NTOK * HH * 32 / 256, 256>>>(qkv, qh, ql, kh, kl);
        k_v_prep<<<dim3(SD / 32, HDIM / 32, BH), dim3(32, 8)>>>(qkv, vth, vtl);

        k_flash<<<dim3(SD / 64, BH), 128>>>(qh, ql, kh, kl, vth, vtl, ath, atl);

        // Wout: 8x16 = 128 tiles
        k_gemm_bf3<<<128, 256, GSM>>>(ath, atl,
                                wouth + (long)l * DD * DD, woutl + (long)l * DD * DD,
                                bout + (long)l * DD, x, x,
                                nullptr, nullptr, nullptr, nullptr,
                                NTOK, DD, DD, 8);

        k_rmsnorm<<<NTOK, 256>>>(x, ln2 + (long)l * DD, hh, hl);

        // Wg + Wu fused dual GEMM: 2 x (22x16) = 704 tiles
        k_gemm_bf3<<<PBLK, 256, GSM>>>(hh, hl,
                                wgh + (long)l * MMF * DD, wgl + (long)l * MMF * DD,
                                bg + (long)l * MMF, nullptr, gate,
                                wuh + (long)l * MMF * DD, wul + (long)l * MMF * DD,
                                bu + (long)l * MMF, up,
                                NTOK, DD, MMF, 22);

        long nel = (long)NTOK * MMF;
        k_silu<<<(int)((nel + 255) / 256), 256>>>(gate, up, gth, gtl);

        // Wd: 8x16 = 128 tiles
        k_gemm_bf3<<<128, 256, GSM>>>(gth, gtl,
                                wdh + (long)l * DD * MP, wdl + (long)l * DD * MP,
                                bd + (long)l * DD, x, x,
                                nullptr, nullptr, nullptr, nullptr,
                                NTOK, MP, DD, 8);
    }

    k_rmsnorm<<<NTOK, 256>>>(x, lnf, hh, hl);
    dim3 gh((VV + 255) / 256, BD);
    k_head<<<gh, 256>>>(hh, hl, Whead, bhead, out);
}

// round 10
// speedup vs baseline: 4.2100x; 1.0092x over previous
#include <cuda_runtime.h>
#include <cuda_bf16.h>
#include <math.h>

#define BD   2
#define SD   1024
#define DD   1024
#define HH   16
#define HDIM 64
#define LL   4
#define MMF  2730
#define MP   2752
#define VV   32000
#define NTOK (BD*SD)
#define BH   (BD*HH)

// ---------------- scratch (device globals; no allocation allowed) ----------
__device__ float g_x[NTOK*DD];
__device__ float g_qkv[NTOK*3*DD];
__device__ float g_gate[NTOK*MMF];
__device__ float g_up[NTOK*MMF];

__device__ __nv_bfloat16 g_h_h[NTOK*DD],    g_h_l[NTOK*DD];
__device__ __nv_bfloat16 g_attn_h[NTOK*DD], g_attn_l[NTOK*DD];
__device__ __nv_bfloat16 g_gate_h[NTOK*MP], g_gate_l[NTOK*MP];

__device__ __nv_bfloat16 g_q_h[BH*SD*HDIM], g_q_l[BH*SD*HDIM];
__device__ __nv_bfloat16 g_k_h[BH*SD*HDIM], g_k_l[BH*SD*HDIM];
__device__ __nv_bfloat16 g_v_h[BH*SD*HDIM], g_v_l[BH*SD*HDIM];

__device__ __nv_bfloat16 g_wqkvT_h[LL*3*DD*DD], g_wqkvT_l[LL*3*DD*DD];
__device__ __nv_bfloat16 g_woutT_h[LL*DD*DD],   g_woutT_l[LL*DD*DD];
__device__ __nv_bfloat16 g_wgT_h[LL*MMF*DD],    g_wgT_l[LL*MMF*DD];
__device__ __nv_bfloat16 g_wuT_h[LL*MMF*DD],    g_wuT_l[LL*MMF*DD];
__device__ __nv_bfloat16 g_wdT_h[(long)LL*DD*MP], g_wdT_l[(long)LL*DD*MP];

// ---------------- helpers ----------------------------------------------------
__device__ __forceinline__ void split_bf(float f, __nv_bfloat16& h, __nv_bfloat16& l) {
    h = __float2bfloat16(f);
    l = __float2bfloat16(f - __bfloat162float(h));
}
__device__ __forceinline__ void pack_split2(float a, float b, unsigned& hi, unsigned& lo) {
    __nv_bfloat162 th, tl;
    th.x = __float2bfloat16(a);
    th.y = __float2bfloat16(b);
    tl.x = __float2bfloat16(a - __bfloat162float(th.x));
    tl.y = __float2bfloat16(b - __bfloat162float(th.y));
    hi = *(unsigned*)&th;
    lo = *(unsigned*)&tl;
}
__device__ __forceinline__ void mma_bf16(float* d, const unsigned* a,
                                         const unsigned* b, const float* c) {
    asm volatile(
        "mma.sync.aligned.m16n8k16.row.col.f32.bf16.bf16.f32 "
        "{%0,%1,%2,%3}, {%4,%5,%6,%7}, {%8,%9}, {%10,%11,%12,%13};"
        : "=f"(d[0]), "=f"(d[1]), "=f"(d[2]), "=f"(d[3])
        : "r"(a[0]), "r"(a[1]), "r"(a[2]), "r"(a[3]),
          "r"(b[0]), "r"(b[1]),
          "f"(c[0]), "f"(c[1]), "f"(c[2]), "f"(c[3]));
}
__device__ __forceinline__ void ldsm4(unsigned& r0, unsigned& r1, unsigned& r2,
                                      unsigned& r3, unsigned addr) {
    asm volatile("ldmatrix.sync.aligned.m8n8.x4.shared.b16 {%0,%1,%2,%3}, [%4];"
                 : "=r"(r0), "=r"(r1), "=r"(r2), "=r"(r3) : "r"(addr));
}
__device__ __forceinline__ void ldsm4t(unsigned& r0, unsigned& r1, unsigned& r2,
                                       unsigned& r3, unsigned addr) {
    asm volatile("ldmatrix.sync.aligned.m8n8.x4.trans.shared.b16 {%0,%1,%2,%3}, [%4];"
                 : "=r"(r0), "=r"(r1), "=r"(r2), "=r"(r3) : "r"(addr));
}
__device__ __forceinline__ void cp16(unsigned saddr, const void* g) {
    asm volatile("cp.async.cg.shared.global [%0], [%1], 16;" :: "r"(saddr), "l"(g));
}
__device__ __forceinline__ void cp_commit() {
    asm volatile("cp.async.commit_group;");
}
template<int N> __device__ __forceinline__ void cp_wait() {
    asm volatile("cp.async.wait_group %0;" :: "n"(N));
}

// ---------------- weight transpose + bf16 split (batched over layers) -------
__global__ void k_wsplit(const float* __restrict__ W,
                         __nv_bfloat16* __restrict__ Th,
                         __nv_bfloat16* __restrict__ Tl,
                         int K, int M, int KP, long wstride, long tstride) {
    W  += (long)blockIdx.z * wstride;
    Th += (long)blockIdx.z * tstride;
    Tl += (long)blockIdx.z * tstride;
    __shared__ float t[32][33];
    int m0 = blockIdx.x * 32, k0 = blockIdx.y * 32;
    int tx = threadIdx.x, ty = threadIdx.y;
    #pragma unroll
    for (int i = 0; i < 32; i += 8) {
        int k = k0 + ty + i, m = m0 + tx;
        t[ty + i][tx] = (k < K && m < M) ? W[(long)k * M + m] : 0.f;
    }
    __syncthreads();
    #pragma unroll
    for (int i = 0; i < 32; i += 8) {
        int m = m0 + ty + i, k = k0 + tx;
        if (m < M && k < KP) {
            __nv_bfloat16 h, l;
            split_bf(t[tx][ty + i], h, l);
            Th[(long)m * KP + k] = h;
            Tl[(long)m * KP + k] = l;
        }
    }
}

__global__ void k_padzero(__nv_bfloat16* __restrict__ gh, __nv_bfloat16* __restrict__ gl) {
    int i = blockIdx.x * 256 + threadIdx.x;
    int row = i / (MP - MMF), col = MMF + i % (MP - MMF);
    if (row < NTOK) {
        gh[(long)row * MP + col] = __float2bfloat16(0.f);
        gl[(long)row * MP + col] = __float2bfloat16(0.f);
    }
}

__global__ void k_embed(const int* __restrict__ tok, const float* __restrict__ emb,
                        float* __restrict__ x) {
    int i = blockIdx.x * 256 + threadIdx.x;
    int n = i >> 10, d = i & 1023;
    x[i] = emb[(long)tok[n] * DD + d];
}

__global__ void __launch_bounds__(256) k_rmsnorm(const float* __restrict__ x,
                                                 const float* __restrict__ w,
                                                 __nv_bfloat16* __restrict__ oh,
                                                 __nv_bfloat16* __restrict__ ol) {
    int row = blockIdx.x;
    const float* xr = x + (long)row * DD;
    float s = 0.f;
    for (int c = threadIdx.x; c < DD; c += 256) { float v = xr[c]; s += v * v; }
    __shared__ float red[8];
    #pragma unroll
    for (int off = 16; off; off >>= 1) s += __shfl_xor_sync(0xffffffffu, s, off);
    if ((threadIdx.x & 31) == 0) red[threadIdx.x >> 5] = s;
    __syncthreads();
    if (threadIdx.x == 0) {
        float t = 0.f;
        #pragma unroll
        for (int i = 0; i < 8; ++i) t += red[i];
        red[0] = t;
    }
    __syncthreads();
    float r = rsqrtf(red[0] * (1.0f / DD) + 1e-6f);
    for (int c = threadIdx.x; c < DD; c += 256) {
        float v = xr[c] * r * w[c];
        __nv_bfloat16 h, l;
        split_bf(v, h, l);
        oh[(long)row * DD + c] = h;
        ol[(long)row * DD + c] = l;
    }
}

// ---------------- bf16 split-3 GEMM: persistent tiles + optional dual -------
#define XS 20
#define ASZ (128*XS)
__global__ void __launch_bounds__(256, 2) k_gemm_bf3(
        const __nv_bfloat16* __restrict__ Ah_, const __nv_bfloat16* __restrict__ Al_,
        const __nv_bfloat16* __restrict__ B1h_, const __nv_bfloat16* __restrict__ B1l_,
        const float* __restrict__ bias1, const float* __restrict__ add,
        float* __restrict__ C1,
        const __nv_bfloat16* __restrict__ B2h_, const __nv_bfloat16* __restrict__ B2l_,
        const float* __restrict__ bias2, float* __restrict__ C2,
        int N, int K, int M, int tilesX) {
    extern __shared__ unsigned sm[];
    const unsigned* Ahw = (const unsigned*)Ah_;
    const unsigned* Alw = (const unsigned*)Al_;
    int tid = threadIdx.x, wid = tid >> 5, lane = tid & 31;
    int wm = (wid & 1) * 64, wn = (wid >> 1) * 32;
    int Kw = K >> 1;
    int NC = Kw >> 4;
    unsigned sbase = (unsigned)__cvta_generic_to_shared(sm);
    int tilesY = N >> 7;
    int per = tilesX * tilesY;
    int total = B2h_ ? 2 * per : per;

    int lrow0 = tid >> 2, lw4 = (tid & 3) * 4;
    int lrow1 = lrow0 + 64;
    int rq   = lane & 7;
    int a_r  = rq + ((lane >> 3) & 1) * 8;
    int a_wo = ((lane >> 4) << 2);
    int b_r  = rq + ((lane >> 4) << 3);
    int b_wo = (((lane >> 3) & 1) << 2);

    for (int tI = blockIdx.x; tI < total; tI += gridDim.x) {
        int which = (tI >= per) ? 1 : 0;
        int tt = which ? tI - per : tI;
        int by = tt / tilesX, bx = tt - by * tilesX;
        int br = by * 128, bc = bx * 128;
        const unsigned* Bhw = (const unsigned*)(which ? B2h_ : B1h_);
        const unsigned* Blw = (const unsigned*)(which ? B2l_ : B1l_);
        const float* bias = which ? bias2 : bias1;
        float* C = which ? C2 : C1;

        int brow0 = bc + lrow0; if (brow0 >= M) brow0 = M - 1;
        int brow1 = bc + lrow1; if (brow1 >= M) brow1 = M - 1;
        float acc[4][4][4] = {};

        auto load_chunk = [&](int c, int stage) {
            int kw = c * 16 + lw4;
            unsigned sb = sbase + (unsigned)stage * (4u * ASZ * 4u);
            unsigned d0 = sb + (lrow0 * XS + lw4) * 4u;
            unsigned d1 = sb + (lrow1 * XS + lw4) * 4u;
            long a0 = (long)(br + lrow0) * Kw + kw;
            long a1 = (long)(br + lrow1) * Kw + kw;
            long b0 = (long)brow0 * Kw + kw;
            long b1 = (long)brow1 * Kw + kw;
            cp16(d0,                 Ahw + a0);
            cp16(d1,                 Ahw + a1);
            cp16(d0 + ASZ * 4u,      Alw + a0);
            cp16(d1 + ASZ * 4u,      Alw + a1);
            cp16(d0 + 2u * ASZ * 4u, Bhw + b0);
            cp16(d1 + 2u * ASZ * 4u, Bhw + b1);
            cp16(d0 + 3u * ASZ * 4u, Blw + b0);
            cp16(d1 + 3u * ASZ * 4u, Blw + b1);
            cp_commit();
        };

        load_chunk(0, 0);

        for (int c = 0; c < NC; ++c) {
            if (c + 1 < NC) {
                load_chunk(c + 1, (c + 1) & 1);
                cp_wait<1>();
            } else {
                cp_wait<0>();
            }
            __syncthreads();
            unsigned stg = sbase + (unsigned)(c & 1) * (4u * ASZ * 4u);
            unsigned aAh = stg;
            unsigned aAl = stg + ASZ * 4u;
            unsigned aBh = stg + 2u * ASZ * 4u;
            unsigned aBl = stg + 3u * ASZ * 4u;
            #pragma unroll
            for (int ks = 0; ks < 2; ++ks) {
                int kpb = ks * 8;
                unsigned ah[4][4], al[4][4], bh[4][2], bl[4][2];
                #pragma unroll
                for (int mt = 0; mt < 4; ++mt) {
                    unsigned off = (unsigned)(((wm + mt * 16 + a_r) * XS + kpb + a_wo) * 4);
                    ldsm4(ah[mt][0], ah[mt][1], ah[mt][2], ah[mt][3], aAh + off);
                    ldsm4(al[mt][0], al[mt][1], al[mt][2], al[mt][3], aAl + off);
                }
                #pragma unroll
                for (int p = 0; p < 2; ++p) {
                    unsigned off = (unsigned)(((wn + p * 16 + b_r) * XS + kpb + b_wo) * 4);
                    ldsm4(bh[2*p][0], bh[2*p][1], bh[2*p+1][0], bh[2*p+1][1], aBh + off);
                    ldsm4(bl[2*p][0], bl[2*p][1], bl[2*p+1][0], bl[2*p+1][1], aBl + off);
                }
                #pragma unroll
                for (int mt = 0; mt < 4; ++mt)
                    #pragma unroll
                    for (int nt = 0; nt < 4; ++nt) {
                        mma_bf16(acc[mt][nt], ah[mt], bh[nt], acc[mt][nt]);
                        mma_bf16(acc[mt][nt], ah[mt], bl[nt], acc[mt][nt]);
                        mma_bf16(acc[mt][nt], al[mt], bh[nt], acc[mt][nt]);
                    }
            }
            __syncthreads();
        }

        int g = lane >> 2, t = lane & 3;
        #pragma unroll
        for (int mt = 0; mt < 4; ++mt) {
            int r0 = br + wm + mt * 16 + g;
            #pragma unroll
            for (int nt = 0; nt < 4; ++nt) {
                int c0 = bc + wn + nt * 8 + 2 * t;
                const float* a4 = acc[mt][nt];
                if (c0 < M) {
                    float bv = bias ? bias[c0] : 0.f;
                    float v0 = a4[0] + bv;
                    float v2 = a4[2] + bv;
                    if (add) { v0 += add[(long)r0 * M + c0]; v2 += add[(long)(r0 + 8) * M + c0]; }
                    C[(long)r0 * M + c0] = v0;
                    C[(long)(r0 + 8) * M + c0] = v2;
                }
                if (c0 + 1 < M) {
                    float bv = bias ? bias[c0 + 1] : 0.f;
                    float v1 = a4[1] + bv;
                    float v3 = a4[3] + bv;
                    if (add) { v1 += add[(long)r0 * M + c0 + 1]; v3 += add[(long)(r0 + 8) * M + c0 + 1]; }
                    C[(long)r0 * M + c0 + 1] = v1;
                    C[(long)(r0 + 8) * M + c0 + 1] = v3;
                }
            }
        }
        __syncthreads();
    }
}

// ---------------- q/k/v prep: rope(q,k) + bf16 split, all [bh][tok][64] -----
__global__ void k_qkv_prep(const float* __restrict__ qkv,
                           __nv_bfloat16* __restrict__ qh, __nv_bfloat16* __restrict__ ql,
                           __nv_bfloat16* __restrict__ kh, __nv_bfloat16* __restrict__ kl,
                           __nv_bfloat16* __restrict__ vh, __nv_bfloat16* __restrict__ vl) {
    int idx = blockIdx.x * 256 + threadIdx.x;
    int j = idx & 31;
    int h = (idx >> 5) & 15;
    int tok = idx >> 9;
    int s = tok & (SD - 1), b = tok >> 10;
    float freq = exp2f(-0.41524101186f * (float)j);
    float ang = (float)s * freq;
    float sn, cs;
    sincosf(ang, &sn, &cs);
    const float* base = qkv + (long)tok * 3 * DD + h * HDIM + 2 * j;
    float qe = base[0], qo = base[1];
    float ke = base[DD], ko = base[DD + 1];
    float ve = base[2 * DD], vo = base[2 * DD + 1];
    float q0 = qe * cs - qo * sn, q1 = qe * sn + qo * cs;
    float k0 = ke * cs - ko * sn, k1 = ke * sn + ko * cs;
    long off = ((long)(b * HH + h) * SD + s) * 32 + j;
    unsigned hi, lo;
    pack_split2(q0, q1, hi, lo);
    ((unsigned*)qh)[off] = hi;
    ((unsigned*)ql)[off] = lo;
    pack_split2(k0, k1, hi, lo);
    ((unsigned*)kh)[off] = hi;
    ((unsigned*)kl)[off] = lo;
    pack_split2(ve, vo, hi, lo);
    ((unsigned*)vh)[off] = hi;
    ((unsigned*)vl)[off] = lo;
}

// ---------------- flash attention: cp.async 2-stage, V via ldmatrix.trans ---
// dyn smem: 2 stages x 4 arrays (Kh,Kl,Vh,Vl) x 64 rows x 36 words
#define FWPA 2304            // words per array (64*36)
#define FSTG (4*FWPA)        // words per stage
__global__ void __launch_bounds__(128) k_flash(
        const __nv_bfloat16* __restrict__ qh_, const __nv_bfloat16* __restrict__ ql_,
        const __nv_bfloat16* __restrict__ kh_, const __nv_bfloat16* __restrict__ kl_,
        const __nv_bfloat16* __restrict__ vh_, const __nv_bfloat16* __restrict__ vl_,
        __nv_bfloat16* __restrict__ oh_, __nv_bfloat16* __restrict__ ol_) {
    extern __shared__ unsigned fsm[];
    int qt = (int)gridDim.x - 1 - blockIdx.x;
    int bh = blockIdx.y;
    int tid = threadIdx.x, wid = tid >> 5, lane = tid & 31;
    int g = lane >> 2, t = lane & 3;
    const unsigned* qhw = (const unsigned*)qh_;
    const unsigned* qlw = (const unsigned*)ql_;
    const unsigned* khw = (const unsigned*)kh_;
    const unsigned* klw = (const unsigned*)kl_;
    const unsigned* vhw = (const unsigned*)vh_;
    const unsigned* vlw = (const unsigned*)vl_;
    unsigned sb = (unsigned)__cvta_generic_to_shared(fsm);

    // K fragment lane map (non-trans)
    int rq  = lane & 7;
    int b_r = rq + ((lane >> 4) << 3);
    int b_wo = (((lane >> 3) & 1) << 2);
    // V fragment lane map (trans)
    int v_r = rq + ((lane >> 3) & 1) * 8;
    int v_c = (lane >> 4) << 2;              // word offset for n-col group

    // ---- stage Q through stage-0 K area, lift to regs ----
    long qbase = ((long)bh * SD + qt * 64) * 32;
    #pragma unroll
    for (int it = 0; it < 16; ++it) {
        int idx = tid + it * 128;
        int row = idx >> 5, col = idx & 31;
        fsm[row * 36 + col]        = qhw[qbase + row * 32 + col];
        fsm[FWPA + row * 36 + col] = qlw[qbase + row * 32 + col];
    }
    __syncthreads();
    int r0 = wid * 16 + g;
    unsigned qfh[4][4], qfl[4][4];
    #pragma unroll
    for (int kk = 0; kk < 4; ++kk) {
        qfh[kk][0] = fsm[r0 * 36 + kk * 8 + t];
        qfh[kk][1] = fsm[(r0 + 8) * 36 + kk * 8 + t];
        qfh[kk][2] = fsm[r0 * 36 + kk * 8 + t + 4];
        qfh[kk][3] = fsm[(r0 + 8) * 36 + kk * 8 + t + 4];
        qfl[kk][0] = fsm[FWPA + r0 * 36 + kk * 8 + t];
        qfl[kk][1] = fsm[FWPA + (r0 + 8) * 36 + kk * 8 + t];
        qfl[kk][2] = fsm[FWPA + r0 * 36 + kk * 8 + t + 4];
        qfl[kk][3] = fsm[FWPA + (r0 + 8) * 36 + kk * 8 + t + 4];
    }
    __syncthreads();

    auto loadKV = [&](int kt, int stg) {
        long kb = ((long)bh * SD + kt * 64) * 32;
        unsigned base = sb + (unsigned)stg * (FSTG * 4u);
        #pragma unroll
        for (int it = 0; it < 4; ++it) {
            int idx = tid + it * 128;
            int row = idx >> 3, wg = (idx & 7) * 4;
            unsigned d = base + (unsigned)(row * 36 + wg) * 4u;
            long gsrc = kb + row * 32 + wg;
            cp16(d,                   khw + gsrc);
            cp16(d + FWPA * 4u,       klw + gsrc);
            cp16(d + 2u * FWPA * 4u,  vhw + gsrc);
            cp16(d + 3u * FWPA * 4u,  vlw + gsrc);
        }
        cp_commit();
    };

    float m0 = -INFINITY, m1 = -INFINITY, l0 = 0.f, l1 = 0.f;
    float od[8][4] = {};

    loadKV(0, 0);
    for (int kt = 0; kt <= qt; ++kt) {
        if (kt + 1 <= qt) {
            loadKV(kt + 1, (kt + 1) & 1);
            cp_wait<1>();
        } else {
            cp_wait<0>();
        }
        __syncthreads();
        unsigned stg = sb + (unsigned)(kt & 1) * (FSTG * 4u);
        unsigned aKh = stg;
        unsigned aKl = stg + FWPA * 4u;
        unsigned aVh = stg + 2u * FWPA * 4u;
        unsigned aVl = stg + 3u * FWPA * 4u;

        // S = Q K^T
        float sacc[8][4] = {};
        #pragma unroll
        for (int kk = 0; kk < 4; ++kk) {
            unsigned kbh[8][2], kbl[8][2];
            #pragma unroll
            for (int p = 0; p < 4; ++p) {
                unsigned off = (unsigned)(((p * 16 + b_r) * 36 + kk * 8 + b_wo) * 4);
                ldsm4(kbh[2*p][0], kbh[2*p][1], kbh[2*p+1][0], kbh[2*p+1][1], aKh + off);
                ldsm4(kbl[2*p][0], kbl[2*p][1], kbl[2*p+1][0], kbl[2*p+1][1], aKl + off);
            }
            #pragma unroll
            for (int nt = 0; nt < 8; ++nt) {
                mma_bf16(sacc[nt], qfh[kk], kbh[nt], sacc[nt]);
                mma_bf16(sacc[nt], qfh[kk], kbl[nt], sacc[nt]);
                mma_bf16(sacc[nt], qfl[kk], kbh[nt], sacc[nt]);
            }
        }
        #pragma unroll
        for (int nt = 0; nt < 8; ++nt) {
            #pragma unroll
            for (int e = 0; e < 4; ++e) sacc[nt][e] *= 0.125f;
        }
        if (kt == qt) {
            #pragma unroll
            for (int nt = 0; nt < 8; ++nt) {
                int c = nt * 8 + 2 * t;
                if (c > r0)         sacc[nt][0] = -1e30f;
                if (c + 1 > r0)     sacc[nt][1] = -1e30f;
                if (c > r0 + 8)     sacc[nt][2] = -1e30f;
                if (c + 1 > r0 + 8) sacc[nt][3] = -1e30f;
            }
        }
        float tm0 = -1e30f, tm1 = -1e30f;
        #pragma unroll
        for (int nt = 0; nt < 8; ++nt) {
            tm0 = fmaxf(tm0, fmaxf(sacc[nt][0], sacc[nt][1]));
            tm1 = fmaxf(tm1, fmaxf(sacc[nt][2], sacc[nt][3]));
        }
        tm0 = fmaxf(tm0, __shfl_xor_sync(0xffffffffu, tm0, 1));
        tm0 = fmaxf(tm0, __shfl_xor_sync(0xffffffffu, tm0, 2));
        tm1 = fmaxf(tm1, __shfl_xor_sync(0xffffffffu, tm1, 1));
        tm1 = fmaxf(tm1, __shfl_xor_sync(0xffffffffu, tm1, 2));
        float mn0 = fmaxf(m0, tm0), mn1 = fmaxf(m1, tm1);
        float sc0 = __expf(m0 - mn0), sc1 = __expf(m1 - mn1);
        m0 = mn0; m1 = mn1;
        l0 *= sc0; l1 *= sc1;
        #pragma unroll
        for (int nt = 0; nt < 8; ++nt) {
            od[nt][0] *= sc0; od[nt][1] *= sc0;
            od[nt][2] *= sc1; od[nt][3] *= sc1;
        }
        #pragma unroll
        for (int nt = 0; nt < 8; ++nt) {
            sacc[nt][0] = __expf(sacc[nt][0] - m0);
            sacc[nt][1] = __expf(sacc[nt][1] - m0);
            sacc[nt][2] = __expf(sacc[nt][2] - m1);
            sacc[nt][3] = __expf(sacc[nt][3] - m1);
            l0 += sacc[nt][0] + sacc[nt][1];
            l1 += sacc[nt][2] + sacc[nt][3];
        }
        unsigned pah[4][4], pal[4][4];
        #pragma unroll
        for (int kk = 0; kk < 4; ++kk) {
            pack_split2(sacc[2*kk][0],   sacc[2*kk][1],   pah[kk][0], pal[kk][0]);
            pack_split2(sacc[2*kk][2],   sacc[2*kk][3],   pah[kk][1], pal[kk][1]);
            pack_split2(sacc[2*kk+1][0], sacc[2*kk+1][1], pah[kk][2], pal[kk][2]);
            pack_split2(sacc[2*kk+1][2], sacc[2*kk+1][3], pah[kk][3], pal[kk][3]);
        }
        // O += P V ; V fragments via ldmatrix.trans from [tok][d] layout
        #pragma unroll
        for (int kk = 0; kk < 4; ++kk) {
            unsigned vbh[8][2], vbl[8][2];
            #pragma unroll
            for (int p = 0; p < 4; ++p) {
                unsigned off = (unsigned)(((kk * 16 + v_r) * 36 + p * 8 + v_c) * 4);
                ldsm4t(vbh[2*p][0], vbh[2*p][1], vbh[2*p+1][0], vbh[2*p+1][1], aVh + off);
                ldsm4t(vbl[2*p][0], vbl[2*p][1], vbl[2*p+1][0], vbl[2*p+1][1], aVl + off);
            }
            #pragma unroll
            for (int nt = 0; nt < 8; ++nt) {
                mma_bf16(od[nt], pah[kk], vbh[nt], od[nt]);
                mma_bf16(od[nt], pah[kk], vbl[nt], od[nt]);
                mma_bf16(od[nt], pal[kk], vbh[nt], od[nt]);
            }
        }
        __syncthreads();
    }

    l0 += __shfl_xor_sync(0xffffffffu, l0, 1);
    l0 += __shfl_xor_sync(0xffffffffu, l0, 2);
    l1 += __shfl_xor_sync(0xffffffffu, l1, 1);
    l1 += __shfl_xor_sync(0xffffffffu, l1, 2);
    float i0 = 1.f / l0, i1 = 1.f / l1;
    int b = bh >> 4, h = bh & 15;
    long ob0 = ((long)(b * SD + qt * 64 + r0)) * DD + h * HDIM;
    long ob1 = ob0 + 8L * DD;
    #pragma unroll
    for (int nt = 0; nt < 8; ++nt) {
        int d = nt * 8 + 2 * t;
        __nv_bfloat16 hh, ll;
        split_bf(od[nt][0] * i0, hh, ll); oh_[ob0 + d] = hh;     ol_[ob0 + d] = ll;
        split_bf(od[nt][1] * i0, hh, ll); oh_[ob0 + d + 1] = hh; ol_[ob0 + d + 1] = ll;
        split_bf(od[nt][2] * i1, hh, ll); oh_[ob1 + d] = hh;     ol_[ob1 + d] = ll;
        split_bf(od[nt][3] * i1, hh, ll); oh_[ob1 + d + 1] = hh; ol_[ob1 + d + 1] = ll;
    }
}

// ---------------- SwiGLU elementwise -> bf16 hi/lo (padded layout) ----------
__global__ void k_silu(const float* __restrict__ g, const float* __restrict__ u,
                       __nv_bfloat16* __restrict__ oh, __nv_bfloat16* __restrict__ ol) {
    long i = (long)blockIdx.x * 256 + threadIdx.x;
    if (i < (long)NTOK * MMF) {
        int row = (int)(i / MMF);
        int col = (int)(i - (long)row * MMF);
        float s = g[i];
        float v = (s / (1.f + expf(-s))) * u[i];
        __nv_bfloat16 h, l;
        split_bf(v, h, l);
        oh[(long)row * MP + col] = h;
        ol[(long)row * MP + col] = l;
    }
}

// ---------------- head --------------------------------------------------------
__global__ void __launch_bounds__(256) k_head(const __nv_bfloat16* __restrict__ hh,
                                              const __nv_bfloat16* __restrict__ hl,
                                              const float* __restrict__ W,
                                              const float* __restrict__ bias,
                                              float* __restrict__ out) {
    int bidx = blockIdx.y;
    int col = blockIdx.x * 256 + threadIdx.x;
    __shared__ float sx[DD];
    long roff = (long)(bidx * SD + SD - 1) * DD;
    for (int c = threadIdx.x; c < DD; c += 256)
        sx[c] = __bfloat162float(hh[roff + c]) + __bfloat162float(hl[roff + c]);
    __syncthreads();
    if (col >= VV) return;
    float acc = 0.f;
    #pragma unroll 8
    for (int k = 0; k < DD; ++k) acc += sx[k] * W[(long)k * VV + col];
    out[(long)bidx * VV + col] = acc + bias[col];
}

// ---------------- driver -----------------------------------------------------
extern "C" void kernel_launch(void* const* d_in, const int* in_sizes, int n_in,
                              void* d_out, int out_size) {
    const int*   tokens = (const int*)  d_in[0];
    const float* embed  = (const float*)d_in[1];
    const float* Wqkv   = (const float*)d_in[2];
    const float* bqkv   = (const float*)d_in[3];
    const float* Wout   = (const float*)d_in[4];
    const float* bout   = (const float*)d_in[5];
    const float* ln1    = (const float*)d_in[6];
    const float* ln2    = (const float*)d_in[7];
    const float* Wg     = (const float*)d_in[8];
    const float* bg     = (const float*)d_in[9];
    const float* Wu     = (const float*)d_in[10];
    const float* bu     = (const float*)d_in[11];
    const float* Wd     = (const float*)d_in[12];
    const float* bd     = (const float*)d_in[13];
    const float* lnf    = (const float*)d_in[14];
    const float* Whead  = (const float*)d_in[15];
    const float* bhead  = (const float*)d_in[16];
    float* out = (float*)d_out;

    float *x, *qkv, *gate, *up;
    __nv_bfloat16 *hh, *hl, *ath, *atl, *gth, *gtl;
    __nv_bfloat16 *qh, *ql, *kh, *kl, *vh, *vl;
    __nv_bfloat16 *wqkvh, *wqkvl, *wouth, *woutl, *wgh, *wgl, *wuh, *wul, *wdh, *wdl;
    cudaGetSymbolAddress((void**)&x,    g_x);
    cudaGetSymbolAddress((void**)&qkv,  g_qkv);
    cudaGetSymbolAddress((void**)&gate, g_gate);
    cudaGetSymbolAddress((void**)&up,   g_up);
    cudaGetSymbolAddress((void**)&hh,   g_h_h);
    cudaGetSymbolAddress((void**)&hl,   g_h_l);
    cudaGetSymbolAddress((void**)&ath,  g_attn_h);
    cudaGetSymbolAddress((void**)&atl,  g_attn_l);
    cudaGetSymbolAddress((void**)&gth,  g_gate_h);
    cudaGetSymbolAddress((void**)&gtl,  g_gate_l);
    cudaGetSymbolAddress((void**)&qh,   g_q_h);
    cudaGetSymbolAddress((void**)&ql,   g_q_l);
    cudaGetSymbolAddress((void**)&kh,   g_k_h);
    cudaGetSymbolAddress((void**)&kl,   g_k_l);
    cudaGetSymbolAddress((void**)&vh,   g_v_h);
    cudaGetSymbolAddress((void**)&vl,   g_v_l);
    cudaGetSymbolAddress((void**)&wqkvh, g_wqkvT_h);
    cudaGetSymbolAddress((void**)&wqkvl, g_wqkvT_l);
    cudaGetSymbolAddress((void**)&wouth, g_woutT_h);
    cudaGetSymbolAddress((void**)&woutl, g_woutT_l);
    cudaGetSymbolAddress((void**)&wgh,  g_wgT_h);
    cudaGetSymbolAddress((void**)&wgl,  g_wgT_l);
    cudaGetSymbolAddress((void**)&wuh,  g_wuT_h);
    cudaGetSymbolAddress((void**)&wul,  g_wuT_l);
    cudaGetSymbolAddress((void**)&wdh,  g_wdT_h);
    cudaGetSymbolAddress((void**)&wdl,  g_wdT_l);

    cudaFuncSetAttribute(k_gemm_bf3, cudaFuncAttributeMaxDynamicSharedMemorySize, 81920);
    cudaFuncSetAttribute(k_flash, cudaFuncAttributeMaxDynamicSharedMemorySize, 2 * FSTG * 4);
    const int GSM = 81920;
    const int FSM = 2 * FSTG * 4;
    const int PBLK = 296;

    // ---- weight split/transpose (batched over layers) ----
    dim3 tb(32, 8);
    k_wsplit<<<dim3(96, 32, LL), tb>>>(Wqkv, wqkvh, wqkvl, DD, 3 * DD, DD,
                                       (long)DD * 3 * DD, (long)3 * DD * DD);
    k_wsplit<<<dim3(32, 32, LL), tb>>>(Wout, wouth, woutl, DD, DD, DD,
                                       (long)DD * DD, (long)DD * DD);
    k_wsplit<<<dim3(86, 32, LL), tb>>>(Wg, wgh, wgl, DD, MMF, DD,
                                       (long)DD * MMF, (long)MMF * DD);
    k_wsplit<<<dim3(86, 32, LL), tb>>>(Wu, wuh, wul, DD, MMF, DD,
                                       (long)DD * MMF, (long)MMF * DD);
    k_wsplit<<<dim3(32, 86, LL), tb>>>(Wd, wdh, wdl, MMF, DD, MP,
                                       (long)MMF * DD, (long)DD * MP);
    k_padzero<<<(NTOK * (MP - MMF) + 255) / 256, 256>>>(gth, gtl);

    k_embed<<<NTOK * DD / 256, 256>>>(tokens, embed, x);

    for (int l = 0; l < LL; ++l) {
        k_rmsnorm<<<NTOK, 256>>>(x, ln1 + (long)l * DD, hh, hl);

        k_gemm_bf3<<<PBLK, 256, GSM>>>(hh, hl,
                                wqkvh + (long)l * 3 * DD * DD, wqkvl + (long)l * 3 * DD * DD,
                                bqkv + (long)l * 3 * DD, nullptr, qkv,
                                nullptr, nullptr, nullptr, nullptr,
                                NTOK, DD, 3 * DD, 24);

        k_qkv_prep<<<NTOK * HH * 32 / 256, 256>>>(qkv, qh, ql, kh, kl, vh, vl);

        k_flash<<<dim3(SD / 64, BH), 128, FSM>>>(qh, ql, kh, kl, vh, vl, ath, atl);

        k_gemm_bf3<<<128, 256, GSM>>>(ath, atl,
                                wouth + (long)l * DD * DD, woutl + (long)l * DD * DD,
                                bout + (long)l * DD, x, x,
                                nullptr, nullptr, nullptr, nullptr,
                                NTOK, DD, DD, 8);

        k_rmsnorm<<<NTOK, 256>>>(x, ln2 + (long)l * DD, hh, hl);

        k_gemm_bf3<<<PBLK, 256, GSM>>>(hh, hl,
                                wgh + (long)l * MMF * DD, wgl + (long)l * MMF * DD,
                                bg + (long)l * MMF, nullptr, gate,
                                wuh + (long)l * MMF * DD, wul + (long)l * MMF * DD,
                                bu + (long)l * MMF, up,
                                NTOK, DD, MMF, 22);

        long nel = (long)NTOK * MMF;
        k_silu<<<(int)((nel + 255) / 256), 256>>>(gate, up, gth, gtl);

        k_gemm_bf3<<<128, 256, GSM>>>(gth, gtl,
                                wdh + (long)l * DD * MP, wdl + (long)l * DD * MP,
                                bd + (long)l * DD, x, x,
                                nullptr, nullptr, nullptr, nullptr,
                                NTOK, MP, DD, 8);
    }

    k_rmsnorm<<<NTOK, 256>>>(x, lnf, hh, hl);
    dim3 gh((VV + 255) / 256, BD);
    k_head<<<gh, 256>>>(hh, hl, Whead, bhead, out);
}

// round 11
// speedup vs baseline: 4.2677x; 1.0137x over previous
#include <cuda_runtime.h>
#include <cuda_bf16.h>
#include <math.h>

#define BD   2
#define SD   1024
#define DD   1024
#define HH   16
#define HDIM 64
#define LL   4
#define MMF  2730
#define MP   2752
#define VV   32000
#define NTOK (BD*SD)
#define BH   (BD*HH)

// ---------------- scratch (device globals; no allocation allowed) ----------
__device__ float g_x[NTOK*DD];
__device__ float g_gate[(long)NTOK*MP];
__device__ float g_up[(long)NTOK*MP];

__device__ __nv_bfloat16 g_h_h[NTOK*DD],    g_h_l[NTOK*DD];
__device__ __nv_bfloat16 g_attn_h[NTOK*DD], g_attn_l[NTOK*DD];
__device__ __nv_bfloat16 g_gate_h[NTOK*MP], g_gate_l[NTOK*MP];

__device__ __nv_bfloat16 g_q_h[BH*SD*HDIM], g_q_l[BH*SD*HDIM];
__device__ __nv_bfloat16 g_k_h[BH*SD*HDIM], g_k_l[BH*SD*HDIM];
__device__ __nv_bfloat16 g_v_h[BH*SD*HDIM], g_v_l[BH*SD*HDIM];

__device__ __nv_bfloat16 g_wqkvT_h[LL*3*DD*DD], g_wqkvT_l[LL*3*DD*DD];
__device__ __nv_bfloat16 g_woutT_h[LL*DD*DD],   g_woutT_l[LL*DD*DD];
__device__ __nv_bfloat16 g_wgT_h[LL*MMF*DD],    g_wgT_l[LL*MMF*DD];
__device__ __nv_bfloat16 g_wuT_h[LL*MMF*DD],    g_wuT_l[LL*MMF*DD];
__device__ __nv_bfloat16 g_wdT_h[(long)LL*DD*MP], g_wdT_l[(long)LL*DD*MP];

// ---------------- helpers ----------------------------------------------------
__device__ __forceinline__ void split_bf(float f, __nv_bfloat16& h, __nv_bfloat16& l) {
    h = __float2bfloat16(f);
    l = __float2bfloat16(f - __bfloat162float(h));
}
__device__ __forceinline__ void pack_split2(float a, float b, unsigned& hi, unsigned& lo) {
    __nv_bfloat162 th, tl;
    th.x = __float2bfloat16(a);
    th.y = __float2bfloat16(b);
    tl.x = __float2bfloat16(a - __bfloat162float(th.x));
    tl.y = __float2bfloat16(b - __bfloat162float(th.y));
    hi = *(unsigned*)&th;
    lo = *(unsigned*)&tl;
}
__device__ __forceinline__ void mma_bf16(float* d, const unsigned* a,
                                         const unsigned* b, const float* c) {
    asm volatile(
        "mma.sync.aligned.m16n8k16.row.col.f32.bf16.bf16.f32 "
        "{%0,%1,%2,%3}, {%4,%5,%6,%7}, {%8,%9}, {%10,%11,%12,%13};"
        : "=f"(d[0]), "=f"(d[1]), "=f"(d[2]), "=f"(d[3])
        : "r"(a[0]), "r"(a[1]), "r"(a[2]), "r"(a[3]),
          "r"(b[0]), "r"(b[1]),
          "f"(c[0]), "f"(c[1]), "f"(c[2]), "f"(c[3]));
}
__device__ __forceinline__ void ldsm4(unsigned& r0, unsigned& r1, unsigned& r2,
                                      unsigned& r3, unsigned addr) {
    asm volatile("ldmatrix.sync.aligned.m8n8.x4.shared.b16 {%0,%1,%2,%3}, [%4];"
                 : "=r"(r0), "=r"(r1), "=r"(r2), "=r"(r3) : "r"(addr));
}
__device__ __forceinline__ void ldsm4t(unsigned& r0, unsigned& r1, unsigned& r2,
                                       unsigned& r3, unsigned addr) {
    asm volatile("ldmatrix.sync.aligned.m8n8.x4.trans.shared.b16 {%0,%1,%2,%3}, [%4];"
                 : "=r"(r0), "=r"(r1), "=r"(r2), "=r"(r3) : "r"(addr));
}
__device__ __forceinline__ void cp16(unsigned saddr, const void* g) {
    asm volatile("cp.async.cg.shared.global [%0], [%1], 16;" :: "r"(saddr), "l"(g));
}
__device__ __forceinline__ void cp_commit() {
    asm volatile("cp.async.commit_group;");
}
template<int N> __device__ __forceinline__ void cp_wait() {
    asm volatile("cp.async.wait_group %0;" :: "n"(N));
}

// ---------------- weight transpose + bf16 split (wide stores) ---------------
// W: K x M fp32 -> Th/Tl: M x KP bf16. Tile: 32 m x 64 k. Block (32,8).
__global__ void k_wsplit(const float* __restrict__ W,
                         __nv_bfloat16* __restrict__ Th,
                         __nv_bfloat16* __restrict__ Tl,
                         int K, int M, int KP, long wstride, long tstride) {
    W  += (long)blockIdx.z * wstride;
    Th += (long)blockIdx.z * tstride;
    Tl += (long)blockIdx.z * tstride;
    __shared__ float t[64][33];
    int m0 = blockIdx.x * 32, k0 = blockIdx.y * 64;
    int tx = threadIdx.x, ty = threadIdx.y;
    #pragma unroll
    for (int i = 0; i < 64; i += 8) {
        int k = k0 + ty + i, m = m0 + tx;
        t[ty + i][tx] = (k < K && m < M) ? W[(long)k * M + m] : 0.f;
    }
    __syncthreads();
    #pragma unroll
    for (int i = 0; i < 32; i += 8) {
        int m = m0 + ty + i, kk = k0 + tx * 2;
        if (m < M && kk < KP) {
            __nv_bfloat16 h0, l0, h1, l1;
            split_bf(t[tx * 2][ty + i], h0, l0);
            split_bf(t[tx * 2 + 1][ty + i], h1, l1);
            __nv_bfloat162 ph; ph.x = h0; ph.y = h1;
            __nv_bfloat162 pl; pl.x = l0; pl.y = l1;
            ((unsigned*)Th)[((long)m * KP + kk) >> 1] = *(unsigned*)&ph;
            ((unsigned*)Tl)[((long)m * KP + kk) >> 1] = *(unsigned*)&pl;
        }
    }
}

__global__ void k_embed(const int* __restrict__ tok, const float* __restrict__ emb,
                        float* __restrict__ x) {
    int i = blockIdx.x * 256 + threadIdx.x;     // NTOK*256 threads
    int n = i >> 8, c4 = (i & 255) * 4;
    *(float4*)(x + (long)n * DD + c4) =
        *(const float4*)(emb + (long)tok[n] * DD + c4);
}

__global__ void __launch_bounds__(256) k_rmsnorm(const float* __restrict__ x,
                                                 const float* __restrict__ w,
                                                 __nv_bfloat16* __restrict__ oh,
                                                 __nv_bfloat16* __restrict__ ol) {
    int row = blockIdx.x;
    int c4 = threadIdx.x * 4;
    float4 xv = *(const float4*)(x + (long)row * DD + c4);
    float s = xv.x * xv.x + xv.y * xv.y + xv.z * xv.z + xv.w * xv.w;
    __shared__ float red[8];
    #pragma unroll
    for (int off = 16; off; off >>= 1) s += __shfl_xor_sync(0xffffffffu, s, off);
    if ((threadIdx.x & 31) == 0) red[threadIdx.x >> 5] = s;
    __syncthreads();
    if (threadIdx.x == 0) {
        float tt = 0.f;
        #pragma unroll
        for (int i = 0; i < 8; ++i) tt += red[i];
        red[0] = tt;
    }
    __syncthreads();
    float r = rsqrtf(red[0] * (1.0f / DD) + 1e-6f);
    float4 wv = *(const float4*)(w + c4);
    unsigned h0, l0, h1, l1;
    pack_split2(xv.x * r * wv.x, xv.y * r * wv.y, h0, l0);
    pack_split2(xv.z * r * wv.z, xv.w * r * wv.w, h1, l1);
    long wi = ((long)row * DD + c4) >> 1;
    ((unsigned*)oh)[wi] = h0;
    ((unsigned*)oh)[wi + 1] = h1;
    ((unsigned*)ol)[wi] = l0;
    ((unsigned*)ol)[wi + 1] = l1;
}

// ---------------- bf16 split-3 GEMM: persistent + dual + qkv-fused epilogue -
#define XS 20
#define ASZ (128*XS)
__global__ void __launch_bounds__(256, 2) k_gemm_bf3(
        const __nv_bfloat16* __restrict__ Ah_, const __nv_bfloat16* __restrict__ Al_,
        const __nv_bfloat16* __restrict__ B1h_, const __nv_bfloat16* __restrict__ B1l_,
        const float* __restrict__ bias1, const float* __restrict__ add,
        float* __restrict__ C1,
        const __nv_bfloat16* __restrict__ B2h_, const __nv_bfloat16* __restrict__ B2l_,
        const float* __restrict__ bias2, float* __restrict__ C2,
        int N, int K, int M, int tilesX, int ldC, int Mstore, int qkv_mode,
        __nv_bfloat16* qh, __nv_bfloat16* ql,
        __nv_bfloat16* kh, __nv_bfloat16* kl,
        __nv_bfloat16* vh, __nv_bfloat16* vl) {
    extern __shared__ unsigned sm[];
    const unsigned* Ahw = (const unsigned*)Ah_;
    const unsigned* Alw = (const unsigned*)Al_;
    int tid = threadIdx.x, wid = tid >> 5, lane = tid & 31;
    int wm = (wid & 1) * 64, wn = (wid >> 1) * 32;
    int Kw = K >> 1;
    int NC = Kw >> 4;
    unsigned sbase = (unsigned)__cvta_generic_to_shared(sm);
    int tilesY = N >> 7;
    int per = tilesX * tilesY;
    int total = B2h_ ? 2 * per : per;

    int lrow0 = tid >> 2, lw4 = (tid & 3) * 4;
    int lrow1 = lrow0 + 64;
    int rq   = lane & 7;
    int a_r  = rq + ((lane >> 3) & 1) * 8;
    int a_wo = ((lane >> 4) << 2);
    int b_r  = rq + ((lane >> 4) << 3);
    int b_wo = (((lane >> 3) & 1) << 2);
    int g = lane >> 2, t = lane & 3;

    for (int tI = blockIdx.x; tI < total; tI += gridDim.x) {
        int which = (tI >= per) ? 1 : 0;
        int tt = which ? tI - per : tI;
        int by = tt / tilesX, bx = tt - by * tilesX;
        int br = by * 128, bc = bx * 128;
        const unsigned* Bhw = (const unsigned*)(which ? B2h_ : B1h_);
        const unsigned* Blw = (const unsigned*)(which ? B2l_ : B1l_);
        const float* bias = which ? bias2 : bias1;
        float* C = which ? C2 : C1;

        int brow0 = bc + lrow0; if (brow0 >= M) brow0 = M - 1;
        int brow1 = bc + lrow1; if (brow1 >= M) brow1 = M - 1;
        float acc[4][4][4] = {};

        auto load_chunk = [&](int c, int stage) {
            int kw = c * 16 + lw4;
            unsigned sb = sbase + (unsigned)stage * (4u * ASZ * 4u);
            unsigned d0 = sb + (lrow0 * XS + lw4) * 4u;
            unsigned d1 = sb + (lrow1 * XS + lw4) * 4u;
            long a0 = (long)(br + lrow0) * Kw + kw;
            long a1 = (long)(br + lrow1) * Kw + kw;
            long b0 = (long)brow0 * Kw + kw;
            long b1 = (long)brow1 * Kw + kw;
            cp16(d0,                 Ahw + a0);
            cp16(d1,                 Ahw + a1);
            cp16(d0 + ASZ * 4u,      Alw + a0);
            cp16(d1 + ASZ * 4u,      Alw + a1);
            cp16(d0 + 2u * ASZ * 4u, Bhw + b0);
            cp16(d1 + 2u * ASZ * 4u, Bhw + b1);
            cp16(d0 + 3u * ASZ * 4u, Blw + b0);
            cp16(d1 + 3u * ASZ * 4u, Blw + b1);
            cp_commit();
        };

        load_chunk(0, 0);

        for (int c = 0; c < NC; ++c) {
            if (c + 1 < NC) {
                load_chunk(c + 1, (c + 1) & 1);
                cp_wait<1>();
            } else {
                cp_wait<0>();
            }
            __syncthreads();
            unsigned stg = sbase + (unsigned)(c & 1) * (4u * ASZ * 4u);
            unsigned aAh = stg;
            unsigned aAl = stg + ASZ * 4u;
            unsigned aBh = stg + 2u * ASZ * 4u;
            unsigned aBl = stg + 3u * ASZ * 4u;
            #pragma unroll
            for (int ks = 0; ks < 2; ++ks) {
                int kpb = ks * 8;
                unsigned ah[4][4], al[4][4], bh[4][2], bl[4][2];
                #pragma unroll
                for (int mt = 0; mt < 4; ++mt) {
                    unsigned off = (unsigned)(((wm + mt * 16 + a_r) * XS + kpb + a_wo) * 4);
                    ldsm4(ah[mt][0], ah[mt][1], ah[mt][2], ah[mt][3], aAh + off);
                    ldsm4(al[mt][0], al[mt][1], al[mt][2], al[mt][3], aAl + off);
                }
                #pragma unroll
                for (int p = 0; p < 2; ++p) {
                    unsigned off = (unsigned)(((wn + p * 16 + b_r) * XS + kpb + b_wo) * 4);
                    ldsm4(bh[2*p][0], bh[2*p][1], bh[2*p+1][0], bh[2*p+1][1], aBh + off);
                    ldsm4(bl[2*p][0], bl[2*p][1], bl[2*p+1][0], bl[2*p+1][1], aBl + off);
                }
                #pragma unroll
                for (int mt = 0; mt < 4; ++mt)
                    #pragma unroll
                    for (int nt = 0; nt < 4; ++nt) {
                        mma_bf16(acc[mt][nt], ah[mt], bh[nt], acc[mt][nt]);
                        mma_bf16(acc[mt][nt], ah[mt], bl[nt], acc[mt][nt]);
                        mma_bf16(acc[mt][nt], al[mt], bh[nt], acc[mt][nt]);
                    }
            }
            __syncthreads();
        }

        if (qkv_mode) {
            // epilogue: rope(q,k) + bf16 split, write [bh][tok][32 words]
            int sec = bc >> 10;                          // tile never straddles
            #pragma unroll
            for (int nt = 0; nt < 4; ++nt) {
                int c0 = bc + wn + nt * 8 + 2 * t;       // even
                int cc = c0 & 1023;
                int h = cc >> 6, j = (cc & 63) >> 1;
                float b0 = bias[c0], b1 = bias[c0 + 1];
                float freq = exp2f(-0.41524101186f * (float)j);
                __nv_bfloat16* oh = (sec == 0) ? qh : (sec == 1) ? kh : vh;
                __nv_bfloat16* ol = (sec == 0) ? ql : (sec == 1) ? kl : vl;
                #pragma unroll
                for (int mt = 0; mt < 4; ++mt) {
                    #pragma unroll
                    for (int rr = 0; rr < 2; ++rr) {
                        int tok = br + wm + mt * 16 + g + rr * 8;
                        float e = acc[mt][nt][rr * 2 + 0] + b0;
                        float o = acc[mt][nt][rr * 2 + 1] + b1;
                        int s = tok & (SD - 1), b = tok >> 10;
                        if (sec < 2) {
                            float sn, cs;
                            sincosf((float)s * freq, &sn, &cs);
                            float e2 = e * cs - o * sn;
                            o = e * sn + o * cs;
                            e = e2;
                        }
                        long off = ((long)(b * HH + h) * SD + s) * 32 + j;
                        unsigned hi, lo;
                        pack_split2(e, o, hi, lo);
                        ((unsigned*)oh)[off] = hi;
                        ((unsigned*)ol)[off] = lo;
                    }
                }
            }
        } else {
            #pragma unroll
            for (int mt = 0; mt < 4; ++mt) {
                int r0 = br + wm + mt * 16 + g;
                #pragma unroll
                for (int nt = 0; nt < 4; ++nt) {
                    int c0 = bc + wn + nt * 8 + 2 * t;
                    const float* a4 = acc[mt][nt];
                    #pragma unroll
                    for (int e = 0; e < 2; ++e) {
                        int cx = c0 + e;
                        if (cx < Mstore) {
                            float v0, v1;
                            if (cx < M) {
                                float bv = bias ? bias[cx] : 0.f;
                                v0 = a4[e] + bv;
                                v1 = a4[2 + e] + bv;
                                if (add) {
                                    v0 += add[(long)r0 * ldC + cx];
                                    v1 += add[(long)(r0 + 8) * ldC + cx];
                                }
                            } else {
                                v0 = 0.f; v1 = 0.f;
                            }
                            C[(long)r0 * ldC + cx] = v0;
                            C[(long)(r0 + 8) * ldC + cx] = v1;
                        }
                    }
                }
            }
        }
        __syncthreads();
    }
}

// ---------------- flash attention (unchanged from R10) ----------------------
#define FWPA 2304
#define FSTG (4*FWPA)
__global__ void __launch_bounds__(128) k_flash(
        const __nv_bfloat16* __restrict__ qh_, const __nv_bfloat16* __restrict__ ql_,
        const __nv_bfloat16* __restrict__ kh_, const __nv_bfloat16* __restrict__ kl_,
        const __nv_bfloat16* __restrict__ vh_, const __nv_bfloat16* __restrict__ vl_,
        __nv_bfloat16* __restrict__ oh_, __nv_bfloat16* __restrict__ ol_) {
    extern __shared__ unsigned fsm[];
    int qt = (int)gridDim.x - 1 - blockIdx.x;
    int bh = blockIdx.y;
    int tid = threadIdx.x, wid = tid >> 5, lane = tid & 31;
    int g = lane >> 2, t = lane & 3;
    const unsigned* qhw = (const unsigned*)qh_;
    const unsigned* qlw = (const unsigned*)ql_;
    const unsigned* khw = (const unsigned*)kh_;
    const unsigned* klw = (const unsigned*)kl_;
    const unsigned* vhw = (const unsigned*)vh_;
    const unsigned* vlw = (const unsigned*)vl_;
    unsigned sb = (unsigned)__cvta_generic_to_shared(fsm);

    int rq  = lane & 7;
    int b_r = rq + ((lane >> 4) << 3);
    int b_wo = (((lane >> 3) & 1) << 2);
    int v_r = rq + ((lane >> 3) & 1) * 8;
    int v_c = (lane >> 4) << 2;

    long qbase = ((long)bh * SD + qt * 64) * 32;
    #pragma unroll
    for (int it = 0; it < 16; ++it) {
        int idx = tid + it * 128;
        int row = idx >> 5, col = idx & 31;
        fsm[row * 36 + col]        = qhw[qbase + row * 32 + col];
        fsm[FWPA + row * 36 + col] = qlw[qbase + row * 32 + col];
    }
    __syncthreads();
    int r0 = wid * 16 + g;
    unsigned qfh[4][4], qfl[4][4];
    #pragma unroll
    for (int kk = 0; kk < 4; ++kk) {
        qfh[kk][0] = fsm[r0 * 36 + kk * 8 + t];
        qfh[kk][1] = fsm[(r0 + 8) * 36 + kk * 8 + t];
        qfh[kk][2] = fsm[r0 * 36 + kk * 8 + t + 4];
        qfh[kk][3] = fsm[(r0 + 8) * 36 + kk * 8 + t + 4];
        qfl[kk][0] = fsm[FWPA + r0 * 36 + kk * 8 + t];
        qfl[kk][1] = fsm[FWPA + (r0 + 8) * 36 + kk * 8 + t];
        qfl[kk][2] = fsm[FWPA + r0 * 36 + kk * 8 + t + 4];
        qfl[kk][3] = fsm[FWPA + (r0 + 8) * 36 + kk * 8 + t + 4];
    }
    __syncthreads();

    auto loadKV = [&](int kt, int stg) {
        long kb = ((long)bh * SD + kt * 64) * 32;
        unsigned base = sb + (unsigned)stg * (FSTG * 4u);
        #pragma unroll
        for (int it = 0; it < 4; ++it) {
            int idx = tid + it * 128;
            int row = idx >> 3, wg = (idx & 7) * 4;
            unsigned d = base + (unsigned)(row * 36 + wg) * 4u;
            long gsrc = kb + row * 32 + wg;
            cp16(d,                   khw + gsrc);
            cp16(d + FWPA * 4u,       klw + gsrc);
            cp16(d + 2u * FWPA * 4u,  vhw + gsrc);
            cp16(d + 3u * FWPA * 4u,  vlw + gsrc);
        }
        cp_commit();
    };

    float m0 = -INFINITY, m1 = -INFINITY, l0 = 0.f, l1 = 0.f;
    float od[8][4] = {};

    loadKV(0, 0);
    for (int kt = 0; kt <= qt; ++kt) {
        if (kt + 1 <= qt) {
            loadKV(kt + 1, (kt + 1) & 1);
            cp_wait<1>();
        } else {
            cp_wait<0>();
        }
        __syncthreads();
        unsigned stg = sb + (unsigned)(kt & 1) * (FSTG * 4u);
        unsigned aKh = stg;
        unsigned aKl = stg + FWPA * 4u;
        unsigned aVh = stg + 2u * FWPA * 4u;
        unsigned aVl = stg + 3u * FWPA * 4u;

        float sacc[8][4] = {};
        #pragma unroll
        for (int kk = 0; kk < 4; ++kk) {
            unsigned kbh[8][2], kbl[8][2];
            #pragma unroll
            for (int p = 0; p < 4; ++p) {
                unsigned off = (unsigned)(((p * 16 + b_r) * 36 + kk * 8 + b_wo) * 4);
                ldsm4(kbh[2*p][0], kbh[2*p][1], kbh[2*p+1][0], kbh[2*p+1][1], aKh + off);
                ldsm4(kbl[2*p][0], kbl[2*p][1], kbl[2*p+1][0], kbl[2*p+1][1], aKl + off);
            }
            #pragma unroll
            for (int nt = 0; nt < 8; ++nt) {
                mma_bf16(sacc[nt], qfh[kk], kbh[nt], sacc[nt]);
                mma_bf16(sacc[nt], qfh[kk], kbl[nt], sacc[nt]);
                mma_bf16(sacc[nt], qfl[kk], kbh[nt], sacc[nt]);
            }
        }
        #pragma unroll
        for (int nt = 0; nt < 8; ++nt) {
            #pragma unroll
            for (int e = 0; e < 4; ++e) sacc[nt][e] *= 0.125f;
        }
        if (kt == qt) {
            #pragma unroll
            for (int nt = 0; nt < 8; ++nt) {
                int c = nt * 8 + 2 * t;
                if (c > r0)         sacc[nt][0] = -1e30f;
                if (c + 1 > r0)     sacc[nt][1] = -1e30f;
                if (c > r0 + 8)     sacc[nt][2] = -1e30f;
                if (c + 1 > r0 + 8) sacc[nt][3] = -1e30f;
            }
        }
        float tm0 = -1e30f, tm1 = -1e30f;
        #pragma unroll
        for (int nt = 0; nt < 8; ++nt) {
            tm0 = fmaxf(tm0, fmaxf(sacc[nt][0], sacc[nt][1]));
            tm1 = fmaxf(tm1, fmaxf(sacc[nt][2], sacc[nt][3]));
        }
        tm0 = fmaxf(tm0, __shfl_xor_sync(0xffffffffu, tm0, 1));
        tm0 = fmaxf(tm0, __shfl_xor_sync(0xffffffffu, tm0, 2));
        tm1 = fmaxf(tm1, __shfl_xor_sync(0xffffffffu, tm1, 1));
        tm1 = fmaxf(tm1, __shfl_xor_sync(0xffffffffu, tm1, 2));
        float mn0 = fmaxf(m0, tm0), mn1 = fmaxf(m1, tm1);
        float sc0 = __expf(m0 - mn0), sc1 = __expf(m1 - mn1);
        m0 = mn0; m1 = mn1;
        l0 *= sc0; l1 *= sc1;
        #pragma unroll
        for (int nt = 0; nt < 8; ++nt) {
            od[nt][0] *= sc0; od[nt][1] *= sc0;
            od[nt][2] *= sc1; od[nt][3] *= sc1;
        }
        #pragma unroll
        for (int nt = 0; nt < 8; ++nt) {
            sacc[nt][0] = __expf(sacc[nt][0] - m0);
            sacc[nt][1] = __expf(sacc[nt][1] - m0);
            sacc[nt][2] = __expf(sacc[nt][2] - m1);
            sacc[nt][3] = __expf(sacc[nt][3] - m1);
            l0 += sacc[nt][0] + sacc[nt][1];
            l1 += sacc[nt][2] + sacc[nt][3];
        }
        unsigned pah[4][4], pal[4][4];
        #pragma unroll
        for (int kk = 0; kk < 4; ++kk) {
            pack_split2(sacc[2*kk][0],   sacc[2*kk][1],   pah[kk][0], pal[kk][0]);
            pack_split2(sacc[2*kk][2],   sacc[2*kk][3],   pah[kk][1], pal[kk][1]);
            pack_split2(sacc[2*kk+1][0], sacc[2*kk+1][1], pah[kk][2], pal[kk][2]);
            pack_split2(sacc[2*kk+1][2], sacc[2*kk+1][3], pah[kk][3], pal[kk][3]);
        }
        #pragma unroll
        for (int kk = 0; kk < 4; ++kk) {
            unsigned vbh[8][2], vbl[8][2];
            #pragma unroll
            for (int p = 0; p < 4; ++p) {
                unsigned off = (unsigned)(((kk * 16 + v_r) * 36 + p * 8 + v_c) * 4);
                ldsm4t(vbh[2*p][0], vbh[2*p][1], vbh[2*p+1][0], vbh[2*p+1][1], aVh + off);
                ldsm4t(vbl[2*p][0], vbl[2*p][1], vbl[2*p+1][0], vbl[2*p+1][1], aVl + off);
            }
            #pragma unroll
            for (int nt = 0; nt < 8; ++nt) {
                mma_bf16(od[nt], pah[kk], vbh[nt], od[nt]);
                mma_bf16(od[nt], pah[kk], vbl[nt], od[nt]);
                mma_bf16(od[nt], pal[kk], vbh[nt], od[nt]);
            }
        }
        __syncthreads();
    }

    l0 += __shfl_xor_sync(0xffffffffu, l0, 1);
    l0 += __shfl_xor_sync(0xffffffffu, l0, 2);
    l1 += __shfl_xor_sync(0xffffffffu, l1, 1);
    l1 += __shfl_xor_sync(0xffffffffu, l1, 2);
    float i0 = 1.f / l0, i1 = 1.f / l1;
    int b = bh >> 4, h = bh & 15;
    long ob0 = ((long)(b * SD + qt * 64 + r0)) * DD + h * HDIM;
    long ob1 = ob0 + 8L * DD;
    #pragma unroll
    for (int nt = 0; nt < 8; ++nt) {
        int d = nt * 8 + 2 * t;
        __nv_bfloat16 hh, ll;
        split_bf(od[nt][0] * i0, hh, ll); oh_[ob0 + d] = hh;     ol_[ob0 + d] = ll;
        split_bf(od[nt][1] * i0, hh, ll); oh_[ob0 + d + 1] = hh; ol_[ob0 + d + 1] = ll;
        split_bf(od[nt][2] * i1, hh, ll); oh_[ob1 + d] = hh;     ol_[ob1 + d] = ll;
        split_bf(od[nt][3] * i1, hh, ll); oh_[ob1 + d + 1] = hh; ol_[ob1 + d + 1] = ll;
    }
}

// ---------------- SwiGLU vectorized (MP-padded fp32 in, split bf16 out) -----
__global__ void k_silu(const float* __restrict__ g, const float* __restrict__ u,
                       __nv_bfloat16* __restrict__ oh, __nv_bfloat16* __restrict__ ol) {
    int idx = blockIdx.x * 256 + threadIdx.x;       // NTOK * (MP/4)
    int row = idx / (MP / 4);
    int c4 = (idx - row * (MP / 4)) * 4;
    long base = (long)row * MP + c4;
    float4 gv = *(const float4*)(g + base);
    float4 uv = *(const float4*)(u + base);
    float v0 = (gv.x / (1.f + expf(-gv.x))) * uv.x;
    float v1 = (gv.y / (1.f + expf(-gv.y))) * uv.y;
    float v2 = (gv.z / (1.f + expf(-gv.z))) * uv.z;
    float v3 = (gv.w / (1.f + expf(-gv.w))) * uv.w;
    unsigned h0, l0, h1, l1;
    pack_split2(v0, v1, h0, l0);
    pack_split2(v2, v3, h1, l1);
    ((unsigned*)oh)[base >> 1] = h0;
    ((unsigned*)oh)[(base >> 1) + 1] = h1;
    ((unsigned*)ol)[base >> 1] = l0;
    ((unsigned*)ol)[(base >> 1) + 1] = l1;
}

// ---------------- head --------------------------------------------------------
__global__ void __launch_bounds__(256) k_head(const __nv_bfloat16* __restrict__ hh,
                                              const __nv_bfloat16* __restrict__ hl,
                                              const float* __restrict__ W,
                                              const float* __restrict__ bias,
                                              float* __restrict__ out) {
    int bidx = blockIdx.y;
    int col = blockIdx.x * 256 + threadIdx.x;
    __shared__ float sx[DD];
    long roff = (long)(bidx * SD + SD - 1) * DD;
    for (int c = threadIdx.x; c < DD; c += 256)
        sx[c] = __bfloat162float(hh[roff + c]) + __bfloat162float(hl[roff + c]);
    __syncthreads();
    if (col >= VV) return;
    float acc = 0.f;
    #pragma unroll 8
    for (int k = 0; k < DD; ++k) acc += sx[k] * W[(long)k * VV + col];
    out[(long)bidx * VV + col] = acc + bias[col];
}

// ---------------- driver -----------------------------------------------------
extern "C" void kernel_launch(void* const* d_in, const int* in_sizes, int n_in,
                              void* d_out, int out_size) {
    const int*   tokens = (const int*)  d_in[0];
    const float* embed  = (const float*)d_in[1];
    const float* Wqkv   = (const float*)d_in[2];
    const float* bqkv   = (const float*)d_in[3];
    const float* Wout   = (const float*)d_in[4];
    const float* bout   = (const float*)d_in[5];
    const float* ln1    = (const float*)d_in[6];
    const float* ln2    = (const float*)d_in[7];
    const float* Wg     = (const float*)d_in[8];
    const float* bg     = (const float*)d_in[9];
    const float* Wu     = (const float*)d_in[10];
    const float* bu     = (const float*)d_in[11];
    const float* Wd     = (const float*)d_in[12];
    const float* bd     = (const float*)d_in[13];
    const float* lnf    = (const float*)d_in[14];
    const float* Whead  = (const float*)d_in[15];
    const float* bhead  = (const float*)d_in[16];
    float* out = (float*)d_out;

    float *x, *gate, *up;
    __nv_bfloat16 *hh, *hl, *ath, *atl, *gth, *gtl;
    __nv_bfloat16 *qh, *ql, *kh, *kl, *vh, *vl;
    __nv_bfloat16 *wqkvh, *wqkvl, *wouth, *woutl, *wgh, *wgl, *wuh, *wul, *wdh, *wdl;
    cudaGetSymbolAddress((void**)&x,    g_x);
    cudaGetSymbolAddress((void**)&gate, g_gate);
    cudaGetSymbolAddress((void**)&up,   g_up);
    cudaGetSymbolAddress((void**)&hh,   g_h_h);
    cudaGetSymbolAddress((void**)&hl,   g_h_l);
    cudaGetSymbolAddress((void**)&ath,  g_attn_h);
    cudaGetSymbolAddress((void**)&atl,  g_attn_l);
    cudaGetSymbolAddress((void**)&gth,  g_gate_h);
    cudaGetSymbolAddress((void**)&gtl,  g_gate_l);
    cudaGetSymbolAddress((void**)&qh,   g_q_h);
    cudaGetSymbolAddress((void**)&ql,   g_q_l);
    cudaGetSymbolAddress((void**)&kh,   g_k_h);
    cudaGetSymbolAddress((void**)&kl,   g_k_l);
    cudaGetSymbolAddress((void**)&vh,   g_v_h);
    cudaGetSymbolAddress((void**)&vl,   g_v_l);
    cudaGetSymbolAddress((void**)&wqkvh, g_wqkvT_h);
    cudaGetSymbolAddress((void**)&wqkvl, g_wqkvT_l);
    cudaGetSymbolAddress((void**)&wouth, g_woutT_h);
    cudaGetSymbolAddress((void**)&woutl, g_woutT_l);
    cudaGetSymbolAddress((void**)&wgh,  g_wgT_h);
    cudaGetSymbolAddress((void**)&wgl,  g_wgT_l);
    cudaGetSymbolAddress((void**)&wuh,  g_wuT_h);
    cudaGetSymbolAddress((void**)&wul,  g_wuT_l);
    cudaGetSymbolAddress((void**)&wdh,  g_wdT_h);
    cudaGetSymbolAddress((void**)&wdl,  g_wdT_l);

    cudaFuncSetAttribute(k_gemm_bf3, cudaFuncAttributeMaxDynamicSharedMemorySize, 81920);
    cudaFuncSetAttribute(k_flash, cudaFuncAttributeMaxDynamicSharedMemorySize, 2 * FSTG * 4);
    const int GSM = 81920;
    const int FSM = 2 * FSTG * 4;
    const int PBLK = 296;

    dim3 tb(32, 8);
    k_wsplit<<<dim3(96, 16, LL), tb>>>(Wqkv, wqkvh, wqkvl, DD, 3 * DD, DD,
                                       (long)DD * 3 * DD, (long)3 * DD * DD);
    k_wsplit<<<dim3(32, 16, LL), tb>>>(Wout, wouth, woutl, DD, DD, DD,
                                       (long)DD * DD, (long)DD * DD);
    k_wsplit<<<dim3(86, 16, LL), tb>>>(Wg, wgh, wgl, DD, MMF, DD,
                                       (long)DD * MMF, (long)MMF * DD);
    k_wsplit<<<dim3(86, 16, LL), tb>>>(Wu, wuh, wul, DD, MMF, DD,
                                       (long)DD * MMF, (long)MMF * DD);
    k_wsplit<<<dim3(32, 43, LL), tb>>>(Wd, wdh, wdl, MMF, DD, MP,
                                       (long)MMF * DD, (long)DD * MP);

    k_embed<<<NTOK, 256>>>(tokens, embed, x);

    for (int l = 0; l < LL; ++l) {
        k_rmsnorm<<<NTOK, 256>>>(x, ln1 + (long)l * DD, hh, hl);

        // QKV with fused rope/split epilogue: 24x16 = 384 tiles
        k_gemm_bf3<<<PBLK, 256, GSM>>>(hh, hl,
                                wqkvh + (long)l * 3 * DD * DD, wqkvl + (long)l * 3 * DD * DD,
                                bqkv + (long)l * 3 * DD, nullptr, nullptr,
                                nullptr, nullptr, nullptr, nullptr,
                                NTOK, DD, 3 * DD, 24, 3 * DD, 3 * DD, 1,
                                qh, ql, kh, kl, vh, vl);

        k_flash<<<dim3(SD / 64, BH), 128, FSM>>>(qh, ql, kh, kl, vh, vl, ath, atl);

        k_gemm_bf3<<<128, 256, GSM>>>(ath, atl,
                                wouth + (long)l * DD * DD, woutl + (long)l * DD * DD,
                                bout + (long)l * DD, x, x,
                                nullptr, nullptr, nullptr, nullptr,
                                NTOK, DD, DD, 8, DD, DD, 0,
                                nullptr, nullptr, nullptr, nullptr, nullptr, nullptr);

        k_rmsnorm<<<NTOK, 256>>>(x, ln2 + (long)l * DD, hh, hl);

        // Wg + Wu dual, MP-padded fp32 out with zero-filled pad
        k_gemm_bf3<<<PBLK, 256, GSM>>>(hh, hl,
                                wgh + (long)l * MMF * DD, wgl + (long)l * MMF * DD,
                                bg + (long)l * MMF, nullptr, gate,
                                wuh + (long)l * MMF * DD, wul + (long)l * MMF * DD,
                                bu + (long)l * MMF, up,
                                NTOK, DD, MMF, 22, MP, MP, 0,
                                nullptr, nullptr, nullptr, nullptr, nullptr, nullptr);

        k_silu<<<NTOK * (MP / 4) / 256, 256>>>(gate, up, gth, gtl);

        k_gemm_bf3<<<128, 256, GSM>>>(gth, gtl,
                                wdh + (long)l * DD * MP, wdl + (long)l * DD * MP,
                                bd + (long)l * DD, x, x,
                                nullptr, nullptr, nullptr, nullptr,
                                NTOK, MP, DD, 8, DD, DD, 0,
                                nullptr, nullptr, nullptr, nullptr, nullptr, nullptr);
    }

    k_rmsnorm<<<NTOK, 256>>>(x, lnf, hh, hl);
    dim3 gh((VV + 255) / 256, BD);
    k_head<<<gh, 256>>>(hh, hl, Whead, bhead, out);
}

// round 12
// speedup vs baseline: 4.3536x; 1.0201x over previous
#include <cuda_runtime.h>
#include <cuda_bf16.h>
#include <math.h>

#define BD   2
#define SD   1024
#define DD   1024
#define HH   16
#define HDIM 64
#define LL   4
#define MMF  2730
#define MP   2752
#define VV   32000
#define NTOK (BD*SD)
#define BH   (BD*HH)

// ---------------- scratch (device globals; no allocation allowed) ----------
__device__ float g_x[NTOK*DD];
__device__ float g_gate[(long)NTOK*MP];     // also reused as split-K partial p0
__device__ float g_up[(long)NTOK*MP];       // also reused as split-K partial p1

__device__ __nv_bfloat16 g_h_h[NTOK*DD],    g_h_l[NTOK*DD];
__device__ __nv_bfloat16 g_attn_h[NTOK*DD], g_attn_l[NTOK*DD];
__device__ __nv_bfloat16 g_gate_h[NTOK*MP], g_gate_l[NTOK*MP];

__device__ __nv_bfloat16 g_q_h[BH*SD*HDIM], g_q_l[BH*SD*HDIM];
__device__ __nv_bfloat16 g_k_h[BH*SD*HDIM], g_k_l[BH*SD*HDIM];
__device__ __nv_bfloat16 g_v_h[BH*SD*HDIM], g_v_l[BH*SD*HDIM];

__device__ __nv_bfloat16 g_wqkvT_h[LL*3*DD*DD], g_wqkvT_l[LL*3*DD*DD];
__device__ __nv_bfloat16 g_woutT_h[LL*DD*DD],   g_woutT_l[LL*DD*DD];
__device__ __nv_bfloat16 g_wgT_h[LL*MMF*DD],    g_wgT_l[LL*MMF*DD];
__device__ __nv_bfloat16 g_wuT_h[LL*MMF*DD],    g_wuT_l[LL*MMF*DD];
__device__ __nv_bfloat16 g_wdT_h[(long)LL*DD*MP], g_wdT_l[(long)LL*DD*MP];

// ---------------- helpers ----------------------------------------------------
__device__ __forceinline__ void split_bf(float f, __nv_bfloat16& h, __nv_bfloat16& l) {
    h = __float2bfloat16(f);
    l = __float2bfloat16(f - __bfloat162float(h));
}
__device__ __forceinline__ void pack_split2(float a, float b, unsigned& hi, unsigned& lo) {
    __nv_bfloat162 th, tl;
    th.x = __float2bfloat16(a);
    th.y = __float2bfloat16(b);
    tl.x = __float2bfloat16(a - __bfloat162float(th.x));
    tl.y = __float2bfloat16(b - __bfloat162float(th.y));
    hi = *(unsigned*)&th;
    lo = *(unsigned*)&tl;
}
__device__ __forceinline__ void mma_bf16(float* d, const unsigned* a,
                                         const unsigned* b, const float* c) {
    asm volatile(
        "mma.sync.aligned.m16n8k16.row.col.f32.bf16.bf16.f32 "
        "{%0,%1,%2,%3}, {%4,%5,%6,%7}, {%8,%9}, {%10,%11,%12,%13};"
        : "=f"(d[0]), "=f"(d[1]), "=f"(d[2]), "=f"(d[3])
        : "r"(a[0]), "r"(a[1]), "r"(a[2]), "r"(a[3]),
          "r"(b[0]), "r"(b[1]),
          "f"(c[0]), "f"(c[1]), "f"(c[2]), "f"(c[3]));
}
__device__ __forceinline__ void ldsm4(unsigned& r0, unsigned& r1, unsigned& r2,
                                      unsigned& r3, unsigned addr) {
    asm volatile("ldmatrix.sync.aligned.m8n8.x4.shared.b16 {%0,%1,%2,%3}, [%4];"
                 : "=r"(r0), "=r"(r1), "=r"(r2), "=r"(r3) : "r"(addr));
}
__device__ __forceinline__ void ldsm4t(unsigned& r0, unsigned& r1, unsigned& r2,
                                       unsigned& r3, unsigned addr) {
    asm volatile("ldmatrix.sync.aligned.m8n8.x4.trans.shared.b16 {%0,%1,%2,%3}, [%4];"
                 : "=r"(r0), "=r"(r1), "=r"(r2), "=r"(r3) : "r"(addr));
}
__device__ __forceinline__ void cp16(unsigned saddr, const void* g) {
    asm volatile("cp.async.cg.shared.global [%0], [%1], 16;" :: "r"(saddr), "l"(g));
}
__device__ __forceinline__ void cp_commit() {
    asm volatile("cp.async.commit_group;");
}
template<int N> __device__ __forceinline__ void cp_wait() {
    asm volatile("cp.async.wait_group %0;" :: "n"(N));
}

// ---------------- weight transpose + bf16 split ------------------------------
__global__ void k_wsplit(const float* __restrict__ W,
                         __nv_bfloat16* __restrict__ Th,
                         __nv_bfloat16* __restrict__ Tl,
                         int K, int M, int KP, long wstride, long tstride) {
    W  += (long)blockIdx.z * wstride;
    Th += (long)blockIdx.z * tstride;
    Tl += (long)blockIdx.z * tstride;
    __shared__ float t[64][33];
    int m0 = blockIdx.x * 32, k0 = blockIdx.y * 64;
    int tx = threadIdx.x, ty = threadIdx.y;
    #pragma unroll
    for (int i = 0; i < 64; i += 8) {
        int k = k0 + ty + i, m = m0 + tx;
        t[ty + i][tx] = (k < K && m < M) ? W[(long)k * M + m] : 0.f;
    }
    __syncthreads();
    #pragma unroll
    for (int i = 0; i < 32; i += 8) {
        int m = m0 + ty + i, kk = k0 + tx * 2;
        if (m < M && kk < KP) {
            __nv_bfloat16 h0, l0, h1, l1;
            split_bf(t[tx * 2][ty + i], h0, l0);
            split_bf(t[tx * 2 + 1][ty + i], h1, l1);
            __nv_bfloat162 ph; ph.x = h0; ph.y = h1;
            __nv_bfloat162 pl; pl.x = l0; pl.y = l1;
            ((unsigned*)Th)[((long)m * KP + kk) >> 1] = *(unsigned*)&ph;
            ((unsigned*)Tl)[((long)m * KP + kk) >> 1] = *(unsigned*)&pl;
        }
    }
}

__global__ void k_embed(const int* __restrict__ tok, const float* __restrict__ emb,
                        float* __restrict__ x) {
    int i = blockIdx.x * 256 + threadIdx.x;
    int n = i >> 8, c4 = (i & 255) * 4;
    *(float4*)(x + (long)n * DD + c4) =
        *(const float4*)(emb + (long)tok[n] * DD + c4);
}

__global__ void __launch_bounds__(256) k_rmsnorm(const float* __restrict__ x,
                                                 const float* __restrict__ w,
                                                 __nv_bfloat16* __restrict__ oh,
                                                 __nv_bfloat16* __restrict__ ol) {
    int row = blockIdx.x;
    int c4 = threadIdx.x * 4;
    float4 xv = *(const float4*)(x + (long)row * DD + c4);
    float s = xv.x * xv.x + xv.y * xv.y + xv.z * xv.z + xv.w * xv.w;
    __shared__ float red[8];
    #pragma unroll
    for (int off = 16; off; off >>= 1) s += __shfl_xor_sync(0xffffffffu, s, off);
    if ((threadIdx.x & 31) == 0) red[threadIdx.x >> 5] = s;
    __syncthreads();
    if (threadIdx.x == 0) {
        float tt = 0.f;
        #pragma unroll
        for (int i = 0; i < 8; ++i) tt += red[i];
        red[0] = tt;
    }
    __syncthreads();
    float r = rsqrtf(red[0] * (1.0f / DD) + 1e-6f);
    float4 wv = *(const float4*)(w + c4);
    unsigned h0, l0, h1, l1;
    pack_split2(xv.x * r * wv.x, xv.y * r * wv.y, h0, l0);
    pack_split2(xv.z * r * wv.z, xv.w * r * wv.w, h1, l1);
    long wi = ((long)row * DD + c4) >> 1;
    ((unsigned*)oh)[wi] = h0;
    ((unsigned*)oh)[wi + 1] = h1;
    ((unsigned*)ol)[wi] = l0;
    ((unsigned*)ol)[wi + 1] = l1;
}

// ---- combine split-K partials + residual + bias, then rmsnorm -> bf16 split -
__global__ void __launch_bounds__(256) k_comb_rms(float* __restrict__ x,
                                                  const float* __restrict__ p0,
                                                  const float* __restrict__ p1,
                                                  const float* __restrict__ bias,
                                                  const float* __restrict__ w,
                                                  __nv_bfloat16* __restrict__ oh,
                                                  __nv_bfloat16* __restrict__ ol) {
    int row = blockIdx.x;
    int c4 = threadIdx.x * 4;
    long base = (long)row * DD + c4;
    float4 xv = *(float4*)(x + base);
    float4 a = *(const float4*)(p0 + base);
    float4 b = *(const float4*)(p1 + base);
    float4 bv = *(const float4*)(bias + c4);
    xv.x += a.x + b.x + bv.x;
    xv.y += a.y + b.y + bv.y;
    xv.z += a.z + b.z + bv.z;
    xv.w += a.w + b.w + bv.w;
    *(float4*)(x + base) = xv;
    float s = xv.x * xv.x + xv.y * xv.y + xv.z * xv.z + xv.w * xv.w;
    __shared__ float red[8];
    #pragma unroll
    for (int off = 16; off; off >>= 1) s += __shfl_xor_sync(0xffffffffu, s, off);
    if ((threadIdx.x & 31) == 0) red[threadIdx.x >> 5] = s;
    __syncthreads();
    if (threadIdx.x == 0) {
        float tt = 0.f;
        #pragma unroll
        for (int i = 0; i < 8; ++i) tt += red[i];
        red[0] = tt;
    }
    __syncthreads();
    float r = rsqrtf(red[0] * (1.0f / DD) + 1e-6f);
    float4 wv = *(const float4*)(w + c4);
    unsigned h0, l0, h1, l1;
    pack_split2(xv.x * r * wv.x, xv.y * r * wv.y, h0, l0);
    pack_split2(xv.z * r * wv.z, xv.w * r * wv.w, h1, l1);
    long wi = base >> 1;
    ((unsigned*)oh)[wi] = h0;
    ((unsigned*)oh)[wi + 1] = h1;
    ((unsigned*)ol)[wi] = l0;
    ((unsigned*)ol)[wi + 1] = l1;
}

// ---------------- bf16 split-3 GEMM: persistent + dual/splitK + qkv epilogue -
#define XS 20
#define ASZ (128*XS)
__global__ void __launch_bounds__(256, 2) k_gemm_bf3(
        const __nv_bfloat16* __restrict__ Ah_, const __nv_bfloat16* __restrict__ Al_,
        const __nv_bfloat16* __restrict__ B1h_, const __nv_bfloat16* __restrict__ B1l_,
        const float* __restrict__ bias1, const float* __restrict__ add,
        float* __restrict__ C1,
        const __nv_bfloat16* __restrict__ B2h_, const __nv_bfloat16* __restrict__ B2l_,
        const float* __restrict__ bias2, float* __restrict__ C2,
        int N, int K, int M, int tilesX, int ldC, int Mstore, int qkv_mode, int ksplit,
        __nv_bfloat16* qh, __nv_bfloat16* ql,
        __nv_bfloat16* kh, __nv_bfloat16* kl,
        __nv_bfloat16* vh, __nv_bfloat16* vl) {
    extern __shared__ unsigned sm[];
    const unsigned* Ahw = (const unsigned*)Ah_;
    const unsigned* Alw = (const unsigned*)Al_;
    int tid = threadIdx.x, wid = tid >> 5, lane = tid & 31;
    int wm = (wid & 1) * 64, wn = (wid >> 1) * 32;
    int Kw = K >> 1;
    int NC = Kw >> 4;
    int NCH = NC / ksplit;
    unsigned sbase = (unsigned)__cvta_generic_to_shared(sm);
    int tilesY = N >> 7;
    int per = tilesX * tilesY;
    int total = per * ((B2h_ || ksplit == 2) ? 2 : 1);

    int lrow0 = tid >> 2, lw4 = (tid & 3) * 4;
    int lrow1 = lrow0 + 64;
    int rq   = lane & 7;
    int a_r  = rq + ((lane >> 3) & 1) * 8;
    int a_wo = ((lane >> 4) << 2);
    int b_r  = rq + ((lane >> 4) << 3);
    int b_wo = (((lane >> 3) & 1) << 2);
    int g = lane >> 2, t = lane & 3;

    for (int tI = blockIdx.x; tI < total; tI += gridDim.x) {
        int sel = (tI >= per) ? 1 : 0;               // dual-B or K-half
        int tt = sel ? tI - per : tI;
        int by = tt / tilesX, bx = tt - by * tilesX;
        int br = by * 128, bc = bx * 128;
        const unsigned* Bhw = (const unsigned*)((B2h_ && sel) ? B2h_ : B1h_);
        const unsigned* Blw = (const unsigned*)((B2l_ && sel) ? B2l_ : B1l_);
        const float* bias = (B2h_ && sel) ? bias2 : bias1;
        float* C = sel ? C2 : C1;
        int c0 = (ksplit == 2 && sel) ? NCH : 0;

        int brow0 = bc + lrow0; if (brow0 >= M) brow0 = M - 1;
        int brow1 = bc + lrow1; if (brow1 >= M) brow1 = M - 1;
        float acc[4][4][4] = {};

        auto load_chunk = [&](int c, int stage) {
            int kw = c * 16 + lw4;
            unsigned sb = sbase + (unsigned)stage * (4u * ASZ * 4u);
            unsigned d0 = sb + (lrow0 * XS + lw4) * 4u;
            unsigned d1 = sb + (lrow1 * XS + lw4) * 4u;
            long a0 = (long)(br + lrow0) * Kw + kw;
            long a1 = (long)(br + lrow1) * Kw + kw;
            long b0 = (long)brow0 * Kw + kw;
            long b1 = (long)brow1 * Kw + kw;
            cp16(d0,                 Ahw + a0);
            cp16(d1,                 Ahw + a1);
            cp16(d0 + ASZ * 4u,      Alw + a0);
            cp16(d1 + ASZ * 4u,      Alw + a1);
            cp16(d0 + 2u * ASZ * 4u, Bhw + b0);
            cp16(d1 + 2u * ASZ * 4u, Bhw + b1);
            cp16(d0 + 3u * ASZ * 4u, Blw + b0);
            cp16(d1 + 3u * ASZ * 4u, Blw + b1);
            cp_commit();
        };

        load_chunk(c0, 0);

        for (int cl = 0; cl < NCH; ++cl) {
            if (cl + 1 < NCH) {
                load_chunk(c0 + cl + 1, (cl + 1) & 1);
                cp_wait<1>();
            } else {
                cp_wait<0>();
            }
            __syncthreads();
            unsigned stg = sbase + (unsigned)(cl & 1) * (4u * ASZ * 4u);
            unsigned aAh = stg;
            unsigned aAl = stg + ASZ * 4u;
            unsigned aBh = stg + 2u * ASZ * 4u;
            unsigned aBl = stg + 3u * ASZ * 4u;
            #pragma unroll
            for (int ks = 0; ks < 2; ++ks) {
                int kpb = ks * 8;
                unsigned ah[4][4], al[4][4], bh[4][2], bl[4][2];
                #pragma unroll
                for (int mt = 0; mt < 4; ++mt) {
                    unsigned off = (unsigned)(((wm + mt * 16 + a_r) * XS + kpb + a_wo) * 4);
                    ldsm4(ah[mt][0], ah[mt][1], ah[mt][2], ah[mt][3], aAh + off);
                    ldsm4(al[mt][0], al[mt][1], al[mt][2], al[mt][3], aAl + off);
                }
                #pragma unroll
                for (int p = 0; p < 2; ++p) {
                    unsigned off = (unsigned)(((wn + p * 16 + b_r) * XS + kpb + b_wo) * 4);
                    ldsm4(bh[2*p][0], bh[2*p][1], bh[2*p+1][0], bh[2*p+1][1], aBh + off);
                    ldsm4(bl[2*p][0], bl[2*p][1], bl[2*p+1][0], bl[2*p+1][1], aBl + off);
                }
                #pragma unroll
                for (int mt = 0; mt < 4; ++mt)
                    #pragma unroll
                    for (int nt = 0; nt < 4; ++nt) {
                        mma_bf16(acc[mt][nt], ah[mt], bh[nt], acc[mt][nt]);
                        mma_bf16(acc[mt][nt], ah[mt], bl[nt], acc[mt][nt]);
                        mma_bf16(acc[mt][nt], al[mt], bh[nt], acc[mt][nt]);
                    }
            }
            __syncthreads();
        }

        if (qkv_mode) {
            int sec = bc >> 10;
            #pragma unroll
            for (int nt = 0; nt < 4; ++nt) {
                int c0x = bc + wn + nt * 8 + 2 * t;
                int cc = c0x & 1023;
                int h = cc >> 6, j = (cc & 63) >> 1;
                float b0 = bias[c0x], b1 = bias[c0x + 1];
                float freq = exp2f(-0.41524101186f * (float)j);
                __nv_bfloat16* oh = (sec == 0) ? qh : (sec == 1) ? kh : vh;
                __nv_bfloat16* ol = (sec == 0) ? ql : (sec == 1) ? kl : vl;
                #pragma unroll
                for (int mt = 0; mt < 4; ++mt) {
                    #pragma unroll
                    for (int rr = 0; rr < 2; ++rr) {
                        int tok = br + wm + mt * 16 + g + rr * 8;
                        float e = acc[mt][nt][rr * 2 + 0] + b0;
                        float o = acc[mt][nt][rr * 2 + 1] + b1;
                        int s = tok & (SD - 1), b = tok >> 10;
                        if (sec < 2) {
                            float sn, cs;
                            sincosf((float)s * freq, &sn, &cs);
                            float e2 = e * cs - o * sn;
                            o = e * sn + o * cs;
                            e = e2;
                        }
                        long off = ((long)(b * HH + h) * SD + s) * 32 + j;
                        unsigned hi, lo;
                        pack_split2(e, o, hi, lo);
                        ((unsigned*)oh)[off] = hi;
                        ((unsigned*)ol)[off] = lo;
                    }
                }
            }
        } else {
            #pragma unroll
            for (int mt = 0; mt < 4; ++mt) {
                int r0 = br + wm + mt * 16 + g;
                #pragma unroll
                for (int nt = 0; nt < 4; ++nt) {
                    int c0x = bc + wn + nt * 8 + 2 * t;
                    const float* a4 = acc[mt][nt];
                    #pragma unroll
                    for (int e = 0; e < 2; ++e) {
                        int cx = c0x + e;
                        if (cx < Mstore) {
                            float v0, v1;
                            if (cx < M) {
                                float bv = bias ? bias[cx] : 0.f;
                                v0 = a4[e] + bv;
                                v1 = a4[2 + e] + bv;
                                if (add) {
                                    v0 += add[(long)r0 * ldC + cx];
                                    v1 += add[(long)(r0 + 8) * ldC + cx];
                                }
                            } else {
                                v0 = 0.f; v1 = 0.f;
                            }
                            C[(long)r0 * ldC + cx] = v0;
                            C[(long)(r0 + 8) * ldC + cx] = v1;
                        }
                    }
                }
            }
        }
        __syncthreads();
    }
}

// ---------------- flash attention (unchanged) -------------------------------
#define FWPA 2304
#define FSTG (4*FWPA)
__global__ void __launch_bounds__(128) k_flash(
        const __nv_bfloat16* __restrict__ qh_, const __nv_bfloat16* __restrict__ ql_,
        const __nv_bfloat16* __restrict__ kh_, const __nv_bfloat16* __restrict__ kl_,
        const __nv_bfloat16* __restrict__ vh_, const __nv_bfloat16* __restrict__ vl_,
        __nv_bfloat16* __restrict__ oh_, __nv_bfloat16* __restrict__ ol_) {
    extern __shared__ unsigned fsm[];
    int qt = (int)gridDim.x - 1 - blockIdx.x;
    int bh = blockIdx.y;
    int tid = threadIdx.x, wid = tid >> 5, lane = tid & 31;
    int g = lane >> 2, t = lane & 3;
    const unsigned* qhw = (const unsigned*)qh_;
    const unsigned* qlw = (const unsigned*)ql_;
    const unsigned* khw = (const unsigned*)kh_;
    const unsigned* klw = (const unsigned*)kl_;
    const unsigned* vhw = (const unsigned*)vh_;
    const unsigned* vlw = (const unsigned*)vl_;
    unsigned sb = (unsigned)__cvta_generic_to_shared(fsm);

    int rq  = lane & 7;
    int b_r = rq + ((lane >> 4) << 3);
    int b_wo = (((lane >> 3) & 1) << 2);
    int v_r = rq + ((lane >> 3) & 1) * 8;
    int v_c = (lane >> 4) << 2;

    long qbase = ((long)bh * SD + qt * 64) * 32;
    #pragma unroll
    for (int it = 0; it < 16; ++it) {
        int idx = tid + it * 128;
        int row = idx >> 5, col = idx & 31;
        fsm[row * 36 + col]        = qhw[qbase + row * 32 + col];
        fsm[FWPA + row * 36 + col] = qlw[qbase + row * 32 + col];
    }
    __syncthreads();
    int r0 = wid * 16 + g;
    unsigned qfh[4][4], qfl[4][4];
    #pragma unroll
    for (int kk = 0; kk < 4; ++kk) {
        qfh[kk][0] = fsm[r0 * 36 + kk * 8 + t];
        qfh[kk][1] = fsm[(r0 + 8) * 36 + kk * 8 + t];
        qfh[kk][2] = fsm[r0 * 36 + kk * 8 + t + 4];
        qfh[kk][3] = fsm[(r0 + 8) * 36 + kk * 8 + t + 4];
        qfl[kk][0] = fsm[FWPA + r0 * 36 + kk * 8 + t];
        qfl[kk][1] = fsm[FWPA + (r0 + 8) * 36 + kk * 8 + t];
        qfl[kk][2] = fsm[FWPA + r0 * 36 + kk * 8 + t + 4];
        qfl[kk][3] = fsm[FWPA + (r0 + 8) * 36 + kk * 8 + t + 4];
    }
    __syncthreads();

    auto loadKV = [&](int kt, int stg) {
        long kb = ((long)bh * SD + kt * 64) * 32;
        unsigned base = sb + (unsigned)stg * (FSTG * 4u);
        #pragma unroll
        for (int it = 0; it < 4; ++it) {
            int idx = tid + it * 128;
            int row = idx >> 3, wg = (idx & 7) * 4;
            unsigned d = base + (unsigned)(row * 36 + wg) * 4u;
            long gsrc = kb + row * 32 + wg;
            cp16(d,                   khw + gsrc);
            cp16(d + FWPA * 4u,       klw + gsrc);
            cp16(d + 2u * FWPA * 4u,  vhw + gsrc);
            cp16(d + 3u * FWPA * 4u,  vlw + gsrc);
        }
        cp_commit();
    };

    float m0 = -INFINITY, m1 = -INFINITY, l0 = 0.f, l1 = 0.f;
    float od[8][4] = {};

    loadKV(0, 0);
    for (int kt = 0; kt <= qt; ++kt) {
        if (kt + 1 <= qt) {
            loadKV(kt + 1, (kt + 1) & 1);
            cp_wait<1>();
        } else {
            cp_wait<0>();
        }
        __syncthreads();
        unsigned stg = sb + (unsigned)(kt & 1) * (FSTG * 4u);
        unsigned aKh = stg;
        unsigned aKl = stg + FWPA * 4u;
        unsigned aVh = stg + 2u * FWPA * 4u;
        unsigned aVl = stg + 3u * FWPA * 4u;

        float sacc[8][4] = {};
        #pragma unroll
        for (int kk = 0; kk < 4; ++kk) {
            unsigned kbh[8][2], kbl[8][2];
            #pragma unroll
            for (int p = 0; p < 4; ++p) {
                unsigned off = (unsigned)(((p * 16 + b_r) * 36 + kk * 8 + b_wo) * 4);
                ldsm4(kbh[2*p][0], kbh[2*p][1], kbh[2*p+1][0], kbh[2*p+1][1], aKh + off);
                ldsm4(kbl[2*p][0], kbl[2*p][1], kbl[2*p+1][0], kbl[2*p+1][1], aKl + off);
            }
            #pragma unroll
            for (int nt = 0; nt < 8; ++nt) {
                mma_bf16(sacc[nt], qfh[kk], kbh[nt], sacc[nt]);
                mma_bf16(sacc[nt], qfh[kk], kbl[nt], sacc[nt]);
                mma_bf16(sacc[nt], qfl[kk], kbh[nt], sacc[nt]);
            }
        }
        #pragma unroll
        for (int nt = 0; nt < 8; ++nt) {
            #pragma unroll
            for (int e = 0; e < 4; ++e) sacc[nt][e] *= 0.125f;
        }
        if (kt == qt) {
            #pragma unroll
            for (int nt = 0; nt < 8; ++nt) {
                int c = nt * 8 + 2 * t;
                if (c > r0)         sacc[nt][0] = -1e30f;
                if (c + 1 > r0)     sacc[nt][1] = -1e30f;
                if (c > r0 + 8)     sacc[nt][2] = -1e30f;
                if (c + 1 > r0 + 8) sacc[nt][3] = -1e30f;
            }
        }
        float tm0 = -1e30f, tm1 = -1e30f;
        #pragma unroll
        for (int nt = 0; nt < 8; ++nt) {
            tm0 = fmaxf(tm0, fmaxf(sacc[nt][0], sacc[nt][1]));
            tm1 = fmaxf(tm1, fmaxf(sacc[nt][2], sacc[nt][3]));
        }
        tm0 = fmaxf(tm0, __shfl_xor_sync(0xffffffffu, tm0, 1));
        tm0 = fmaxf(tm0, __shfl_xor_sync(0xffffffffu, tm0, 2));
        tm1 = fmaxf(tm1, __shfl_xor_sync(0xffffffffu, tm1, 1));
        tm1 = fmaxf(tm1, __shfl_xor_sync(0xffffffffu, tm1, 2));
        float mn0 = fmaxf(m0, tm0), mn1 = fmaxf(m1, tm1);
        float sc0 = __expf(m0 - mn0), sc1 = __expf(m1 - mn1);
        m0 = mn0; m1 = mn1;
        l0 *= sc0; l1 *= sc1;
        #pragma unroll
        for (int nt = 0; nt < 8; ++nt) {
            od[nt][0] *= sc0; od[nt][1] *= sc0;
            od[nt][2] *= sc1; od[nt][3] *= sc1;
        }
        #pragma unroll
        for (int nt = 0; nt < 8; ++nt) {
            sacc[nt][0] = __expf(sacc[nt][0] - m0);
            sacc[nt][1] = __expf(sacc[nt][1] - m0);
            sacc[nt][2] = __expf(sacc[nt][2] - m1);
            sacc[nt][3] = __expf(sacc[nt][3] - m1);
            l0 += sacc[nt][0] + sacc[nt][1];
            l1 += sacc[nt][2] + sacc[nt][3];
        }
        unsigned pah[4][4], pal[4][4];
        #pragma unroll
        for (int kk = 0; kk < 4; ++kk) {
            pack_split2(sacc[2*kk][0],   sacc[2*kk][1],   pah[kk][0], pal[kk][0]);
            pack_split2(sacc[2*kk][2],   sacc[2*kk][3],   pah[kk][1], pal[kk][1]);
            pack_split2(sacc[2*kk+1][0], sacc[2*kk+1][1], pah[kk][2], pal[kk][2]);
            pack_split2(sacc[2*kk+1][2], sacc[2*kk+1][3], pah[kk][3], pal[kk][3]);
        }
        #pragma unroll
        for (int kk = 0; kk < 4; ++kk) {
            unsigned vbh[8][2], vbl[8][2];
            #pragma unroll
            for (int p = 0; p < 4; ++p) {
                unsigned off = (unsigned)(((kk * 16 + v_r) * 36 + p * 8 + v_c) * 4);
                ldsm4t(vbh[2*p][0], vbh[2*p][1], vbh[2*p+1][0], vbh[2*p+1][1], aVh + off);
                ldsm4t(vbl[2*p][0], vbl[2*p][1], vbl[2*p+1][0], vbl[2*p+1][1], aVl + off);
            }
            #pragma unroll
            for (int nt = 0; nt < 8; ++nt) {
                mma_bf16(od[nt], pah[kk], vbh[nt], od[nt]);
                mma_bf16(od[nt], pah[kk], vbl[nt], od[nt]);
                mma_bf16(od[nt], pal[kk], vbh[nt], od[nt]);
            }
        }
        __syncthreads();
    }

    l0 += __shfl_xor_sync(0xffffffffu, l0, 1);
    l0 += __shfl_xor_sync(0xffffffffu, l0, 2);
    l1 += __shfl_xor_sync(0xffffffffu, l1, 1);
    l1 += __shfl_xor_sync(0xffffffffu, l1, 2);
    float i0 = 1.f / l0, i1 = 1.f / l1;
    int b = bh >> 4, h = bh & 15;
    long ob0 = ((long)(b * SD + qt * 64 + r0)) * DD + h * HDIM;
    long ob1 = ob0 + 8L * DD;
    #pragma unroll
    for (int nt = 0; nt < 8; ++nt) {
        int d = nt * 8 + 2 * t;
        __nv_bfloat16 hh, ll;
        split_bf(od[nt][0] * i0, hh, ll); oh_[ob0 + d] = hh;     ol_[ob0 + d] = ll;
        split_bf(od[nt][1] * i0, hh, ll); oh_[ob0 + d + 1] = hh; ol_[ob0 + d + 1] = ll;
        split_bf(od[nt][2] * i1, hh, ll); oh_[ob1 + d] = hh;     ol_[ob1 + d] = ll;
        split_bf(od[nt][3] * i1, hh, ll); oh_[ob1 + d + 1] = hh; ol_[ob1 + d + 1] = ll;
    }
}

// ---------------- SwiGLU vectorized -----------------------------------------
__global__ void k_silu(const float* __restrict__ g, const float* __restrict__ u,
                       __nv_bfloat16* __restrict__ oh, __nv_bfloat16* __restrict__ ol) {
    int idx = blockIdx.x * 256 + threadIdx.x;
    int row = idx / (MP / 4);
    int c4 = (idx - row * (MP / 4)) * 4;
    long base = (long)row * MP + c4;
    float4 gv = *(const float4*)(g + base);
    float4 uv = *(const float4*)(u + base);
    float v0 = (gv.x / (1.f + expf(-gv.x))) * uv.x;
    float v1 = (gv.y / (1.f + expf(-gv.y))) * uv.y;
    float v2 = (gv.z / (1.f + expf(-gv.z))) * uv.z;
    float v3 = (gv.w / (1.f + expf(-gv.w))) * uv.w;
    unsigned h0, l0, h1, l1;
    pack_split2(v0, v1, h0, l0);
    pack_split2(v2, v3, h1, l1);
    ((unsigned*)oh)[base >> 1] = h0;
    ((unsigned*)oh)[(base >> 1) + 1] = h1;
    ((unsigned*)ol)[base >> 1] = l0;
    ((unsigned*)ol)[(base >> 1) + 1] = l1;
}

// ---------------- head --------------------------------------------------------
__global__ void __launch_bounds__(256) k_head(const __nv_bfloat16* __restrict__ hh,
                                              const __nv_bfloat16* __restrict__ hl,
                                              const float* __restrict__ W,
                                              const float* __restrict__ bias,
                                              float* __restrict__ out) {
    int bidx = blockIdx.y;
    int col = blockIdx.x * 256 + threadIdx.x;
    __shared__ float sx[DD];
    long roff = (long)(bidx * SD + SD - 1) * DD;
    for (int c = threadIdx.x; c < DD; c += 256)
        sx[c] = __bfloat162float(hh[roff + c]) + __bfloat162float(hl[roff + c]);
    __syncthreads();
    if (col >= VV) return;
    float acc = 0.f;
    #pragma unroll 8
    for (int k = 0; k < DD; ++k) acc += sx[k] * W[(long)k * VV + col];
    out[(long)bidx * VV + col] = acc + bias[col];
}

// ---------------- driver -----------------------------------------------------
extern "C" void kernel_launch(void* const* d_in, const int* in_sizes, int n_in,
                              void* d_out, int out_size) {
    const int*   tokens = (const int*)  d_in[0];
    const float* embed  = (const float*)d_in[1];
    const float* Wqkv   = (const float*)d_in[2];
    const float* bqkv   = (const float*)d_in[3];
    const float* Wout   = (const float*)d_in[4];
    const float* bout   = (const float*)d_in[5];
    const float* ln1    = (const float*)d_in[6];
    const float* ln2    = (const float*)d_in[7];
    const float* Wg     = (const float*)d_in[8];
    const float* bg     = (const float*)d_in[9];
    const float* Wu     = (const float*)d_in[10];
    const float* bu     = (const float*)d_in[11];
    const float* Wd     = (const float*)d_in[12];
    const float* bd     = (const float*)d_in[13];
    const float* lnf    = (const float*)d_in[14];
    const float* Whead  = (const float*)d_in[15];
    const float* bhead  = (const float*)d_in[16];
    float* out = (float*)d_out;

    float *x, *gate, *up;
    __nv_bfloat16 *hh, *hl, *ath, *atl, *gth, *gtl;
    __nv_bfloat16 *qh, *ql, *kh, *kl, *vh, *vl;
    __nv_bfloat16 *wqkvh, *wqkvl, *wouth, *woutl, *wgh, *wgl, *wuh, *wul, *wdh, *wdl;
    cudaGetSymbolAddress((void**)&x,    g_x);
    cudaGetSymbolAddress((void**)&gate, g_gate);
    cudaGetSymbolAddress((void**)&up,   g_up);
    cudaGetSymbolAddress((void**)&hh,   g_h_h);
    cudaGetSymbolAddress((void**)&hl,   g_h_l);
    cudaGetSymbolAddress((void**)&ath,  g_attn_h);
    cudaGetSymbolAddress((void**)&atl,  g_attn_l);
    cudaGetSymbolAddress((void**)&gth,  g_gate_h);
    cudaGetSymbolAddress((void**)&gtl,  g_gate_l);
    cudaGetSymbolAddress((void**)&qh,   g_q_h);
    cudaGetSymbolAddress((void**)&ql,   g_q_l);
    cudaGetSymbolAddress((void**)&kh,   g_k_h);
    cudaGetSymbolAddress((void**)&kl,   g_k_l);
    cudaGetSymbolAddress((void**)&vh,   g_v_h);
    cudaGetSymbolAddress((void**)&vl,   g_v_l);
    cudaGetSymbolAddress((void**)&wqkvh, g_wqkvT_h);
    cudaGetSymbolAddress((void**)&wqkvl, g_wqkvT_l);
    cudaGetSymbolAddress((void**)&wouth, g_woutT_h);
    cudaGetSymbolAddress((void**)&woutl, g_woutT_l);
    cudaGetSymbolAddress((void**)&wgh,  g_wgT_h);
    cudaGetSymbolAddress((void**)&wgl,  g_wgT_l);
    cudaGetSymbolAddress((void**)&wuh,  g_wuT_h);
    cudaGetSymbolAddress((void**)&wul,  g_wuT_l);
    cudaGetSymbolAddress((void**)&wdh,  g_wdT_h);
    cudaGetSymbolAddress((void**)&wdl,  g_wdT_l);

    cudaFuncSetAttribute(k_gemm_bf3, cudaFuncAttributeMaxDynamicSharedMemorySize, 81920);
    cudaFuncSetAttribute(k_flash, cudaFuncAttributeMaxDynamicSharedMemorySize, 2 * FSTG * 4);
    const int GSM = 81920;
    const int FSM = 2 * FSTG * 4;
    const int PBLK = 296;
    float* p0 = gate;   // split-K partials reuse MLP fp32 scratch
    float* p1 = up;

    dim3 tb(32, 8);
    k_wsplit<<<dim3(96, 16, LL), tb>>>(Wqkv, wqkvh, wqkvl, DD, 3 * DD, DD,
                                       (long)DD * 3 * DD, (long)3 * DD * DD);
    k_wsplit<<<dim3(32, 16, LL), tb>>>(Wout, wouth, woutl, DD, DD, DD,
                                       (long)DD * DD, (long)DD * DD);
    k_wsplit<<<dim3(86, 16, LL), tb>>>(Wg, wgh, wgl, DD, MMF, DD,
                                       (long)DD * MMF, (long)MMF * DD);
    k_wsplit<<<dim3(86, 16, LL), tb>>>(Wu, wuh, wul, DD, MMF, DD,
                                       (long)DD * MMF, (long)MMF * DD);
    k_wsplit<<<dim3(32, 43, LL), tb>>>(Wd, wdh, wdl, MMF, DD, MP,
                                       (long)MMF * DD, (long)DD * MP);

    k_embed<<<NTOK, 256>>>(tokens, embed, x);
    k_rmsnorm<<<NTOK, 256>>>(x, ln1, hh, hl);

    for (int l = 0; l < LL; ++l) {
        // QKV with fused rope/split epilogue
        k_gemm_bf3<<<PBLK, 256, GSM>>>(hh, hl,
                                wqkvh + (long)l * 3 * DD * DD, wqkvl + (long)l * 3 * DD * DD,
                                bqkv + (long)l * 3 * DD, nullptr, nullptr,
                                nullptr, nullptr, nullptr, nullptr,
                                NTOK, DD, 3 * DD, 24, 3 * DD, 3 * DD, 1, 1,
                                qh, ql, kh, kl, vh, vl);

        k_flash<<<dim3(SD / 64, BH), 128, FSM>>>(qh, ql, kh, kl, vh, vl, ath, atl);

        // Wout split-K=2 -> p0,p1 (raw partials)
        k_gemm_bf3<<<256, 256, GSM>>>(ath, atl,
                                wouth + (long)l * DD * DD, woutl + (long)l * DD * DD,
                                nullptr, nullptr, p0,
                                nullptr, nullptr, nullptr, p1,
                                NTOK, DD, DD, 8, DD, DD, 0, 2,
                                nullptr, nullptr, nullptr, nullptr, nullptr, nullptr);
        k_comb_rms<<<NTOK, 256>>>(x, p0, p1, bout + (long)l * DD,
                                  ln2 + (long)l * DD, hh, hl);

        // Wg + Wu dual, MP-padded fp32 out
        k_gemm_bf3<<<PBLK, 256, GSM>>>(hh, hl,
                                wgh + (long)l * MMF * DD, wgl + (long)l * MMF * DD,
                                bg + (long)l * MMF, nullptr, gate,
                                wuh + (long)l * MMF * DD, wul + (long)l * MMF * DD,
                                bu + (long)l * MMF, up,
                                NTOK, DD, MMF, 22, MP, MP, 0, 1,
                                nullptr, nullptr, nullptr, nullptr, nullptr, nullptr);

        k_silu<<<NTOK * (MP / 4) / 256, 256>>>(gate, up, gth, gtl);

        // Wd split-K=2 -> p0,p1 (reuses gate/up after silu consumed them)
        k_gemm_bf3<<<256, 256, GSM>>>(gth, gtl,
                                wdh + (long)l * DD * MP, wdl + (long)l * DD * MP,
                                nullptr, nullptr, p0,
                                nullptr, nullptr, nullptr, p1,
                                NTOK, MP, DD, 8, DD, DD, 0, 2,
                                nullptr, nullptr, nullptr, nullptr, nullptr, nullptr);
        const float* wnext = (l < LL - 1) ? (ln1 + (long)(l + 1) * DD) : lnf;
        k_comb_rms<<<NTOK, 256>>>(x, p0, p1, bd + (long)l * DD, wnext, hh, hl);
    }

    // hh/hl already hold lnf-normalized final hidden state
    dim3 gh((VV + 255) / 256, BD);
    k_head<<<gh, 256>>>(hh, hl, Whead, bhead, out);
}